// round 2
// baseline (speedup 1.0000x reference)
#include <cuda_runtime.h>
#include <math.h>

#define NENT   2048
#define MMEN   64
#define KC     32
#define VOCABN 5053
#define EMBD   300
#define CCSN   512
#define PCOLS  2560
#define HHN    128
#define NSEQ   193
#define NFEAT  4161

__device__ __align__(16) float d_B1t[EMBD * PCOLS];
__device__ __align__(16) float d_P[VOCABN * PCOLS];
__device__ __align__(16) float d_Feats[NFEAT * CCSN];
__device__ __align__(16) float d_Wcat[CCSN * 1024];
__device__ __align__(16) float d_Pre[NFEAT * 1024];
__device__ __align__(16) float d_Hout[NSEQ * KC * 256];
__device__ __align__(16) float d_Pp[2 * MMEN * KC];

__device__ __forceinline__ float sigf(float x) { return 1.f / (1.f + expf(-x)); }

__global__ void prep_kernel(const float* __restrict__ conv_w,
                            const float* __restrict__ Wih_f,
                            const float* __restrict__ Wih_b) {
    int i = blockIdx.x * blockDim.x + threadIdx.x;
    const int tot1 = EMBD * PCOLS;
    if (i < tot1) {
        int e = i / PCOLS, j = i - e * PCOLS;
        int w = j >> 9, c = j & 511;
        d_B1t[i] = conv_w[c * (EMBD * 5) + e * 5 + w];
    } else {
        int i2 = i - tot1;
        if (i2 < CCSN * 1024) {
            int in = i2 >> 10, j = i2 & 1023;
            int dir = j >> 9, col = j & 511;
            const float* W = dir ? Wih_b : Wih_f;
            d_Wcat[i2] = W[col * CCSN + in];
        }
    }
}

// C[M,N] = A[M,K] @ B[K,N], row-major, N % 128 == 0
__global__ void __launch_bounds__(256) gemm_kernel(int M, int N, int K,
    const float* __restrict__ A, const float* __restrict__ B, float* __restrict__ C)
{
    const int BM = 128, BN = 128, BK = 8;
    __shared__ float As[BK][BM];
    __shared__ float Bs[BK][BN + 4];
    int tid = threadIdx.x;
    int bm = blockIdx.y, bn = blockIdx.x;
    int rowBase = (tid >> 4) * 8, colBase = (tid & 15) * 8;
    float acc[8][8];
    #pragma unroll
    for (int i = 0; i < 8; i++)
        #pragma unroll
        for (int j = 0; j < 8; j++) acc[i][j] = 0.f;
    int arow = tid >> 1, ac0 = (tid & 1) * 4;
    int brow = tid >> 5, bc0 = (tid & 31) * 4;
    for (int k0 = 0; k0 < K; k0 += BK) {
        int gr = bm * BM + arow;
        #pragma unroll
        for (int x = 0; x < 4; x++) {
            int gk = k0 + ac0 + x;
            As[ac0 + x][arow] = (gr < M && gk < K) ? A[(size_t)gr * K + gk] : 0.f;
        }
        int gk = k0 + brow;
        bool ok = gk < K;
        const float* Bp = B + (size_t)gk * N + bn * BN + bc0;
        #pragma unroll
        for (int x = 0; x < 4; x++) Bs[brow][bc0 + x] = ok ? Bp[x] : 0.f;
        __syncthreads();
        #pragma unroll
        for (int kk = 0; kk < BK; kk++) {
            float a[8], b[8];
            #pragma unroll
            for (int i = 0; i < 8; i++) a[i] = As[kk][rowBase + i];
            #pragma unroll
            for (int j = 0; j < 8; j++) b[j] = Bs[kk][colBase + j];
            #pragma unroll
            for (int i = 0; i < 8; i++)
                #pragma unroll
                for (int j = 0; j < 8; j++) acc[i][j] += a[i] * b[j];
        }
        __syncthreads();
    }
    #pragma unroll
    for (int i = 0; i < 8; i++) {
        int gr = bm * BM + rowBase + i;
        if (gr < M) {
            float* Cp = C + (size_t)gr * N + bn * BN + colBase;
            #pragma unroll
            for (int j = 0; j < 8; j++) Cp[j] = acc[i][j];
        }
    }
}

__global__ void __launch_bounds__(128) conv_kernel(
    const int* __restrict__ title, const int* __restrict__ body,
    const int* __restrict__ ctx, const int* __restrict__ doc,
    const float* __restrict__ conv_b)
{
    __shared__ int chars[512];
    int b = blockIdx.x, tid = threadIdx.x;
    const int* src; int L;
    if (b < NENT)                 { src = title + b * 32;             L = 32;  }
    else if (b < 2 * NENT)        { src = body + (b - NENT) * 128;    L = 128; }
    else if (b < 2 * NENT + MMEN) { src = ctx + (b - 2 * NENT) * 128; L = 128; }
    else                          { src = doc;                        L = 512; }
    for (int i = tid; i < L; i += 128) chars[i] = src[i];
    __syncthreads();
    int c4 = tid * 4;
    float mx0 = -1e30f, mx1 = -1e30f, mx2 = -1e30f, mx3 = -1e30f;
    int Lout = L - 4;
    for (int t = 0; t < Lout; t++) {
        float s0 = 0.f, s1 = 0.f, s2 = 0.f, s3 = 0.f;
        #pragma unroll
        for (int w = 0; w < 5; w++) {
            const float4 p = *(const float4*)&d_P[(size_t)chars[t + w] * PCOLS + (w << 9) + c4];
            s0 += p.x; s1 += p.y; s2 += p.z; s3 += p.w;
        }
        mx0 = fmaxf(mx0, s0); mx1 = fmaxf(mx1, s1);
        mx2 = fmaxf(mx2, s2); mx3 = fmaxf(mx3, s3);
    }
    const float4 bb = *(const float4*)&conv_b[c4];
    float4 o;
    o.x = fmaxf(0.f, mx0 + bb.x); o.y = fmaxf(0.f, mx1 + bb.y);
    o.z = fmaxf(0.f, mx2 + bb.z); o.w = fmaxf(0.f, mx3 + bb.w);
    *(float4*)&d_Feats[(size_t)b * CCSN + c4] = o;
}

__global__ void __launch_bounds__(128) lstm_kernel(
    const int* __restrict__ cand_idx,
    const float* __restrict__ Whh_f, const float* __restrict__ Whh_b,
    const float* __restrict__ bih_f, const float* __restrict__ bhh_f,
    const float* __restrict__ bih_b, const float* __restrict__ bhh_b)
{
    __shared__ __align__(16) float hsm[4][HHN];
    __shared__ __align__(16) float presm[4][512];
    __shared__ int rowIdx[4][KC];
    int tid = threadIdx.x;
    int dir = blockIdx.y;
    int s0 = blockIdx.x * 4;
    const float* Whh = dir ? Whh_b : Whh_f;
    const float* bih = dir ? bih_b : bih_f;
    const float* bhh = dir ? bhh_b : bhh_f;
    int preOff = dir * 512;
    float bias[4];
    #pragma unroll
    for (int g = 0; g < 4; g++) { int col = (g << 7) + tid; bias[g] = bih[col] + bhh[col]; }
    {
        int s = tid >> 5, t = tid & 31;
        int seq = s0 + s;
        int row;
        if (seq < 64)       row = cand_idx[seq * 32 + t];
        else if (seq < 128) row = NENT + cand_idx[(seq - 64) * 32 + t];
        else if (seq < 192) row = 2 * NENT + (seq - 128);
        else                row = NFEAT - 1;
        rowIdx[s][t] = row;
    }
    #pragma unroll
    for (int s = 0; s < 4; s++) hsm[s][tid] = 0.f;
    float cst[4] = {0.f, 0.f, 0.f, 0.f};
    int nS = NSEQ - s0; if (nS > 4) nS = 4;
    __syncthreads();
    for (int st = 0; st < KC; st++) {
        int t = dir ? (KC - 1 - st) : st;
        #pragma unroll
        for (int s = 0; s < 4; s++) {
            const float* prow = d_Pre + (size_t)rowIdx[s][t] * 1024 + preOff;
            *(float4*)&presm[s][tid * 4] = *(const float4*)&prow[tid * 4];
        }
        __syncthreads();
        float acc[4][4];
        #pragma unroll
        for (int g = 0; g < 4; g++)
            #pragma unroll
            for (int s = 0; s < 4; s++)
                acc[g][s] = presm[s][(g << 7) + tid] + bias[g];
        #pragma unroll 4
        for (int h4 = 0; h4 < HHN; h4 += 4) {
            float4 hv[4];
            #pragma unroll
            for (int s = 0; s < 4; s++) hv[s] = *(const float4*)&hsm[s][h4];
            #pragma unroll
            for (int g = 0; g < 4; g++) {
                const float4 wv = *(const float4*)&Whh[(size_t)((g << 7) + tid) * HHN + h4];
                #pragma unroll
                for (int s = 0; s < 4; s++) {
                    acc[g][s] += wv.x * hv[s].x; acc[g][s] += wv.y * hv[s].y;
                    acc[g][s] += wv.z * hv[s].z; acc[g][s] += wv.w * hv[s].w;
                }
            }
        }
        float hnew[4];
        #pragma unroll
        for (int s = 0; s < 4; s++) {
            float ig = sigf(acc[0][s]);
            float fg = sigf(acc[1][s]);
            float gg = tanhf(acc[2][s]);
            float og = sigf(acc[3][s]);
            cst[s] = fg * cst[s] + ig * gg;
            hnew[s] = og * tanhf(cst[s]);
        }
        __syncthreads();
        #pragma unroll
        for (int s = 0; s < 4; s++) {
            hsm[s][tid] = hnew[s];
            if (s < nS)
                d_Hout[((size_t)(s0 + s) * KC + t) * 256 + dir * HHN + tid] = hnew[s];
        }
    }
}

__global__ void __launch_bounds__(256) att_kernel(
    const float* __restrict__ wc, const float* __restrict__ bcp,
    const float* __restrict__ wq, const float* __restrict__ bqp,
    const float* __restrict__ wcq, const float* __restrict__ bcqp,
    const float* __restrict__ wz, const float* __restrict__ bzp)
{
    extern __shared__ float sbuf[];
    float* csm = sbuf;                 // 32*257
    float* qsm = csm + 8224;           // 32*257
    float* sA  = qsm + 8224;           // 32*33
    float* cwcA = sA + 1056;           // 32
    float* qwqA = cwcA + 32;           // 32
    float* rowmaxA = qwqA + 32;        // 32
    float* betaA = rowmaxA + 32;       // 32
    float* q2cA = betaA + 32;          // 256
    float* wcqs = q2cA + 256;          // 256
    int m = blockIdx.x, fl = blockIdx.y, tid = threadIdx.x;
    int seqC = fl ? 192 : (128 + m);
    int seqQ = fl ? (64 + m) : m;
    const float* Crow = d_Hout + (size_t)seqC * KC * 256;
    const float* Qrow = d_Hout + (size_t)seqQ * KC * 256;
    for (int idx = tid; idx < 32 * 256; idx += 256) {
        int i = idx >> 8, d = idx & 255;
        csm[i * 257 + d] = Crow[i * 256 + d];
        qsm[i * 257 + d] = Qrow[i * 256 + d];
    }
    wcqs[tid] = wcq[tid];
    __syncthreads();
    if (tid < 32) {
        float a = 0.f;
        for (int d = 0; d < 256; d++) a += csm[tid * 257 + d] * wc[d];
        cwcA[tid] = a;
    } else if (tid < 64) {
        int j = tid - 32;
        float a = 0.f;
        for (int d = 0; d < 256; d++) a += qsm[j * 257 + d] * wq[d];
        qwqA[j] = a;
    }
    __syncthreads();
    float K0 = bcp[0] + bqp[0] + bcqp[0];
    for (int e = tid; e < 1024; e += 256) {
        int i = e >> 5, j = e & 31;
        float acc = 0.f;
        for (int d = 0; d < 256; d++)
            acc += csm[i * 257 + d] * wcqs[d] * qsm[j * 257 + d];
        sA[i * 33 + j] = acc + cwcA[i] + qwqA[j] + K0;
    }
    __syncthreads();
    if (tid < 32) {
        int i = tid;
        float mx = -1e30f;
        for (int j = 0; j < 32; j++) mx = fmaxf(mx, sA[i * 33 + j]);
        rowmaxA[i] = mx;
        float s = 0.f;
        for (int j = 0; j < 32; j++) { float e2 = expf(sA[i * 33 + j] - mx); sA[i * 33 + j] = e2; s += e2; }
        float inv = 1.f / s;
        for (int j = 0; j < 32; j++) sA[i * 33 + j] *= inv;
    }
    __syncthreads();
    if (tid == 0) {
        float mx = -1e30f;
        for (int i = 0; i < 32; i++) mx = fmaxf(mx, rowmaxA[i]);
        float s = 0.f;
        for (int i = 0; i < 32; i++) { float e2 = expf(rowmaxA[i] - mx); betaA[i] = e2; s += e2; }
        float inv = 1.f / s;
        for (int i = 0; i < 32; i++) betaA[i] *= inv;
    }
    __syncthreads();
    {
        float a = 0.f;
        for (int i = 0; i < 32; i++) a += betaA[i] * csm[i * 257 + tid];
        q2cA[tid] = a;
    }
    __syncthreads();
    {
        int i = tid >> 3, sub = tid & 7, d0 = sub * 32;
        float pp = 0.f;
        for (int dd = 0; dd < 32; dd++) {
            int d = d0 + dd;
            float c2 = 0.f;
            for (int j = 0; j < 32; j++) c2 += sA[i * 33 + j] * qsm[j * 257 + d];
            float cd = csm[i * 257 + d];
            pp += cd * wz[d] + c2 * wz[256 + d] + cd * c2 * wz[512 + d] + cd * q2cA[d] * wz[768 + d];
        }
        pp += __shfl_xor_sync(0xffffffffu, pp, 1);
        pp += __shfl_xor_sync(0xffffffffu, pp, 2);
        pp += __shfl_xor_sync(0xffffffffu, pp, 4);
        if (sub == 0) d_Pp[fl * 2048 + m * 32 + i] = pp + bzp[0];
    }
}

__global__ void __launch_bounds__(256) final_kernel(
    const int* __restrict__ cand,
    const float* __restrict__ wp1, const float* __restrict__ bp1,
    const float* __restrict__ wp2, const float* __restrict__ bp2,
    float* __restrict__ out)
{
    int m = blockIdx.x, tid = threadIdx.x;
    const int R = MMEN * NENT;
    for (int j = tid; j < NENT; j += 256) {
        out[m * NENT + j] = 0.f;
        out[R + m * NENT + j] = 0.f;
        out[2 * R + m * NENT + j] = 0.f;
    }
    __syncthreads();
    if (tid < 32) {
        float s = wp1[0] * d_Pp[m * 32 + tid] + bp1[0] + wp2[0] * d_Pp[2048 + m * 32 + tid] + bp2[0];
        float mx = s;
        #pragma unroll
        for (int o = 16; o; o >>= 1) mx = fmaxf(mx, __shfl_xor_sync(0xffffffffu, mx, o));
        float e = expf(s - mx);
        float se = e, ss = s;
        #pragma unroll
        for (int o = 16; o; o >>= 1) {
            se += __shfl_xor_sync(0xffffffffu, se, o);
            ss += __shfl_xor_sync(0xffffffffu, ss, o);
        }
        int col = cand[m * 32 + tid];
        out[m * NENT + col] = s;
        out[R + m * NENT + col] = e / se;
        out[2 * R + m * NENT + col] = s / ss;
    }
}

extern "C" void kernel_launch(void* const* d_in, const int* in_sizes, int n_in,
                              void* d_out, int out_size) {
    const int* title = (const int*)d_in[0];
    const int* body  = (const int*)d_in[1];
    // d_in[2] = mention_vec (unused by reference)
    const int* ctx   = (const int*)d_in[3];
    const int* doc   = (const int*)d_in[4];
    const int* cand  = (const int*)d_in[5];
    const float* emb    = (const float*)d_in[6];
    const float* conv_w = (const float*)d_in[7];
    const float* conv_b = (const float*)d_in[8];
    const float* Wih_f = (const float*)d_in[9];
    const float* Whh_f = (const float*)d_in[10];
    const float* bih_f = (const float*)d_in[11];
    const float* bhh_f = (const float*)d_in[12];
    const float* Wih_b = (const float*)d_in[13];
    const float* Whh_b = (const float*)d_in[14];
    const float* bih_b = (const float*)d_in[15];
    const float* bhh_b = (const float*)d_in[16];
    const float* wc  = (const float*)d_in[17];
    const float* bc  = (const float*)d_in[18];
    const float* wq  = (const float*)d_in[19];
    const float* bq  = (const float*)d_in[20];
    const float* wcq = (const float*)d_in[21];
    const float* bcq = (const float*)d_in[22];
    const float* wz  = (const float*)d_in[23];
    const float* bz  = (const float*)d_in[24];
    const float* w_p1 = (const float*)d_in[25];
    const float* b_p1 = (const float*)d_in[26];
    const float* w_p2 = (const float*)d_in[27];
    const float* b_p2 = (const float*)d_in[28];
    float* out = (float*)d_out;

    float *pB1t, *pP, *pFeats, *pWcat, *pPre;
    cudaGetSymbolAddress((void**)&pB1t, d_B1t);
    cudaGetSymbolAddress((void**)&pP, d_P);
    cudaGetSymbolAddress((void**)&pFeats, d_Feats);
    cudaGetSymbolAddress((void**)&pWcat, d_Wcat);
    cudaGetSymbolAddress((void**)&pPre, d_Pre);

    prep_kernel<<<(EMBD * PCOLS + CCSN * 1024 + 255) / 256, 256>>>(conv_w, Wih_f, Wih_b);
    gemm_kernel<<<dim3(PCOLS / 128, (VOCABN + 127) / 128), 256>>>(VOCABN, PCOLS, EMBD, emb, pB1t, pP);
    conv_kernel<<<NFEAT, 128>>>(title, body, ctx, doc, conv_b);
    gemm_kernel<<<dim3(1024 / 128, (NFEAT + 127) / 128), 256>>>(NFEAT, 1024, CCSN, pFeats, pWcat, pPre);
    lstm_kernel<<<dim3((NSEQ + 3) / 4, 2), 128>>>(cand, Whh_f, Whh_b, bih_f, bhh_f, bih_b, bhh_b);
    cudaFuncSetAttribute(att_kernel, cudaFuncAttributeMaxDynamicSharedMemorySize, 73728);
    att_kernel<<<dim3(MMEN, 2), 256, 72576>>>(wc, bc, wq, bq, wcq, bcq, wz, bz);
    final_kernel<<<MMEN, 256>>>(cand, w_p1, b_p1, w_p2, b_p2, out);
}

// round 3
// speedup vs baseline: 1.0735x; 1.0735x over previous
#include <cuda_runtime.h>
#include <math.h>

#define NENT   2048
#define MMEN   64
#define KC     32
#define VOCABN 5053
#define EMBD   300
#define CCSN   512
#define PCOLS  2560
#define HHN    128
#define NSEQ   193
#define NFEAT  4161

__device__ __align__(16) float d_B1t[EMBD * PCOLS];
__device__ __align__(16) float d_P[VOCABN * PCOLS];
__device__ __align__(16) float d_Feats[NFEAT * CCSN];
__device__ __align__(16) float d_Wcat[CCSN * 1024];
__device__ __align__(16) float d_Pre[NFEAT * 1024];
__device__ __align__(16) float d_Hout[NSEQ * KC * 256];
__device__ __align__(16) float d_Pp[2 * MMEN * KC];
__device__ __align__(16) float d_Wt[2 * 32 * 2048];   // [dir][h4-block][4*HH cols][4 h] transposed Whh

__device__ __forceinline__ float sigf(float x) { return 1.f / (1.f + expf(-x)); }

__global__ void prep_kernel(const float* __restrict__ conv_w,
                            const float* __restrict__ Wih_f,
                            const float* __restrict__ Wih_b,
                            const float* __restrict__ Whh_f,
                            const float* __restrict__ Whh_b) {
    int i = blockIdx.x * blockDim.x + threadIdx.x;
    const int tot1 = EMBD * PCOLS;          // 768000
    const int tot2 = CCSN * 1024;           // 524288
    if (i < tot1) {
        int e = i / PCOLS, j = i - e * PCOLS;
        int w = j >> 9, c = j & 511;
        d_B1t[i] = conv_w[c * (EMBD * 5) + e * 5 + w];
        return;
    }
    int i2 = i - tot1;
    if (i2 < tot2) {
        int in = i2 >> 10, j = i2 & 1023;
        int dir = j >> 9, col = j & 511;
        const float* W = dir ? Wih_b : Wih_f;
        d_Wcat[i2] = W[col * CCSN + in];
        return;
    }
    int i3 = i2 - tot2;
    if (i3 < 2 * 32 * 2048) {
        int dir = i3 >> 16;
        int r = i3 & 65535;
        int hb = r >> 11, rem = r & 2047;
        int col = rem >> 2, j = rem & 3;
        const float* W = dir ? Whh_b : Whh_f;
        d_Wt[i3] = W[col * HHN + hb * 4 + j];
    }
}

// C[M,N] = A[M,K] @ B[K,N], row-major. N%128==0, K%4==0, A rows 16B-aligned.
__global__ void __launch_bounds__(256) gemm_kernel(int M, int N, int K,
    const float* __restrict__ A, const float* __restrict__ B, float* __restrict__ C)
{
    const int BM = 128, BN = 128, BK = 16;
    __shared__ float As[2][BK][BM];
    __shared__ float Bs[2][BK][BN + 4];
    int tid = threadIdx.x;
    int bm = blockIdx.y, bn = blockIdx.x;
    int rowBase = (tid >> 4) * 8, colBase = (tid & 15) * 8;
    // A tile load: row ar (0..127), k offset ak (0 or 8), two float4
    int ar = tid >> 1, ak = (tid & 1) * 8;
    // B tile load: k row bkr (0..15), col bcol (0..120), two float4
    int bkr = tid >> 4, bcol = (tid & 15) * 8;
    int garow = bm * BM + ar;
    const float* Bbase = B + (size_t)bkr * N + bn * BN + bcol;

    float acc[8][8];
    #pragma unroll
    for (int i = 0; i < 8; i++)
        #pragma unroll
        for (int j = 0; j < 8; j++) acc[i][j] = 0.f;

    int nk = (K + BK - 1) / BK;
    float4 a0, a1, b0, b1;
    // prologue: load k-block 0 into regs
    {
        int gk0 = ak, gk1 = ak + 4;
        a0 = (garow < M && gk0 < K) ? *(const float4*)&A[(size_t)garow * K + gk0] : make_float4(0,0,0,0);
        a1 = (garow < M && gk1 < K) ? *(const float4*)&A[(size_t)garow * K + gk1] : make_float4(0,0,0,0);
        bool okb = bkr < K;
        b0 = okb ? *(const float4*)&Bbase[0] : make_float4(0,0,0,0);
        b1 = okb ? *(const float4*)&Bbase[4] : make_float4(0,0,0,0);
    }
    int cur = 0;
    // store prologue into smem buf 0
    As[0][ak + 0][ar] = a0.x; As[0][ak + 1][ar] = a0.y; As[0][ak + 2][ar] = a0.z; As[0][ak + 3][ar] = a0.w;
    As[0][ak + 4][ar] = a1.x; As[0][ak + 5][ar] = a1.y; As[0][ak + 6][ar] = a1.z; As[0][ak + 7][ar] = a1.w;
    *(float4*)&Bs[0][bkr][bcol] = b0;
    *(float4*)&Bs[0][bkr][bcol + 4] = b1;
    __syncthreads();

    for (int kb = 0; kb < nk; kb++) {
        if (kb + 1 < nk) {
            int k0 = (kb + 1) * BK;
            int gk0 = k0 + ak, gk1 = k0 + ak + 4;
            a0 = (garow < M && gk0 < K) ? *(const float4*)&A[(size_t)garow * K + gk0] : make_float4(0,0,0,0);
            a1 = (garow < M && gk1 < K) ? *(const float4*)&A[(size_t)garow * K + gk1] : make_float4(0,0,0,0);
            bool okb = (k0 + bkr) < K;
            const float* Bp = Bbase + (size_t)k0 * N;
            b0 = okb ? *(const float4*)&Bp[0] : make_float4(0,0,0,0);
            b1 = okb ? *(const float4*)&Bp[4] : make_float4(0,0,0,0);
            int nxt = cur ^ 1;
            As[nxt][ak + 0][ar] = a0.x; As[nxt][ak + 1][ar] = a0.y; As[nxt][ak + 2][ar] = a0.z; As[nxt][ak + 3][ar] = a0.w;
            As[nxt][ak + 4][ar] = a1.x; As[nxt][ak + 5][ar] = a1.y; As[nxt][ak + 6][ar] = a1.z; As[nxt][ak + 7][ar] = a1.w;
            *(float4*)&Bs[nxt][bkr][bcol] = b0;
            *(float4*)&Bs[nxt][bkr][bcol + 4] = b1;
        }
        #pragma unroll
        for (int kk = 0; kk < BK; kk++) {
            float a[8], b[8];
            *(float4*)&a[0] = *(const float4*)&As[cur][kk][rowBase];
            *(float4*)&a[4] = *(const float4*)&As[cur][kk][rowBase + 4];
            *(float4*)&b[0] = *(const float4*)&Bs[cur][kk][colBase];
            *(float4*)&b[4] = *(const float4*)&Bs[cur][kk][colBase + 4];
            #pragma unroll
            for (int i = 0; i < 8; i++)
                #pragma unroll
                for (int j = 0; j < 8; j++) acc[i][j] += a[i] * b[j];
        }
        __syncthreads();
        cur ^= 1;
    }
    #pragma unroll
    for (int i = 0; i < 8; i++) {
        int gr = bm * BM + rowBase + i;
        if (gr < M) {
            float* Cp = C + (size_t)gr * N + bn * BN + colBase;
            *(float4*)&Cp[0] = *(const float4*)&acc[i][0];
            *(float4*)&Cp[4] = *(const float4*)&acc[i][4];
        }
    }
}

__global__ void __launch_bounds__(128) conv_kernel(
    const int* __restrict__ title, const int* __restrict__ body,
    const int* __restrict__ ctx, const int* __restrict__ doc,
    const float* __restrict__ conv_b)
{
    __shared__ int chars[512];
    int b = blockIdx.x, tid = threadIdx.x;
    const int* src; int L;
    if (b < NENT)                 { src = title + b * 32;             L = 32;  }
    else if (b < 2 * NENT)        { src = body + (b - NENT) * 128;    L = 128; }
    else if (b < 2 * NENT + MMEN) { src = ctx + (b - 2 * NENT) * 128; L = 128; }
    else                          { src = doc;                        L = 512; }
    for (int i = tid; i < L; i += 128) chars[i] = src[i];
    __syncthreads();
    int c4 = tid * 4;
    float mx0 = -1e30f, mx1 = -1e30f, mx2 = -1e30f, mx3 = -1e30f;
    int Lout = L - 4;
    #pragma unroll 2
    for (int t = 0; t < Lout; t++) {
        float s0 = 0.f, s1 = 0.f, s2 = 0.f, s3 = 0.f;
        #pragma unroll
        for (int w = 0; w < 5; w++) {
            const float4 p = *(const float4*)&d_P[(size_t)chars[t + w] * PCOLS + (w << 9) + c4];
            s0 += p.x; s1 += p.y; s2 += p.z; s3 += p.w;
        }
        mx0 = fmaxf(mx0, s0); mx1 = fmaxf(mx1, s1);
        mx2 = fmaxf(mx2, s2); mx3 = fmaxf(mx3, s3);
    }
    const float4 bb = *(const float4*)&conv_b[c4];
    float4 o;
    o.x = fmaxf(0.f, mx0 + bb.x); o.y = fmaxf(0.f, mx1 + bb.y);
    o.z = fmaxf(0.f, mx2 + bb.z); o.w = fmaxf(0.f, mx3 + bb.w);
    *(float4*)&d_Feats[(size_t)b * CCSN + c4] = o;
}

__global__ void __launch_bounds__(128) lstm_kernel(
    const int* __restrict__ cand_idx,
    const float* __restrict__ bih_f, const float* __restrict__ bhh_f,
    const float* __restrict__ bih_b, const float* __restrict__ bhh_b)
{
    __shared__ __align__(16) float hsm[4][HHN];
    __shared__ __align__(16) float presm[4][512];
    __shared__ int rowIdx[4][KC];
    int tid = threadIdx.x;
    int dir = blockIdx.y;
    int s0 = blockIdx.x * 4;
    const float* bih = dir ? bih_b : bih_f;
    const float* bhh = dir ? bhh_b : bhh_f;
    const float* Wt = d_Wt + dir * 65536;
    int preOff = dir * 512;
    float bias[4];
    #pragma unroll
    for (int g = 0; g < 4; g++) { int col = (g << 7) + tid; bias[g] = bih[col] + bhh[col]; }
    {
        int s = tid >> 5, t = tid & 31;
        int seq = s0 + s;
        int row;
        if (seq < 64)       row = cand_idx[seq * 32 + t];
        else if (seq < 128) row = NENT + cand_idx[(seq - 64) * 32 + t];
        else if (seq < 192) row = 2 * NENT + (seq - 128);
        else                row = NFEAT - 1;
        rowIdx[s][t] = row;
    }
    #pragma unroll
    for (int s = 0; s < 4; s++) hsm[s][tid] = 0.f;
    float cst[4] = {0.f, 0.f, 0.f, 0.f};
    int nS = NSEQ - s0; if (nS > 4) nS = 4;
    __syncthreads();
    for (int st = 0; st < KC; st++) {
        int t = dir ? (KC - 1 - st) : st;
        #pragma unroll
        for (int s = 0; s < 4; s++) {
            const float* prow = d_Pre + (size_t)rowIdx[s][t] * 1024 + preOff;
            *(float4*)&presm[s][tid * 4] = *(const float4*)&prow[tid * 4];
        }
        __syncthreads();
        float acc[4][4];
        #pragma unroll
        for (int g = 0; g < 4; g++)
            #pragma unroll
            for (int s = 0; s < 4; s++)
                acc[g][s] = presm[s][(g << 7) + tid] + bias[g];
        #pragma unroll 4
        for (int hb = 0; hb < 32; hb++) {
            float4 hv[4];
            #pragma unroll
            for (int s = 0; s < 4; s++) hv[s] = *(const float4*)&hsm[s][hb * 4];
            #pragma unroll
            for (int g = 0; g < 4; g++) {
                // coalesced: lanes read consecutive float4s
                const float4 wv = *(const float4*)&Wt[hb * 2048 + (((g << 7) + tid) << 2)];
                #pragma unroll
                for (int s = 0; s < 4; s++) {
                    acc[g][s] += wv.x * hv[s].x; acc[g][s] += wv.y * hv[s].y;
                    acc[g][s] += wv.z * hv[s].z; acc[g][s] += wv.w * hv[s].w;
                }
            }
        }
        float hnew[4];
        #pragma unroll
        for (int s = 0; s < 4; s++) {
            float ig = sigf(acc[0][s]);
            float fg = sigf(acc[1][s]);
            float gg = tanhf(acc[2][s]);
            float og = sigf(acc[3][s]);
            cst[s] = fg * cst[s] + ig * gg;
            hnew[s] = og * tanhf(cst[s]);
        }
        __syncthreads();
        #pragma unroll
        for (int s = 0; s < 4; s++) {
            hsm[s][tid] = hnew[s];
            if (s < nS)
                d_Hout[((size_t)(s0 + s) * KC + t) * 256 + dir * HHN + tid] = hnew[s];
        }
    }
}

__global__ void __launch_bounds__(256) att_kernel(
    const float* __restrict__ wc, const float* __restrict__ bcp,
    const float* __restrict__ wq, const float* __restrict__ bqp,
    const float* __restrict__ wcq, const float* __restrict__ bcqp,
    const float* __restrict__ wz, const float* __restrict__ bzp)
{
    extern __shared__ float sbuf[];
    float* csm = sbuf;                 // 32*257
    float* qsm = csm + 8224;           // 32*257
    float* sA  = qsm + 8224;           // 32*33
    float* cwcA = sA + 1056;
    float* qwqA = cwcA + 32;
    float* rowmaxA = qwqA + 32;
    float* betaA = rowmaxA + 32;
    float* q2cA = betaA + 32;          // 256
    float* wcqs = q2cA + 256;          // 256
    int m = blockIdx.x, fl = blockIdx.y, tid = threadIdx.x;
    int seqC = fl ? 192 : (128 + m);
    int seqQ = fl ? (64 + m) : m;
    const float* Crow = d_Hout + (size_t)seqC * KC * 256;
    const float* Qrow = d_Hout + (size_t)seqQ * KC * 256;
    for (int idx = tid; idx < 32 * 256; idx += 256) {
        int i = idx >> 8, d = idx & 255;
        csm[i * 257 + d] = Crow[i * 256 + d];
        qsm[i * 257 + d] = Qrow[i * 256 + d];
    }
    wcqs[tid] = wcq[tid];
    __syncthreads();
    if (tid < 32) {
        float a = 0.f;
        for (int d = 0; d < 256; d++) a += csm[tid * 257 + d] * wc[d];
        cwcA[tid] = a;
    } else if (tid < 64) {
        int j = tid - 32;
        float a = 0.f;
        for (int d = 0; d < 256; d++) a += qsm[j * 257 + d] * wq[d];
        qwqA[j] = a;
    }
    __syncthreads();
    float K0 = bcp[0] + bqp[0] + bcqp[0];
    for (int e = tid; e < 1024; e += 256) {
        int i = e >> 5, j = e & 31;
        float acc = 0.f;
        for (int d = 0; d < 256; d++)
            acc += csm[i * 257 + d] * wcqs[d] * qsm[j * 257 + d];
        sA[i * 33 + j] = acc + cwcA[i] + qwqA[j] + K0;
    }
    __syncthreads();
    if (tid < 32) {
        int i = tid;
        float mx = -1e30f;
        for (int j = 0; j < 32; j++) mx = fmaxf(mx, sA[i * 33 + j]);
        rowmaxA[i] = mx;
        float s = 0.f;
        for (int j = 0; j < 32; j++) { float e2 = expf(sA[i * 33 + j] - mx); sA[i * 33 + j] = e2; s += e2; }
        float inv = 1.f / s;
        for (int j = 0; j < 32; j++) sA[i * 33 + j] *= inv;
    }
    __syncthreads();
    if (tid == 0) {
        float mx = -1e30f;
        for (int i = 0; i < 32; i++) mx = fmaxf(mx, rowmaxA[i]);
        float s = 0.f;
        for (int i = 0; i < 32; i++) { float e2 = expf(rowmaxA[i] - mx); betaA[i] = e2; s += e2; }
        float inv = 1.f / s;
        for (int i = 0; i < 32; i++) betaA[i] *= inv;
    }
    __syncthreads();
    {
        float a = 0.f;
        for (int i = 0; i < 32; i++) a += betaA[i] * csm[i * 257 + tid];
        q2cA[tid] = a;
    }
    __syncthreads();
    {
        int i = tid >> 3, sub = tid & 7, d0 = sub * 32;
        float pp = 0.f;
        for (int dd = 0; dd < 32; dd++) {
            int d = d0 + dd;
            float c2 = 0.f;
            for (int j = 0; j < 32; j++) c2 += sA[i * 33 + j] * qsm[j * 257 + d];
            float cd = csm[i * 257 + d];
            pp += cd * wz[d] + c2 * wz[256 + d] + cd * c2 * wz[512 + d] + cd * q2cA[d] * wz[768 + d];
        }
        pp += __shfl_xor_sync(0xffffffffu, pp, 1);
        pp += __shfl_xor_sync(0xffffffffu, pp, 2);
        pp += __shfl_xor_sync(0xffffffffu, pp, 4);
        if (sub == 0) d_Pp[fl * 2048 + m * 32 + i] = pp + bzp[0];
    }
}

__global__ void __launch_bounds__(256) final_kernel(
    const int* __restrict__ cand,
    const float* __restrict__ wp1, const float* __restrict__ bp1,
    const float* __restrict__ wp2, const float* __restrict__ bp2,
    float* __restrict__ out)
{
    int m = blockIdx.x, tid = threadIdx.x;
    const int R = MMEN * NENT;
    for (int j = tid; j < NENT; j += 256) {
        out[m * NENT + j] = 0.f;
        out[R + m * NENT + j] = 0.f;
        out[2 * R + m * NENT + j] = 0.f;
    }
    __syncthreads();
    if (tid < 32) {
        float s = wp1[0] * d_Pp[m * 32 + tid] + bp1[0] + wp2[0] * d_Pp[2048 + m * 32 + tid] + bp2[0];
        float mx = s;
        #pragma unroll
        for (int o = 16; o; o >>= 1) mx = fmaxf(mx, __shfl_xor_sync(0xffffffffu, mx, o));
        float e = expf(s - mx);
        float se = e, ss = s;
        #pragma unroll
        for (int o = 16; o; o >>= 1) {
            se += __shfl_xor_sync(0xffffffffu, se, o);
            ss += __shfl_xor_sync(0xffffffffu, ss, o);
        }
        int col = cand[m * 32 + tid];
        out[m * NENT + col] = s;
        out[R + m * NENT + col] = e / se;
        out[2 * R + m * NENT + col] = s / ss;
    }
}

extern "C" void kernel_launch(void* const* d_in, const int* in_sizes, int n_in,
                              void* d_out, int out_size) {
    const int* title = (const int*)d_in[0];
    const int* body  = (const int*)d_in[1];
    const int* ctx   = (const int*)d_in[3];
    const int* doc   = (const int*)d_in[4];
    const int* cand  = (const int*)d_in[5];
    const float* emb    = (const float*)d_in[6];
    const float* conv_w = (const float*)d_in[7];
    const float* conv_b = (const float*)d_in[8];
    const float* Wih_f = (const float*)d_in[9];
    const float* Whh_f = (const float*)d_in[10];
    const float* bih_f = (const float*)d_in[11];
    const float* bhh_f = (const float*)d_in[12];
    const float* Wih_b = (const float*)d_in[13];
    const float* Whh_b = (const float*)d_in[14];
    const float* bih_b = (const float*)d_in[15];
    const float* bhh_b = (const float*)d_in[16];
    const float* wc  = (const float*)d_in[17];
    const float* bc  = (const float*)d_in[18];
    const float* wq  = (const float*)d_in[19];
    const float* bq  = (const float*)d_in[20];
    const float* wcq = (const float*)d_in[21];
    const float* bcq = (const float*)d_in[22];
    const float* wz  = (const float*)d_in[23];
    const float* bz  = (const float*)d_in[24];
    const float* w_p1 = (const float*)d_in[25];
    const float* b_p1 = (const float*)d_in[26];
    const float* w_p2 = (const float*)d_in[27];
    const float* b_p2 = (const float*)d_in[28];
    float* out = (float*)d_out;

    float *pB1t, *pP, *pFeats, *pWcat, *pPre;
    cudaGetSymbolAddress((void**)&pB1t, d_B1t);
    cudaGetSymbolAddress((void**)&pP, d_P);
    cudaGetSymbolAddress((void**)&pFeats, d_Feats);
    cudaGetSymbolAddress((void**)&pWcat, d_Wcat);
    cudaGetSymbolAddress((void**)&pPre, d_Pre);

    const int PREP_TOT = EMBD * PCOLS + CCSN * 1024 + 2 * 32 * 2048;
    prep_kernel<<<(PREP_TOT + 255) / 256, 256>>>(conv_w, Wih_f, Wih_b, Whh_f, Whh_b);
    gemm_kernel<<<dim3(PCOLS / 128, (VOCABN + 127) / 128), 256>>>(VOCABN, PCOLS, EMBD, emb, pB1t, pP);
    conv_kernel<<<NFEAT, 128>>>(title, body, ctx, doc, conv_b);
    gemm_kernel<<<dim3(1024 / 128, (NFEAT + 127) / 128), 256>>>(NFEAT, 1024, CCSN, pFeats, pWcat, pPre);
    lstm_kernel<<<dim3((NSEQ + 3) / 4, 2), 128>>>(cand, bih_f, bhh_f, bih_b, bhh_b);
    cudaFuncSetAttribute(att_kernel, cudaFuncAttributeMaxDynamicSharedMemorySize, 73728);
    att_kernel<<<dim3(MMEN, 2), 256, 72576>>>(wc, bc, wq, bq, wcq, bcq, wz, bz);
    final_kernel<<<MMEN, 256>>>(cand, w_p1, b_p1, w_p2, b_p2, out);
}

// round 4
// speedup vs baseline: 1.2572x; 1.1711x over previous
#include <cuda_runtime.h>
#include <math.h>

#define NENT   2048
#define MMEN   64
#define KC     32
#define VOCABN 5053
#define EMBD   300
#define CCSN   512
#define PCOLS  2560
#define HHN    128
#define NSEQ   193
#define NFEAT  4161

__device__ __align__(16) float d_B1t[EMBD * PCOLS];
__device__ __align__(16) float d_P[VOCABN * PCOLS];
__device__ __align__(16) float d_Feats[NFEAT * CCSN];
__device__ __align__(16) float d_Wcat[CCSN * 1024];
__device__ __align__(16) float d_Pre[NFEAT * 1024];
__device__ __align__(16) float d_Hout[NSEQ * KC * 256];
__device__ __align__(16) float d_Pp[2 * MMEN * KC];
__device__ __align__(16) float d_Wt[2 * 32 * 2048];

typedef unsigned long long u64t;

__device__ __forceinline__ u64t pack2(float x, float y) {
    u64t r;
    asm("mov.b64 %0, {%1, %2};" : "=l"(r) : "f"(x), "f"(y));
    return r;
}
__device__ __forceinline__ void unpack2(u64t v, float& x, float& y) {
    asm("mov.b64 {%0, %1}, %2;" : "=f"(x), "=f"(y) : "l"(v));
}
__device__ __forceinline__ void fma2(u64t& d, u64t a, u64t b) {
    asm("fma.rn.f32x2 %0, %1, %2, %0;" : "+l"(d) : "l"(a), "l"(b));
}

__device__ __forceinline__ float sigf(float x) { return 1.f / (1.f + expf(-x)); }

__global__ void prep_kernel(const float* __restrict__ conv_w,
                            const float* __restrict__ Wih_f,
                            const float* __restrict__ Wih_b,
                            const float* __restrict__ Whh_f,
                            const float* __restrict__ Whh_b) {
    int i = blockIdx.x * blockDim.x + threadIdx.x;
    const int tot1 = EMBD * PCOLS;
    const int tot2 = CCSN * 1024;
    if (i < tot1) {
        int e = i / PCOLS, j = i - e * PCOLS;
        int w = j >> 9, c = j & 511;
        d_B1t[i] = conv_w[c * (EMBD * 5) + e * 5 + w];
        return;
    }
    int i2 = i - tot1;
    if (i2 < tot2) {
        int in = i2 >> 10, j = i2 & 1023;
        int dir = j >> 9, col = j & 511;
        const float* W = dir ? Wih_b : Wih_f;
        d_Wcat[i2] = W[col * CCSN + in];
        return;
    }
    int i3 = i2 - tot2;
    if (i3 < 2 * 32 * 2048) {
        int dir = i3 >> 16;
        int r = i3 & 65535;
        int hb = r >> 11, rem = r & 2047;
        int col = rem >> 2, j = rem & 3;
        const float* W = dir ? Whh_b : Whh_f;
        d_Wt[i3] = W[col * HHN + hb * 4 + j];
    }
}

// C[M,N] = A[M,K] @ B[K,N], row-major, f32x2 inner product
__global__ void __launch_bounds__(256) gemm_kernel(int M, int N, int K,
    const float* __restrict__ A, const float* __restrict__ B, float* __restrict__ C)
{
    const int BM = 128, BN = 128, BK = 16;
    __shared__ float As[2][BK][BM];
    __shared__ float Bs[2][BK][BN + 4];
    int tid = threadIdx.x;
    int bm = blockIdx.y, bn = blockIdx.x;
    int rowBase = (tid >> 4) * 8, colBase = (tid & 15) * 8;
    int ar = tid >> 1, ak = (tid & 1) * 8;
    int bkr = tid >> 4, bcol = (tid & 15) * 8;
    int garow = bm * BM + ar;
    const float* Bbase = B + (size_t)bkr * N + bn * BN + bcol;

    u64t acc2[8][4];
    #pragma unroll
    for (int i = 0; i < 8; i++)
        #pragma unroll
        for (int j = 0; j < 4; j++) acc2[i][j] = 0ull;

    int nk = (K + BK - 1) / BK;
    float4 a0, a1, b0, b1;
    {
        int gk0 = ak, gk1 = ak + 4;
        a0 = (garow < M && gk0 < K) ? *(const float4*)&A[(size_t)garow * K + gk0] : make_float4(0,0,0,0);
        a1 = (garow < M && gk1 < K) ? *(const float4*)&A[(size_t)garow * K + gk1] : make_float4(0,0,0,0);
        bool okb = bkr < K;
        b0 = okb ? *(const float4*)&Bbase[0] : make_float4(0,0,0,0);
        b1 = okb ? *(const float4*)&Bbase[4] : make_float4(0,0,0,0);
    }
    int cur = 0;
    As[0][ak + 0][ar] = a0.x; As[0][ak + 1][ar] = a0.y; As[0][ak + 2][ar] = a0.z; As[0][ak + 3][ar] = a0.w;
    As[0][ak + 4][ar] = a1.x; As[0][ak + 5][ar] = a1.y; As[0][ak + 6][ar] = a1.z; As[0][ak + 7][ar] = a1.w;
    *(float4*)&Bs[0][bkr][bcol] = b0;
    *(float4*)&Bs[0][bkr][bcol + 4] = b1;
    __syncthreads();

    for (int kb = 0; kb < nk; kb++) {
        if (kb + 1 < nk) {
            int k0 = (kb + 1) * BK;
            int gk0 = k0 + ak, gk1 = k0 + ak + 4;
            a0 = (garow < M && gk0 < K) ? *(const float4*)&A[(size_t)garow * K + gk0] : make_float4(0,0,0,0);
            a1 = (garow < M && gk1 < K) ? *(const float4*)&A[(size_t)garow * K + gk1] : make_float4(0,0,0,0);
            bool okb = (k0 + bkr) < K;
            const float* Bp = Bbase + (size_t)k0 * N;
            b0 = okb ? *(const float4*)&Bp[0] : make_float4(0,0,0,0);
            b1 = okb ? *(const float4*)&Bp[4] : make_float4(0,0,0,0);
            int nxt = cur ^ 1;
            As[nxt][ak + 0][ar] = a0.x; As[nxt][ak + 1][ar] = a0.y; As[nxt][ak + 2][ar] = a0.z; As[nxt][ak + 3][ar] = a0.w;
            As[nxt][ak + 4][ar] = a1.x; As[nxt][ak + 5][ar] = a1.y; As[nxt][ak + 6][ar] = a1.z; As[nxt][ak + 7][ar] = a1.w;
            *(float4*)&Bs[nxt][bkr][bcol] = b0;
            *(float4*)&Bs[nxt][bkr][bcol + 4] = b1;
        }
        #pragma unroll
        for (int kk = 0; kk < BK; kk++) {
            float a[8];
            *(float4*)&a[0] = *(const float4*)&As[cur][kk][rowBase];
            *(float4*)&a[4] = *(const float4*)&As[cur][kk][rowBase + 4];
            ulonglong2 t0 = *(const ulonglong2*)&Bs[cur][kk][colBase];
            ulonglong2 t1 = *(const ulonglong2*)&Bs[cur][kk][colBase + 4];
            u64t b2[4] = {t0.x, t0.y, t1.x, t1.y};
            #pragma unroll
            for (int i = 0; i < 8; i++) {
                u64t av = pack2(a[i], a[i]);
                fma2(acc2[i][0], av, b2[0]);
                fma2(acc2[i][1], av, b2[1]);
                fma2(acc2[i][2], av, b2[2]);
                fma2(acc2[i][3], av, b2[3]);
            }
        }
        __syncthreads();
        cur ^= 1;
    }
    #pragma unroll
    for (int i = 0; i < 8; i++) {
        int gr = bm * BM + rowBase + i;
        if (gr < M) {
            float o[8];
            #pragma unroll
            for (int j = 0; j < 4; j++) unpack2(acc2[i][j], o[j * 2], o[j * 2 + 1]);
            float* Cp = C + (size_t)gr * N + bn * BN + colBase;
            *(float4*)&Cp[0] = *(const float4*)&o[0];
            *(float4*)&Cp[4] = *(const float4*)&o[4];
        }
    }
}

__global__ void __launch_bounds__(128) conv_kernel(
    const int* __restrict__ title, const int* __restrict__ body,
    const int* __restrict__ ctx, const int* __restrict__ doc,
    const float* __restrict__ conv_b)
{
    __shared__ int chars[512];
    int b = blockIdx.x, tid = threadIdx.x;
    const int* src; int L;
    if (b < NENT)                 { src = title + b * 32;             L = 32;  }
    else if (b < 2 * NENT)        { src = body + (b - NENT) * 128;    L = 128; }
    else if (b < 2 * NENT + MMEN) { src = ctx + (b - 2 * NENT) * 128; L = 128; }
    else                          { src = doc;                        L = 512; }
    for (int i = tid; i < L; i += 128) chars[i] = src[i];
    __syncthreads();
    int c4 = tid * 4;
    float mx0 = -1e30f, mx1 = -1e30f, mx2 = -1e30f, mx3 = -1e30f;
    int Lout = L - 4;
    #pragma unroll 2
    for (int t = 0; t < Lout; t++) {
        float s0 = 0.f, s1 = 0.f, s2 = 0.f, s3 = 0.f;
        #pragma unroll
        for (int w = 0; w < 5; w++) {
            const float4 p = *(const float4*)&d_P[(size_t)chars[t + w] * PCOLS + (w << 9) + c4];
            s0 += p.x; s1 += p.y; s2 += p.z; s3 += p.w;
        }
        mx0 = fmaxf(mx0, s0); mx1 = fmaxf(mx1, s1);
        mx2 = fmaxf(mx2, s2); mx3 = fmaxf(mx3, s3);
    }
    const float4 bb = *(const float4*)&conv_b[c4];
    float4 o;
    o.x = fmaxf(0.f, mx0 + bb.x); o.y = fmaxf(0.f, mx1 + bb.y);
    o.z = fmaxf(0.f, mx2 + bb.z); o.w = fmaxf(0.f, mx3 + bb.w);
    *(float4*)&d_Feats[(size_t)b * CCSN + c4] = o;
}

__global__ void __launch_bounds__(128) lstm_kernel(
    const int* __restrict__ cand_idx,
    const float* __restrict__ bih_f, const float* __restrict__ bhh_f,
    const float* __restrict__ bih_b, const float* __restrict__ bhh_b)
{
    __shared__ __align__(16) float hsm2[HHN][4];     // [h][s]
    __shared__ __align__(16) float presm[4][512];
    __shared__ int rowIdx[4][KC];
    int tid = threadIdx.x;
    int dir = blockIdx.y;
    int s0 = blockIdx.x * 4;
    const float* bih = dir ? bih_b : bih_f;
    const float* bhh = dir ? bhh_b : bhh_f;
    const float* Wt = d_Wt + dir * 65536;
    int preOff = dir * 512;
    float bias[4];
    #pragma unroll
    for (int g = 0; g < 4; g++) { int col = (g << 7) + tid; bias[g] = bih[col] + bhh[col]; }
    {
        int s = tid >> 5, t = tid & 31;
        int seq = s0 + s;
        int row;
        if (seq < 64)       row = cand_idx[seq * 32 + t];
        else if (seq < 128) row = NENT + cand_idx[(seq - 64) * 32 + t];
        else if (seq < 192) row = 2 * NENT + (seq - 128);
        else                row = NFEAT - 1;
        rowIdx[s][t] = row;
    }
    *(float4*)&hsm2[tid][0] = make_float4(0.f, 0.f, 0.f, 0.f);
    float cst[4] = {0.f, 0.f, 0.f, 0.f};
    int nS = NSEQ - s0; if (nS > 4) nS = 4;
    __syncthreads();
    for (int st = 0; st < KC; st++) {
        int t = dir ? (KC - 1 - st) : st;
        #pragma unroll
        for (int s = 0; s < 4; s++) {
            const float* prow = d_Pre + (size_t)rowIdx[s][t] * 1024 + preOff;
            *(float4*)&presm[s][tid * 4] = *(const float4*)&prow[tid * 4];
        }
        __syncthreads();
        // acc2[g][p]: packed pair over s={2p, 2p+1}
        u64t acc2[4][2];
        #pragma unroll
        for (int g = 0; g < 4; g++) {
            int col = (g << 7) + tid;
            acc2[g][0] = pack2(presm[0][col] + bias[g], presm[1][col] + bias[g]);
            acc2[g][1] = pack2(presm[2][col] + bias[g], presm[3][col] + bias[g]);
        }
        #pragma unroll 4
        for (int hb = 0; hb < 32; hb++) {
            ulonglong2 hv[4];
            #pragma unroll
            for (int j = 0; j < 4; j++)
                hv[j] = *(const ulonglong2*)&hsm2[hb * 4 + j][0];
            #pragma unroll
            for (int g = 0; g < 4; g++) {
                const float4 wv = *(const float4*)&Wt[hb * 2048 + (((g << 7) + tid) << 2)];
                u64t w0 = pack2(wv.x, wv.x), w1 = pack2(wv.y, wv.y);
                u64t w2 = pack2(wv.z, wv.z), w3 = pack2(wv.w, wv.w);
                fma2(acc2[g][0], w0, hv[0].x); fma2(acc2[g][1], w0, hv[0].y);
                fma2(acc2[g][0], w1, hv[1].x); fma2(acc2[g][1], w1, hv[1].y);
                fma2(acc2[g][0], w2, hv[2].x); fma2(acc2[g][1], w2, hv[2].y);
                fma2(acc2[g][0], w3, hv[3].x); fma2(acc2[g][1], w3, hv[3].y);
            }
        }
        float accs[4][4];
        #pragma unroll
        for (int g = 0; g < 4; g++) {
            unpack2(acc2[g][0], accs[g][0], accs[g][1]);
            unpack2(acc2[g][1], accs[g][2], accs[g][3]);
        }
        float hnew[4];
        #pragma unroll
        for (int s = 0; s < 4; s++) {
            float ig = sigf(accs[0][s]);
            float fg = sigf(accs[1][s]);
            float gg = tanhf(accs[2][s]);
            float og = sigf(accs[3][s]);
            cst[s] = fg * cst[s] + ig * gg;
            hnew[s] = og * tanhf(cst[s]);
        }
        __syncthreads();
        *(float4*)&hsm2[tid][0] = *(const float4*)&hnew[0];
        #pragma unroll
        for (int s = 0; s < 4; s++) {
            if (s < nS)
                d_Hout[((size_t)(s0 + s) * KC + t) * 256 + dir * HHN + tid] = hnew[s];
        }
    }
}

__global__ void __launch_bounds__(256) att_kernel(
    const float* __restrict__ wc, const float* __restrict__ bcp,
    const float* __restrict__ wq, const float* __restrict__ bqp,
    const float* __restrict__ wcq, const float* __restrict__ bcqp,
    const float* __restrict__ wz, const float* __restrict__ bzp)
{
    extern __shared__ float sbuf[];
    float* csm = sbuf;
    float* qsm = csm + 8224;
    float* sA  = qsm + 8224;
    float* cwcA = sA + 1056;
    float* qwqA = cwcA + 32;
    float* rowmaxA = qwqA + 32;
    float* betaA = rowmaxA + 32;
    float* q2cA = betaA + 32;
    float* wcqs = q2cA + 256;
    int m = blockIdx.x, fl = blockIdx.y, tid = threadIdx.x;
    int seqC = fl ? 192 : (128 + m);
    int seqQ = fl ? (64 + m) : m;
    const float* Crow = d_Hout + (size_t)seqC * KC * 256;
    const float* Qrow = d_Hout + (size_t)seqQ * KC * 256;
    for (int idx = tid; idx < 32 * 256; idx += 256) {
        int i = idx >> 8, d = idx & 255;
        csm[i * 257 + d] = Crow[i * 256 + d];
        qsm[i * 257 + d] = Qrow[i * 256 + d];
    }
    wcqs[tid] = wcq[tid];
    __syncthreads();
    if (tid < 32) {
        float a = 0.f;
        for (int d = 0; d < 256; d++) a += csm[tid * 257 + d] * wc[d];
        cwcA[tid] = a;
    } else if (tid < 64) {
        int j = tid - 32;
        float a = 0.f;
        for (int d = 0; d < 256; d++) a += qsm[j * 257 + d] * wq[d];
        qwqA[j] = a;
    }
    __syncthreads();
    float K0 = bcp[0] + bqp[0] + bcqp[0];
    for (int e = tid; e < 1024; e += 256) {
        int i = e >> 5, j = e & 31;
        float acc = 0.f;
        for (int d = 0; d < 256; d++)
            acc += csm[i * 257 + d] * wcqs[d] * qsm[j * 257 + d];
        sA[i * 33 + j] = acc + cwcA[i] + qwqA[j] + K0;
    }
    __syncthreads();
    if (tid < 32) {
        int i = tid;
        float mx = -1e30f;
        for (int j = 0; j < 32; j++) mx = fmaxf(mx, sA[i * 33 + j]);
        rowmaxA[i] = mx;
        float s = 0.f;
        for (int j = 0; j < 32; j++) { float e2 = expf(sA[i * 33 + j] - mx); sA[i * 33 + j] = e2; s += e2; }
        float inv = 1.f / s;
        for (int j = 0; j < 32; j++) sA[i * 33 + j] *= inv;
    }
    __syncthreads();
    if (tid == 0) {
        float mx = -1e30f;
        for (int i = 0; i < 32; i++) mx = fmaxf(mx, rowmaxA[i]);
        float s = 0.f;
        for (int i = 0; i < 32; i++) { float e2 = expf(rowmaxA[i] - mx); betaA[i] = e2; s += e2; }
        float inv = 1.f / s;
        for (int i = 0; i < 32; i++) betaA[i] *= inv;
    }
    __syncthreads();
    {
        float a = 0.f;
        for (int i = 0; i < 32; i++) a += betaA[i] * csm[i * 257 + tid];
        q2cA[tid] = a;
    }
    __syncthreads();
    {
        int i = tid >> 3, sub = tid & 7, d0 = sub * 32;
        float pp = 0.f;
        for (int dd = 0; dd < 32; dd++) {
            int d = d0 + dd;
            float c2 = 0.f;
            for (int j = 0; j < 32; j++) c2 += sA[i * 33 + j] * qsm[j * 257 + d];
            float cd = csm[i * 257 + d];
            pp += cd * wz[d] + c2 * wz[256 + d] + cd * c2 * wz[512 + d] + cd * q2cA[d] * wz[768 + d];
        }
        pp += __shfl_xor_sync(0xffffffffu, pp, 1);
        pp += __shfl_xor_sync(0xffffffffu, pp, 2);
        pp += __shfl_xor_sync(0xffffffffu, pp, 4);
        if (sub == 0) d_Pp[fl * 2048 + m * 32 + i] = pp + bzp[0];
    }
}

__global__ void __launch_bounds__(256) final_kernel(
    const int* __restrict__ cand,
    const float* __restrict__ wp1, const float* __restrict__ bp1,
    const float* __restrict__ wp2, const float* __restrict__ bp2,
    float* __restrict__ out)
{
    int m = blockIdx.x, tid = threadIdx.x;
    const int R = MMEN * NENT;
    for (int j = tid; j < NENT; j += 256) {
        out[m * NENT + j] = 0.f;
        out[R + m * NENT + j] = 0.f;
        out[2 * R + m * NENT + j] = 0.f;
    }
    __syncthreads();
    if (tid < 32) {
        float s = wp1[0] * d_Pp[m * 32 + tid] + bp1[0] + wp2[0] * d_Pp[2048 + m * 32 + tid] + bp2[0];
        float mx = s;
        #pragma unroll
        for (int o = 16; o; o >>= 1) mx = fmaxf(mx, __shfl_xor_sync(0xffffffffu, mx, o));
        float e = expf(s - mx);
        float se = e, ss = s;
        #pragma unroll
        for (int o = 16; o; o >>= 1) {
            se += __shfl_xor_sync(0xffffffffu, se, o);
            ss += __shfl_xor_sync(0xffffffffu, ss, o);
        }
        int col = cand[m * 32 + tid];
        out[m * NENT + col] = s;
        out[R + m * NENT + col] = e / se;
        out[2 * R + m * NENT + col] = s / ss;
    }
}

extern "C" void kernel_launch(void* const* d_in, const int* in_sizes, int n_in,
                              void* d_out, int out_size) {
    const int* title = (const int*)d_in[0];
    const int* body  = (const int*)d_in[1];
    const int* ctx   = (const int*)d_in[3];
    const int* doc   = (const int*)d_in[4];
    const int* cand  = (const int*)d_in[5];
    const float* emb    = (const float*)d_in[6];
    const float* conv_w = (const float*)d_in[7];
    const float* conv_b = (const float*)d_in[8];
    const float* Wih_f = (const float*)d_in[9];
    const float* Whh_f = (const float*)d_in[10];
    const float* bih_f = (const float*)d_in[11];
    const float* bhh_f = (const float*)d_in[12];
    const float* Wih_b = (const float*)d_in[13];
    const float* Whh_b = (const float*)d_in[14];
    const float* bih_b = (const float*)d_in[15];
    const float* bhh_b = (const float*)d_in[16];
    const float* wc  = (const float*)d_in[17];
    const float* bc  = (const float*)d_in[18];
    const float* wq  = (const float*)d_in[19];
    const float* bq  = (const float*)d_in[20];
    const float* wcq = (const float*)d_in[21];
    const float* bcq = (const float*)d_in[22];
    const float* wz  = (const float*)d_in[23];
    const float* bz  = (const float*)d_in[24];
    const float* w_p1 = (const float*)d_in[25];
    const float* b_p1 = (const float*)d_in[26];
    const float* w_p2 = (const float*)d_in[27];
    const float* b_p2 = (const float*)d_in[28];
    float* out = (float*)d_out;

    float *pB1t, *pP, *pFeats, *pWcat, *pPre;
    cudaGetSymbolAddress((void**)&pB1t, d_B1t);
    cudaGetSymbolAddress((void**)&pP, d_P);
    cudaGetSymbolAddress((void**)&pFeats, d_Feats);
    cudaGetSymbolAddress((void**)&pWcat, d_Wcat);
    cudaGetSymbolAddress((void**)&pPre, d_Pre);

    const int PREP_TOT = EMBD * PCOLS + CCSN * 1024 + 2 * 32 * 2048;
    prep_kernel<<<(PREP_TOT + 255) / 256, 256>>>(conv_w, Wih_f, Wih_b, Whh_f, Whh_b);
    gemm_kernel<<<dim3(PCOLS / 128, (VOCABN + 127) / 128), 256>>>(VOCABN, PCOLS, EMBD, emb, pB1t, pP);
    conv_kernel<<<NFEAT, 128>>>(title, body, ctx, doc, conv_b);
    gemm_kernel<<<dim3(1024 / 128, (NFEAT + 127) / 128), 256>>>(NFEAT, 1024, CCSN, pFeats, pWcat, pPre);
    lstm_kernel<<<dim3((NSEQ + 3) / 4, 2), 128>>>(cand, bih_f, bhh_f, bih_b, bhh_b);
    cudaFuncSetAttribute(att_kernel, cudaFuncAttributeMaxDynamicSharedMemorySize, 73728);
    att_kernel<<<dim3(MMEN, 2), 256, 72576>>>(wc, bc, wq, bq, wcq, bcq, wz, bz);
    final_kernel<<<MMEN, 256>>>(cand, w_p1, b_p1, w_p2, b_p2, out);
}

// round 6
// speedup vs baseline: 1.5371x; 1.2226x over previous
#include <cuda_runtime.h>
#include <cuda_bf16.h>
#include <math.h>

#define NENT   2048
#define MMEN   64
#define KC     32
#define VOCABN 5053
#define EMBD   300
#define CCSN   512
#define PCOLS  2560
#define HHN    128
#define NSEQ   193
#define NFEAT  4161
#define MPAD1  5120
#define KPAD1  320
#define MPAD2  4224
#define KPAD2  512

__device__ __align__(16) float d_P[VOCABN * PCOLS];
__device__ __align__(16) float d_Pre[NFEAT * 1024];
__device__ __align__(16) float d_Hout[NSEQ * KC * 256];
__device__ __align__(16) float d_Pp[2 * MMEN * KC];
__device__ __align__(16) float d_Wt[2 * 32 * 2048];
__device__ __align__(16) __nv_bfloat16 d_AeH[MPAD1 * KPAD1];
__device__ __align__(16) __nv_bfloat16 d_AeL[MPAD1 * KPAD1];
__device__ __align__(16) __nv_bfloat16 d_B1H[PCOLS * KPAD1];
__device__ __align__(16) __nv_bfloat16 d_B1L[PCOLS * KPAD1];
__device__ __align__(16) __nv_bfloat16 d_FtH[MPAD2 * KPAD2];
__device__ __align__(16) __nv_bfloat16 d_FtL[MPAD2 * KPAD2];
__device__ __align__(16) __nv_bfloat16 d_WcH[1024 * KPAD2];
__device__ __align__(16) __nv_bfloat16 d_WcL[1024 * KPAD2];

typedef unsigned long long u64t;

__device__ __forceinline__ float sigf(float x) { return 1.f / (1.f + expf(-x)); }

__device__ __forceinline__ unsigned smem_u32(const void* p) {
    unsigned r;
    asm("{ .reg .u64 t; cvta.to.shared.u64 t, %1; cvt.u32.u64 %0, t; }" : "=r"(r) : "l"(p));
    return r;
}

static __device__ __forceinline__ void split_bf16(float v, __nv_bfloat16& h, __nv_bfloat16& l) {
    h = __float2bfloat16(v);
    l = __float2bfloat16(v - __bfloat162float(h));
}

__device__ __forceinline__ void ldmx4(unsigned* a, unsigned addr) {
    asm volatile("ldmatrix.sync.aligned.m8n8.x4.shared.b16 {%0,%1,%2,%3}, [%4];"
        : "=r"(a[0]), "=r"(a[1]), "=r"(a[2]), "=r"(a[3]) : "r"(addr));
}
__device__ __forceinline__ void ldmx2(unsigned* b, unsigned addr) {
    asm volatile("ldmatrix.sync.aligned.m8n8.x2.shared.b16 {%0,%1}, [%2];"
        : "=r"(b[0]), "=r"(b[1]) : "r"(addr));
}
__device__ __forceinline__ void mma16816(float* c, const unsigned* a, const unsigned* b) {
    asm volatile("mma.sync.aligned.m16n8k16.row.col.f32.bf16.bf16.f32 "
        "{%0,%1,%2,%3}, {%4,%5,%6,%7}, {%8,%9}, {%0,%1,%2,%3};"
        : "+f"(c[0]), "+f"(c[1]), "+f"(c[2]), "+f"(c[3])
        : "r"(a[0]), "r"(a[1]), "r"(a[2]), "r"(a[3]), "r"(b[0]), "r"(b[1]));
}

__global__ void prep_kernel(const float* __restrict__ conv_w,
                            const float* __restrict__ Wih_f,
                            const float* __restrict__ Wih_b,
                            const float* __restrict__ Whh_f,
                            const float* __restrict__ Whh_b,
                            const float* __restrict__ emb) {
    int i = blockIdx.x * blockDim.x + threadIdx.x;
    const int T1 = PCOLS * KPAD1;
    const int T2 = 1024 * KPAD2;
    const int T3 = MPAD1 * KPAD1;
    const int T4 = 2 * 32 * 2048;
    if (i < T1) {
        int j = i / KPAD1, e = i - j * KPAD1;
        int w = j >> 9, c = j & 511;
        float v = (e < EMBD) ? conv_w[c * (EMBD * 5) + e * 5 + w] : 0.f;
        split_bf16(v, d_B1H[i], d_B1L[i]);
        return;
    }
    int i2 = i - T1;
    if (i2 < T2) {
        int n = i2 >> 9, k = i2 & 511;
        int dir = n >> 9, col = n & 511;
        float v = (dir ? Wih_b : Wih_f)[col * CCSN + k];
        split_bf16(v, d_WcH[i2], d_WcL[i2]);
        return;
    }
    int i3 = i2 - T2;
    if (i3 < T3) {
        int r = i3 / KPAD1, k = i3 - r * KPAD1;
        float v = (r < VOCABN && k < EMBD) ? emb[r * EMBD + k] : 0.f;
        split_bf16(v, d_AeH[i3], d_AeL[i3]);
        return;
    }
    int i4 = i3 - T3;
    if (i4 < T4) {
        int dir = i4 >> 16;
        int r = i4 & 65535;
        int hb = r >> 11, rem = r & 2047;
        int col = rem >> 2, j = rem & 3;
        const float* W = dir ? Whh_b : Whh_f;
        d_Wt[i4] = W[col * HHN + hb * 4 + j];
    }
}

// C[M,N] = (AH+AL)[Mpad,Kpad] @ (BH+BL)[N,Kpad]^T via mma.sync bf16, 3-term split
#define SROW 40   // smem row stride in halves (32 data + 8 pad)
__global__ void __launch_bounds__(256) gemm_mma(
    int M, int Kpad, int ldc,
    const __nv_bfloat16* __restrict__ AH, const __nv_bfloat16* __restrict__ AL,
    const __nv_bfloat16* __restrict__ BH, const __nv_bfloat16* __restrict__ BL,
    float* __restrict__ C)
{
    __shared__ __align__(16) __nv_bfloat16 sAH[128 * SROW];
    __shared__ __align__(16) __nv_bfloat16 sAL[128 * SROW];
    __shared__ __align__(16) __nv_bfloat16 sBH[128 * SROW];
    __shared__ __align__(16) __nv_bfloat16 sBL[128 * SROW];
    int tid = threadIdx.x, wid = tid >> 5, lane = tid & 31;
    int gm0 = blockIdx.y * 128, gn0 = blockIdx.x * 128;
    int wm0 = (wid & 1) * 64, wn0 = (wid >> 1) * 32;
    unsigned bAH = smem_u32(sAH), bAL = smem_u32(sAL);
    unsigned bBH = smem_u32(sBH), bBL = smem_u32(sBL);

    float acc[4][4][4];
    #pragma unroll
    for (int mi = 0; mi < 4; mi++)
        #pragma unroll
        for (int ni = 0; ni < 4; ni++)
            #pragma unroll
            for (int x = 0; x < 4; x++) acc[mi][ni][x] = 0.f;

    // load indices: each thread handles 2 rows per tile
    int lr = tid >> 2, lq = tid & 3;
    // ldmatrix address components
    int arow = lane & 15;            // A: row within 16-row tile
    int acol = (lane >> 4) * 8;      // A: k-offset half
    int brow = lane & 7;             // B: n-row within 8
    int bcol = lane & 8;             // B: k-offset half (0 or 8)

    int nchunks = Kpad >> 5;
    for (int kc = 0; kc < nchunks; kc++) {
        int kbase = kc << 5;
        {
            size_t ga0 = (size_t)(gm0 + lr) * Kpad + kbase + lq * 8;
            size_t ga1 = (size_t)(gm0 + lr + 64) * Kpad + kbase + lq * 8;
            size_t gb0 = (size_t)(gn0 + lr) * Kpad + kbase + lq * 8;
            size_t gb1 = (size_t)(gn0 + lr + 64) * Kpad + kbase + lq * 8;
            int so0 = lr * SROW + lq * 8, so1 = (lr + 64) * SROW + lq * 8;
            *(uint4*)&sAH[so0] = *(const uint4*)(AH + ga0);
            *(uint4*)&sAH[so1] = *(const uint4*)(AH + ga1);
            *(uint4*)&sAL[so0] = *(const uint4*)(AL + ga0);
            *(uint4*)&sAL[so1] = *(const uint4*)(AL + ga1);
            *(uint4*)&sBH[so0] = *(const uint4*)(BH + gb0);
            *(uint4*)&sBH[so1] = *(const uint4*)(BH + gb1);
            *(uint4*)&sBL[so0] = *(const uint4*)(BL + gb0);
            *(uint4*)&sBL[so1] = *(const uint4*)(BL + gb1);
        }
        __syncthreads();
        #pragma unroll
        for (int ko = 0; ko < 32; ko += 16) {
            unsigned fAH[4][4], fAL[4][4], fBH[4][2], fBL[4][2];
            #pragma unroll
            for (int ni = 0; ni < 4; ni++) {
                unsigned off = ((unsigned)((wn0 + ni * 8 + brow) * SROW + ko + bcol)) * 2u;
                ldmx2(fBH[ni], bBH + off);
                ldmx2(fBL[ni], bBL + off);
            }
            #pragma unroll
            for (int mi = 0; mi < 4; mi++) {
                unsigned off = ((unsigned)((wm0 + mi * 16 + arow) * SROW + ko + acol)) * 2u;
                ldmx4(fAH[mi], bAH + off);
                ldmx4(fAL[mi], bAL + off);
            }
            #pragma unroll
            for (int mi = 0; mi < 4; mi++)
                #pragma unroll
                for (int ni = 0; ni < 4; ni++) {
                    mma16816(acc[mi][ni], fAH[mi], fBH[ni]);
                    mma16816(acc[mi][ni], fAH[mi], fBL[ni]);
                    mma16816(acc[mi][ni], fAL[mi], fBH[ni]);
                }
        }
        __syncthreads();
    }
    int gid = lane >> 2, tc = (lane & 3) * 2;
    #pragma unroll
    for (int mi = 0; mi < 4; mi++) {
        #pragma unroll
        for (int ni = 0; ni < 4; ni++) {
            int m0 = gm0 + wm0 + mi * 16 + gid;
            int n = gn0 + wn0 + ni * 8 + tc;
            if (m0 < M) {
                float2 v; v.x = acc[mi][ni][0]; v.y = acc[mi][ni][1];
                *(float2*)&C[(size_t)m0 * ldc + n] = v;
            }
            if (m0 + 8 < M) {
                float2 v; v.x = acc[mi][ni][2]; v.y = acc[mi][ni][3];
                *(float2*)&C[(size_t)(m0 + 8) * ldc + n] = v;
            }
        }
    }
}

__global__ void __launch_bounds__(128) conv_kernel(
    const int* __restrict__ title, const int* __restrict__ body,
    const int* __restrict__ ctx, const int* __restrict__ doc,
    const float* __restrict__ conv_b)
{
    __shared__ int chars[512];
    int b = blockIdx.x, tid = threadIdx.x;
    int c4 = tid * 4;
    if (b >= NFEAT) {
        #pragma unroll
        for (int i = 0; i < 4; i++) {
            d_FtH[(size_t)b * CCSN + c4 + i] = __float2bfloat16(0.f);
            d_FtL[(size_t)b * CCSN + c4 + i] = __float2bfloat16(0.f);
        }
        return;
    }
    const int* src; int L;
    if (b < NENT)                 { src = title + b * 32;             L = 32;  }
    else if (b < 2 * NENT)        { src = body + (b - NENT) * 128;    L = 128; }
    else if (b < 2 * NENT + MMEN) { src = ctx + (b - 2 * NENT) * 128; L = 128; }
    else                          { src = doc;                        L = 512; }
    for (int i = tid; i < L; i += 128) chars[i] = src[i];
    __syncthreads();
    float mx0 = -1e30f, mx1 = -1e30f, mx2 = -1e30f, mx3 = -1e30f;
    int Lout = L - 4;
    #pragma unroll 2
    for (int t = 0; t < Lout; t++) {
        float s0 = 0.f, s1 = 0.f, s2 = 0.f, s3 = 0.f;
        #pragma unroll
        for (int w = 0; w < 5; w++) {
            const float4 p = *(const float4*)&d_P[(size_t)chars[t + w] * PCOLS + (w << 9) + c4];
            s0 += p.x; s1 += p.y; s2 += p.z; s3 += p.w;
        }
        mx0 = fmaxf(mx0, s0); mx1 = fmaxf(mx1, s1);
        mx2 = fmaxf(mx2, s2); mx3 = fmaxf(mx3, s3);
    }
    const float4 bb = *(const float4*)&conv_b[c4];
    float o[4];
    o[0] = fmaxf(0.f, mx0 + bb.x); o[1] = fmaxf(0.f, mx1 + bb.y);
    o[2] = fmaxf(0.f, mx2 + bb.z); o[3] = fmaxf(0.f, mx3 + bb.w);
    #pragma unroll
    for (int i = 0; i < 4; i++) {
        __nv_bfloat16 h, l;
        split_bf16(o[i], h, l);
        d_FtH[(size_t)b * CCSN + c4 + i] = h;
        d_FtL[(size_t)b * CCSN + c4 + i] = l;
    }
}

__device__ __forceinline__ u64t pack2(float x, float y) {
    u64t r;
    asm("mov.b64 %0, {%1, %2};" : "=l"(r) : "f"(x), "f"(y));
    return r;
}
__device__ __forceinline__ void unpack2(u64t v, float& x, float& y) {
    asm("mov.b64 {%0, %1}, %2;" : "=f"(x), "=f"(y) : "l"(v));
}
__device__ __forceinline__ void fma2(u64t& d, u64t a, u64t b) {
    asm("fma.rn.f32x2 %0, %1, %2, %0;" : "+l"(d) : "l"(a), "l"(b));
}

__global__ void __launch_bounds__(128) lstm_kernel(
    const int* __restrict__ cand_idx,
    const float* __restrict__ bih_f, const float* __restrict__ bhh_f,
    const float* __restrict__ bih_b, const float* __restrict__ bhh_b)
{
    __shared__ __align__(16) float hsm2[HHN][4];
    __shared__ __align__(16) float presm[4][512];
    __shared__ int rowIdx[4][KC];
    int tid = threadIdx.x;
    int dir = blockIdx.y;
    int s0 = blockIdx.x * 4;
    const float* bih = dir ? bih_b : bih_f;
    const float* bhh = dir ? bhh_b : bhh_f;
    const float* Wt = d_Wt + dir * 65536;
    int preOff = dir * 512;
    float bias[4];
    #pragma unroll
    for (int g = 0; g < 4; g++) { int col = (g << 7) + tid; bias[g] = bih[col] + bhh[col]; }
    {
        int s = tid >> 5, t = tid & 31;
        int seq = s0 + s;
        int row;
        if (seq < 64)       row = cand_idx[seq * 32 + t];
        else if (seq < 128) row = NENT + cand_idx[(seq - 64) * 32 + t];
        else if (seq < 192) row = 2 * NENT + (seq - 128);
        else                row = NFEAT - 1;
        rowIdx[s][t] = row;
    }
    *(float4*)&hsm2[tid][0] = make_float4(0.f, 0.f, 0.f, 0.f);
    float cst[4] = {0.f, 0.f, 0.f, 0.f};
    int nS = NSEQ - s0; if (nS > 4) nS = 4;
    __syncthreads();
    for (int st = 0; st < KC; st++) {
        int t = dir ? (KC - 1 - st) : st;
        #pragma unroll
        for (int s = 0; s < 4; s++) {
            const float* prow = d_Pre + (size_t)rowIdx[s][t] * 1024 + preOff;
            *(float4*)&presm[s][tid * 4] = *(const float4*)&prow[tid * 4];
        }
        __syncthreads();
        u64t acc2[4][2];
        #pragma unroll
        for (int g = 0; g < 4; g++) {
            int col = (g << 7) + tid;
            acc2[g][0] = pack2(presm[0][col] + bias[g], presm[1][col] + bias[g]);
            acc2[g][1] = pack2(presm[2][col] + bias[g], presm[3][col] + bias[g]);
        }
        #pragma unroll 4
        for (int hb = 0; hb < 32; hb++) {
            ulonglong2 hv[4];
            #pragma unroll
            for (int j = 0; j < 4; j++)
                hv[j] = *(const ulonglong2*)&hsm2[hb * 4 + j][0];
            #pragma unroll
            for (int g = 0; g < 4; g++) {
                const float4 wv = *(const float4*)&Wt[hb * 2048 + (((g << 7) + tid) << 2)];
                u64t w0 = pack2(wv.x, wv.x), w1 = pack2(wv.y, wv.y);
                u64t w2 = pack2(wv.z, wv.z), w3 = pack2(wv.w, wv.w);
                fma2(acc2[g][0], w0, hv[0].x); fma2(acc2[g][1], w0, hv[0].y);
                fma2(acc2[g][0], w1, hv[1].x); fma2(acc2[g][1], w1, hv[1].y);
                fma2(acc2[g][0], w2, hv[2].x); fma2(acc2[g][1], w2, hv[2].y);
                fma2(acc2[g][0], w3, hv[3].x); fma2(acc2[g][1], w3, hv[3].y);
            }
        }
        float accs[4][4];
        #pragma unroll
        for (int g = 0; g < 4; g++) {
            unpack2(acc2[g][0], accs[g][0], accs[g][1]);
            unpack2(acc2[g][1], accs[g][2], accs[g][3]);
        }
        float hnew[4];
        #pragma unroll
        for (int s = 0; s < 4; s++) {
            float ig = sigf(accs[0][s]);
            float fg = sigf(accs[1][s]);
            float gg = tanhf(accs[2][s]);
            float og = sigf(accs[3][s]);
            cst[s] = fg * cst[s] + ig * gg;
            hnew[s] = og * tanhf(cst[s]);
        }
        __syncthreads();
        *(float4*)&hsm2[tid][0] = *(const float4*)&hnew[0];
        #pragma unroll
        for (int s = 0; s < 4; s++) {
            if (s < nS)
                d_Hout[((size_t)(s0 + s) * KC + t) * 256 + dir * HHN + tid] = hnew[s];
        }
    }
}

__global__ void __launch_bounds__(256) att_kernel(
    const float* __restrict__ wc, const float* __restrict__ bcp,
    const float* __restrict__ wq, const float* __restrict__ bqp,
    const float* __restrict__ wcq, const float* __restrict__ bcqp,
    const float* __restrict__ wz, const float* __restrict__ bzp)
{
    extern __shared__ float sbuf[];
    float* csm = sbuf;
    float* qsm = csm + 8224;
    float* sA  = qsm + 8224;
    float* cwcA = sA + 1056;
    float* qwqA = cwcA + 32;
    float* rowmaxA = qwqA + 32;
    float* betaA = rowmaxA + 32;
    float* q2cA = betaA + 32;
    float* wcqs = q2cA + 256;
    int m = blockIdx.x, fl = blockIdx.y, tid = threadIdx.x;
    int seqC = fl ? 192 : (128 + m);
    int seqQ = fl ? (64 + m) : m;
    const float* Crow = d_Hout + (size_t)seqC * KC * 256;
    const float* Qrow = d_Hout + (size_t)seqQ * KC * 256;
    for (int idx = tid; idx < 32 * 256; idx += 256) {
        int i = idx >> 8, d = idx & 255;
        csm[i * 257 + d] = Crow[i * 256 + d];
        qsm[i * 257 + d] = Qrow[i * 256 + d];
    }
    wcqs[tid] = wcq[tid];
    __syncthreads();
    if (tid < 32) {
        float a = 0.f;
        for (int d = 0; d < 256; d++) a += csm[tid * 257 + d] * wc[d];
        cwcA[tid] = a;
    } else if (tid < 64) {
        int j = tid - 32;
        float a = 0.f;
        for (int d = 0; d < 256; d++) a += qsm[j * 257 + d] * wq[d];
        qwqA[j] = a;
    }
    __syncthreads();
    float K0 = bcp[0] + bqp[0] + bcqp[0];
    for (int e = tid; e < 1024; e += 256) {
        int i = e >> 5, j = e & 31;
        float acc = 0.f;
        for (int d = 0; d < 256; d++)
            acc += csm[i * 257 + d] * wcqs[d] * qsm[j * 257 + d];
        sA[i * 33 + j] = acc + cwcA[i] + qwqA[j] + K0;
    }
    __syncthreads();
    if (tid < 32) {
        int i = tid;
        float mx = -1e30f;
        for (int j = 0; j < 32; j++) mx = fmaxf(mx, sA[i * 33 + j]);
        rowmaxA[i] = mx;
        float s = 0.f;
        for (int j = 0; j < 32; j++) { float e2 = expf(sA[i * 33 + j] - mx); sA[i * 33 + j] = e2; s += e2; }
        float inv = 1.f / s;
        for (int j = 0; j < 32; j++) sA[i * 33 + j] *= inv;
    }
    __syncthreads();
    if (tid == 0) {
        float mx = -1e30f;
        for (int i = 0; i < 32; i++) mx = fmaxf(mx, rowmaxA[i]);
        float s = 0.f;
        for (int i = 0; i < 32; i++) { float e2 = expf(rowmaxA[i] - mx); betaA[i] = e2; s += e2; }
        float inv = 1.f / s;
        for (int i = 0; i < 32; i++) betaA[i] *= inv;
    }
    __syncthreads();
    {
        float a = 0.f;
        for (int i = 0; i < 32; i++) a += betaA[i] * csm[i * 257 + tid];
        q2cA[tid] = a;
    }
    __syncthreads();
    {
        int i = tid >> 3, sub = tid & 7, d0 = sub * 32;
        float pp = 0.f;
        for (int dd = 0; dd < 32; dd++) {
            int d = d0 + dd;
            float c2 = 0.f;
            for (int j = 0; j < 32; j++) c2 += sA[i * 33 + j] * qsm[j * 257 + d];
            float cd = csm[i * 257 + d];
            pp += cd * wz[d] + c2 * wz[256 + d] + cd * c2 * wz[512 + d] + cd * q2cA[d] * wz[768 + d];
        }
        pp += __shfl_xor_sync(0xffffffffu, pp, 1);
        pp += __shfl_xor_sync(0xffffffffu, pp, 2);
        pp += __shfl_xor_sync(0xffffffffu, pp, 4);
        if (sub == 0) d_Pp[fl * 2048 + m * 32 + i] = pp + bzp[0];
    }
}

__global__ void __launch_bounds__(256) final_kernel(
    const int* __restrict__ cand,
    const float* __restrict__ wp1, const float* __restrict__ bp1,
    const float* __restrict__ wp2, const float* __restrict__ bp2,
    float* __restrict__ out)
{
    int m = blockIdx.x, tid = threadIdx.x;
    const int R = MMEN * NENT;
    for (int j = tid; j < NENT; j += 256) {
        out[m * NENT + j] = 0.f;
        out[R + m * NENT + j] = 0.f;
        out[2 * R + m * NENT + j] = 0.f;
    }
    __syncthreads();
    if (tid < 32) {
        float s = wp1[0] * d_Pp[m * 32 + tid] + bp1[0] + wp2[0] * d_Pp[2048 + m * 32 + tid] + bp2[0];
        float mx = s;
        #pragma unroll
        for (int o = 16; o; o >>= 1) mx = fmaxf(mx, __shfl_xor_sync(0xffffffffu, mx, o));
        float e = expf(s - mx);
        float se = e, ss = s;
        #pragma unroll
        for (int o = 16; o; o >>= 1) {
            se += __shfl_xor_sync(0xffffffffu, se, o);
            ss += __shfl_xor_sync(0xffffffffu, ss, o);
        }
        int col = cand[m * 32 + tid];
        out[m * NENT + col] = s;
        out[R + m * NENT + col] = e / se;
        out[2 * R + m * NENT + col] = s / ss;
    }
}

extern "C" void kernel_launch(void* const* d_in, const int* in_sizes, int n_in,
                              void* d_out, int out_size) {
    const int* title = (const int*)d_in[0];
    const int* body  = (const int*)d_in[1];
    const int* ctx   = (const int*)d_in[3];
    const int* doc   = (const int*)d_in[4];
    const int* cand  = (const int*)d_in[5];
    const float* emb    = (const float*)d_in[6];
    const float* conv_w = (const float*)d_in[7];
    const float* conv_b = (const float*)d_in[8];
    const float* Wih_f = (const float*)d_in[9];
    const float* Whh_f = (const float*)d_in[10];
    const float* bih_f = (const float*)d_in[11];
    const float* bhh_f = (const float*)d_in[12];
    const float* Wih_b = (const float*)d_in[13];
    const float* Whh_b = (const float*)d_in[14];
    const float* bih_b = (const float*)d_in[15];
    const float* bhh_b = (const float*)d_in[16];
    const float* wc  = (const float*)d_in[17];
    const float* bc  = (const float*)d_in[18];
    const float* wq  = (const float*)d_in[19];
    const float* bq  = (const float*)d_in[20];
    const float* wcq = (const float*)d_in[21];
    const float* bcq = (const float*)d_in[22];
    const float* wz  = (const float*)d_in[23];
    const float* bz  = (const float*)d_in[24];
    const float* w_p1 = (const float*)d_in[25];
    const float* b_p1 = (const float*)d_in[26];
    const float* w_p2 = (const float*)d_in[27];
    const float* b_p2 = (const float*)d_in[28];
    float* out = (float*)d_out;

    float *pP, *pPre;
    __nv_bfloat16 *pAeH, *pAeL, *pB1H, *pB1L, *pFtH, *pFtL, *pWcH, *pWcL;
    cudaGetSymbolAddress((void**)&pP, d_P);
    cudaGetSymbolAddress((void**)&pPre, d_Pre);
    cudaGetSymbolAddress((void**)&pAeH, d_AeH);
    cudaGetSymbolAddress((void**)&pAeL, d_AeL);
    cudaGetSymbolAddress((void**)&pB1H, d_B1H);
    cudaGetSymbolAddress((void**)&pB1L, d_B1L);
    cudaGetSymbolAddress((void**)&pFtH, d_FtH);
    cudaGetSymbolAddress((void**)&pFtL, d_FtL);
    cudaGetSymbolAddress((void**)&pWcH, d_WcH);
    cudaGetSymbolAddress((void**)&pWcL, d_WcL);

    const int PREP_TOT = PCOLS * KPAD1 + 1024 * KPAD2 + MPAD1 * KPAD1 + 2 * 32 * 2048;
    cudaFuncSetAttribute(att_kernel, cudaFuncAttributeMaxDynamicSharedMemorySize, 73728);

    prep_kernel<<<(PREP_TOT + 255) / 256, 256>>>(conv_w, Wih_f, Wih_b, Whh_f, Whh_b, emb);
    gemm_mma<<<dim3(PCOLS / 128, MPAD1 / 128), 256>>>(
        VOCABN, KPAD1, PCOLS, pAeH, pAeL, pB1H, pB1L, pP);
    conv_kernel<<<MPAD2, 128>>>(title, body, ctx, doc, conv_b);
    gemm_mma<<<dim3(1024 / 128, MPAD2 / 128), 256>>>(
        NFEAT, KPAD2, 1024, pFtH, pFtL, pWcH, pWcL, pPre);
    lstm_kernel<<<dim3((NSEQ + 3) / 4, 2), 128>>>(cand, bih_f, bhh_f, bih_b, bhh_b);
    att_kernel<<<dim3(MMEN, 2), 256, 72576>>>(wc, bc, wq, bq, wcq, bcq, wz, bz);
    final_kernel<<<MMEN, 256>>>(cand, w_p1, b_p1, w_p2, b_p2, out);
}

// round 7
// speedup vs baseline: 1.7651x; 1.1483x over previous
#include <cuda_runtime.h>
#include <cuda_bf16.h>
#include <cuda_fp16.h>
#include <math.h>

#define NENT   2048
#define MMEN   64
#define KC     32
#define VOCABN 5053
#define EMBD   300
#define CCSN   512
#define PCOLS  2560
#define HHN    128
#define NSEQ   193
#define NFEAT  4161
#define MPAD1  5120
#define KPAD1  320
#define MPAD2  4224
#define KPAD2  512

__device__ __align__(16) __half d_Ph[VOCABN * PCOLS];
__device__ __align__(16) float d_Pre[NFEAT * 1024];
__device__ __align__(16) float d_Hout[NSEQ * KC * 256];
__device__ __align__(16) float d_Pp[2 * MMEN * KC];
__device__ __align__(16) float d_Wt[2 * 32 * 2048];
__device__ __align__(16) __nv_bfloat16 d_AeH[MPAD1 * KPAD1];
__device__ __align__(16) __nv_bfloat16 d_AeL[MPAD1 * KPAD1];
__device__ __align__(16) __nv_bfloat16 d_B1H[PCOLS * KPAD1];
__device__ __align__(16) __nv_bfloat16 d_B1L[PCOLS * KPAD1];
__device__ __align__(16) __nv_bfloat16 d_FtH[MPAD2 * KPAD2];
__device__ __align__(16) __nv_bfloat16 d_FtL[MPAD2 * KPAD2];
__device__ __align__(16) __nv_bfloat16 d_WcH[1024 * KPAD2];
__device__ __align__(16) __nv_bfloat16 d_WcL[1024 * KPAD2];

typedef unsigned long long u64t;

__device__ __forceinline__ float sigf(float x) { return 1.f / (1.f + expf(-x)); }

__device__ __forceinline__ unsigned smem_u32(const void* p) {
    unsigned r;
    asm("{ .reg .u64 t; cvta.to.shared.u64 t, %1; cvt.u32.u64 %0, t; }" : "=r"(r) : "l"(p));
    return r;
}

static __device__ __forceinline__ void split_bf16(float v, __nv_bfloat16& h, __nv_bfloat16& l) {
    h = __float2bfloat16(v);
    l = __float2bfloat16(v - __bfloat162float(h));
}

__device__ __forceinline__ void ldmx4(unsigned* a, unsigned addr) {
    asm volatile("ldmatrix.sync.aligned.m8n8.x4.shared.b16 {%0,%1,%2,%3}, [%4];"
        : "=r"(a[0]), "=r"(a[1]), "=r"(a[2]), "=r"(a[3]) : "r"(addr));
}
__device__ __forceinline__ void ldmx2(unsigned* b, unsigned addr) {
    asm volatile("ldmatrix.sync.aligned.m8n8.x2.shared.b16 {%0,%1}, [%2];"
        : "=r"(b[0]), "=r"(b[1]) : "r"(addr));
}
__device__ __forceinline__ void mma16816(float* c, const unsigned* a, const unsigned* b) {
    asm volatile("mma.sync.aligned.m16n8k16.row.col.f32.bf16.bf16.f32 "
        "{%0,%1,%2,%3}, {%4,%5,%6,%7}, {%8,%9}, {%0,%1,%2,%3};"
        : "+f"(c[0]), "+f"(c[1]), "+f"(c[2]), "+f"(c[3])
        : "r"(a[0]), "r"(a[1]), "r"(a[2]), "r"(a[3]), "r"(b[0]), "r"(b[1]));
}

__global__ void prep_kernel(const float* __restrict__ conv_w,
                            const float* __restrict__ Wih_f,
                            const float* __restrict__ Wih_b,
                            const float* __restrict__ Whh_f,
                            const float* __restrict__ Whh_b,
                            const float* __restrict__ emb) {
    int i = blockIdx.x * blockDim.x + threadIdx.x;
    const int T1 = PCOLS * KPAD1;
    const int T2 = 1024 * KPAD2;
    const int T3 = MPAD1 * KPAD1;
    const int T4 = 2 * 32 * 2048;
    if (i < T1) {
        int j = i / KPAD1, e = i - j * KPAD1;
        int w = j >> 9, c = j & 511;
        float v = (e < EMBD) ? conv_w[c * (EMBD * 5) + e * 5 + w] : 0.f;
        split_bf16(v, d_B1H[i], d_B1L[i]);
        return;
    }
    int i2 = i - T1;
    if (i2 < T2) {
        int n = i2 >> 9, k = i2 & 511;
        int dir = n >> 9, col = n & 511;
        float v = (dir ? Wih_b : Wih_f)[col * CCSN + k];
        split_bf16(v, d_WcH[i2], d_WcL[i2]);
        return;
    }
    int i3 = i2 - T2;
    if (i3 < T3) {
        int r = i3 / KPAD1, k = i3 - r * KPAD1;
        float v = (r < VOCABN && k < EMBD) ? emb[r * EMBD + k] : 0.f;
        split_bf16(v, d_AeH[i3], d_AeL[i3]);
        return;
    }
    int i4 = i3 - T3;
    if (i4 < T4) {
        int dir = i4 >> 16;
        int r = i4 & 65535;
        int hb = r >> 11, rem = r & 2047;
        int col = rem >> 2, j = rem & 3;
        const float* W = dir ? Whh_b : Whh_f;
        d_Wt[i4] = W[col * HHN + hb * 4 + j];
    }
}

// C[M,N] = (AH+AL) @ (BH+BL)^T via mma.sync bf16, 3-term split. HOUT: fp16 output.
#define SROW 40
template <int HOUT>
__global__ void __launch_bounds__(256) gemm_mma(
    int M, int Kpad, int ldc,
    const __nv_bfloat16* __restrict__ AH, const __nv_bfloat16* __restrict__ AL,
    const __nv_bfloat16* __restrict__ BH, const __nv_bfloat16* __restrict__ BL,
    void* __restrict__ Cv)
{
    __shared__ __align__(16) __nv_bfloat16 sAH[128 * SROW];
    __shared__ __align__(16) __nv_bfloat16 sAL[128 * SROW];
    __shared__ __align__(16) __nv_bfloat16 sBH[128 * SROW];
    __shared__ __align__(16) __nv_bfloat16 sBL[128 * SROW];
    int tid = threadIdx.x, wid = tid >> 5, lane = tid & 31;
    int gm0 = blockIdx.y * 128, gn0 = blockIdx.x * 128;
    int wm0 = (wid & 1) * 64, wn0 = (wid >> 1) * 32;
    unsigned bAH = smem_u32(sAH), bAL = smem_u32(sAL);
    unsigned bBH = smem_u32(sBH), bBL = smem_u32(sBL);

    float acc[4][4][4];
    #pragma unroll
    for (int mi = 0; mi < 4; mi++)
        #pragma unroll
        for (int ni = 0; ni < 4; ni++)
            #pragma unroll
            for (int x = 0; x < 4; x++) acc[mi][ni][x] = 0.f;

    int lr = tid >> 2, lq = tid & 3;
    int arow = lane & 15;
    int acol = (lane >> 4) * 8;
    int brow = lane & 7;
    int bcol = lane & 8;

    int nchunks = Kpad >> 5;
    for (int kc = 0; kc < nchunks; kc++) {
        int kbase = kc << 5;
        {
            size_t ga0 = (size_t)(gm0 + lr) * Kpad + kbase + lq * 8;
            size_t ga1 = (size_t)(gm0 + lr + 64) * Kpad + kbase + lq * 8;
            size_t gb0 = (size_t)(gn0 + lr) * Kpad + kbase + lq * 8;
            size_t gb1 = (size_t)(gn0 + lr + 64) * Kpad + kbase + lq * 8;
            int so0 = lr * SROW + lq * 8, so1 = (lr + 64) * SROW + lq * 8;
            *(uint4*)&sAH[so0] = *(const uint4*)(AH + ga0);
            *(uint4*)&sAH[so1] = *(const uint4*)(AH + ga1);
            *(uint4*)&sAL[so0] = *(const uint4*)(AL + ga0);
            *(uint4*)&sAL[so1] = *(const uint4*)(AL + ga1);
            *(uint4*)&sBH[so0] = *(const uint4*)(BH + gb0);
            *(uint4*)&sBH[so1] = *(const uint4*)(BH + gb1);
            *(uint4*)&sBL[so0] = *(const uint4*)(BL + gb0);
            *(uint4*)&sBL[so1] = *(const uint4*)(BL + gb1);
        }
        __syncthreads();
        #pragma unroll
        for (int ko = 0; ko < 32; ko += 16) {
            unsigned fAH[4][4], fAL[4][4], fBH[4][2], fBL[4][2];
            #pragma unroll
            for (int ni = 0; ni < 4; ni++) {
                unsigned off = ((unsigned)((wn0 + ni * 8 + brow) * SROW + ko + bcol)) * 2u;
                ldmx2(fBH[ni], bBH + off);
                ldmx2(fBL[ni], bBL + off);
            }
            #pragma unroll
            for (int mi = 0; mi < 4; mi++) {
                unsigned off = ((unsigned)((wm0 + mi * 16 + arow) * SROW + ko + acol)) * 2u;
                ldmx4(fAH[mi], bAH + off);
                ldmx4(fAL[mi], bAL + off);
            }
            #pragma unroll
            for (int mi = 0; mi < 4; mi++)
                #pragma unroll
                for (int ni = 0; ni < 4; ni++) {
                    mma16816(acc[mi][ni], fAH[mi], fBH[ni]);
                    mma16816(acc[mi][ni], fAH[mi], fBL[ni]);
                    mma16816(acc[mi][ni], fAL[mi], fBH[ni]);
                }
        }
        __syncthreads();
    }
    int gid = lane >> 2, tc = (lane & 3) * 2;
    #pragma unroll
    for (int mi = 0; mi < 4; mi++) {
        #pragma unroll
        for (int ni = 0; ni < 4; ni++) {
            int m0 = gm0 + wm0 + mi * 16 + gid;
            int n = gn0 + wn0 + ni * 8 + tc;
            if (HOUT) {
                __half* C = (__half*)Cv;
                if (m0 < M)
                    *(__half2*)&C[(size_t)m0 * ldc + n] =
                        __floats2half2_rn(acc[mi][ni][0], acc[mi][ni][1]);
                if (m0 + 8 < M)
                    *(__half2*)&C[(size_t)(m0 + 8) * ldc + n] =
                        __floats2half2_rn(acc[mi][ni][2], acc[mi][ni][3]);
            } else {
                float* C = (float*)Cv;
                if (m0 < M) {
                    float2 v; v.x = acc[mi][ni][0]; v.y = acc[mi][ni][1];
                    *(float2*)&C[(size_t)m0 * ldc + n] = v;
                }
                if (m0 + 8 < M) {
                    float2 v; v.x = acc[mi][ni][2]; v.y = acc[mi][ni][3];
                    *(float2*)&C[(size_t)(m0 + 8) * ldc + n] = v;
                }
            }
        }
    }
}

__global__ void __launch_bounds__(128) conv_kernel(
    const int* __restrict__ title, const int* __restrict__ body,
    const int* __restrict__ ctx, const int* __restrict__ doc,
    const float* __restrict__ conv_b)
{
    __shared__ int chars[512];
    int b = blockIdx.x, tid = threadIdx.x;
    int c4 = tid * 4;
    if (b >= NFEAT) {
        #pragma unroll
        for (int i = 0; i < 4; i++) {
            d_FtH[(size_t)b * CCSN + c4 + i] = __float2bfloat16(0.f);
            d_FtL[(size_t)b * CCSN + c4 + i] = __float2bfloat16(0.f);
        }
        return;
    }
    const int* src; int L;
    if (b < NENT)                 { src = title + b * 32;             L = 32;  }
    else if (b < 2 * NENT)        { src = body + (b - NENT) * 128;    L = 128; }
    else if (b < 2 * NENT + MMEN) { src = ctx + (b - 2 * NENT) * 128; L = 128; }
    else                          { src = doc;                        L = 512; }
    for (int i = tid; i < L; i += 128) chars[i] = src[i];
    __syncthreads();
    float mx0 = -1e30f, mx1 = -1e30f, mx2 = -1e30f, mx3 = -1e30f;
    int Lout = L - 4;
    #pragma unroll 2
    for (int t = 0; t < Lout; t++) {
        float s0 = 0.f, s1 = 0.f, s2 = 0.f, s3 = 0.f;
        #pragma unroll
        for (int w = 0; w < 5; w++) {
            const __half* prow = d_Ph + (size_t)chars[t + w] * PCOLS + (w << 9) + c4;
            uint2 u = *(const uint2*)prow;
            float2 f0 = __half22float2(*(const __half2*)&u.x);
            float2 f1 = __half22float2(*(const __half2*)&u.y);
            s0 += f0.x; s1 += f0.y; s2 += f1.x; s3 += f1.y;
        }
        mx0 = fmaxf(mx0, s0); mx1 = fmaxf(mx1, s1);
        mx2 = fmaxf(mx2, s2); mx3 = fmaxf(mx3, s3);
    }
    const float4 bb = *(const float4*)&conv_b[c4];
    float o[4];
    o[0] = fmaxf(0.f, mx0 + bb.x); o[1] = fmaxf(0.f, mx1 + bb.y);
    o[2] = fmaxf(0.f, mx2 + bb.z); o[3] = fmaxf(0.f, mx3 + bb.w);
    #pragma unroll
    for (int i = 0; i < 4; i++) {
        __nv_bfloat16 h, l;
        split_bf16(o[i], h, l);
        d_FtH[(size_t)b * CCSN + c4 + i] = h;
        d_FtL[(size_t)b * CCSN + c4 + i] = l;
    }
}

__device__ __forceinline__ u64t pack2(float x, float y) {
    u64t r;
    asm("mov.b64 %0, {%1, %2};" : "=l"(r) : "f"(x), "f"(y));
    return r;
}
__device__ __forceinline__ void unpack2(u64t v, float& x, float& y) {
    asm("mov.b64 {%0, %1}, %2;" : "=f"(x), "=f"(y) : "l"(v));
}
__device__ __forceinline__ void fma2(u64t& d, u64t a, u64t b) {
    asm("fma.rn.f32x2 %0, %1, %2, %0;" : "+l"(d) : "l"(a), "l"(b));
}

__global__ void __launch_bounds__(128) lstm_kernel(
    const int* __restrict__ cand_idx,
    const float* __restrict__ bih_f, const float* __restrict__ bhh_f,
    const float* __restrict__ bih_b, const float* __restrict__ bhh_b)
{
    __shared__ __align__(16) float hsm2[HHN][4];
    __shared__ __align__(16) float presm[4][512];
    __shared__ int rowIdx[4][KC];
    int tid = threadIdx.x;
    int dir = blockIdx.y;
    int s0 = blockIdx.x * 4;
    const float* bih = dir ? bih_b : bih_f;
    const float* bhh = dir ? bhh_b : bhh_f;
    const float* Wt = d_Wt + dir * 65536;
    int preOff = dir * 512;
    float bias[4];
    #pragma unroll
    for (int g = 0; g < 4; g++) { int col = (g << 7) + tid; bias[g] = bih[col] + bhh[col]; }
    {
        int s = tid >> 5, t = tid & 31;
        int seq = s0 + s;
        int row;
        if (seq < 64)       row = cand_idx[seq * 32 + t];
        else if (seq < 128) row = NENT + cand_idx[(seq - 64) * 32 + t];
        else if (seq < 192) row = 2 * NENT + (seq - 128);
        else                row = NFEAT - 1;
        rowIdx[s][t] = row;
    }
    *(float4*)&hsm2[tid][0] = make_float4(0.f, 0.f, 0.f, 0.f);
    float cst[4] = {0.f, 0.f, 0.f, 0.f};
    int nS = NSEQ - s0; if (nS > 4) nS = 4;
    __syncthreads();
    for (int st = 0; st < KC; st++) {
        int t = dir ? (KC - 1 - st) : st;
        #pragma unroll
        for (int s = 0; s < 4; s++) {
            const float* prow = d_Pre + (size_t)rowIdx[s][t] * 1024 + preOff;
            *(float4*)&presm[s][tid * 4] = *(const float4*)&prow[tid * 4];
        }
        __syncthreads();
        u64t acc2[4][2];
        #pragma unroll
        for (int g = 0; g < 4; g++) {
            int col = (g << 7) + tid;
            acc2[g][0] = pack2(presm[0][col] + bias[g], presm[1][col] + bias[g]);
            acc2[g][1] = pack2(presm[2][col] + bias[g], presm[3][col] + bias[g]);
        }
        #pragma unroll 4
        for (int hb = 0; hb < 32; hb++) {
            ulonglong2 hv[4];
            #pragma unroll
            for (int j = 0; j < 4; j++)
                hv[j] = *(const ulonglong2*)&hsm2[hb * 4 + j][0];
            #pragma unroll
            for (int g = 0; g < 4; g++) {
                const float4 wv = *(const float4*)&Wt[hb * 2048 + (((g << 7) + tid) << 2)];
                u64t w0 = pack2(wv.x, wv.x), w1 = pack2(wv.y, wv.y);
                u64t w2 = pack2(wv.z, wv.z), w3 = pack2(wv.w, wv.w);
                fma2(acc2[g][0], w0, hv[0].x); fma2(acc2[g][1], w0, hv[0].y);
                fma2(acc2[g][0], w1, hv[1].x); fma2(acc2[g][1], w1, hv[1].y);
                fma2(acc2[g][0], w2, hv[2].x); fma2(acc2[g][1], w2, hv[2].y);
                fma2(acc2[g][0], w3, hv[3].x); fma2(acc2[g][1], w3, hv[3].y);
            }
        }
        float accs[4][4];
        #pragma unroll
        for (int g = 0; g < 4; g++) {
            unpack2(acc2[g][0], accs[g][0], accs[g][1]);
            unpack2(acc2[g][1], accs[g][2], accs[g][3]);
        }
        float hnew[4];
        #pragma unroll
        for (int s = 0; s < 4; s++) {
            float ig = sigf(accs[0][s]);
            float fg = sigf(accs[1][s]);
            float gg = tanhf(accs[2][s]);
            float og = sigf(accs[3][s]);
            cst[s] = fg * cst[s] + ig * gg;
            hnew[s] = og * tanhf(cst[s]);
        }
        __syncthreads();
        *(float4*)&hsm2[tid][0] = *(const float4*)&hnew[0];
        #pragma unroll
        for (int s = 0; s < 4; s++) {
            if (s < nS)
                d_Hout[((size_t)(s0 + s) * KC + t) * 256 + dir * HHN + tid] = hnew[s];
        }
    }
}

__global__ void __launch_bounds__(256) att_kernel(
    const float* __restrict__ wc, const float* __restrict__ bcp,
    const float* __restrict__ wq, const float* __restrict__ bqp,
    const float* __restrict__ wcq, const float* __restrict__ bcqp,
    const float* __restrict__ wz, const float* __restrict__ bzp)
{
    extern __shared__ float sbuf[];
    float* csm = sbuf;
    float* qsm = csm + 8224;
    float* sA  = qsm + 8224;
    float* cwcA = sA + 1056;
    float* qwqA = cwcA + 32;
    float* rowmaxA = qwqA + 32;
    float* betaA = rowmaxA + 32;
    float* q2cA = betaA + 32;
    float* wcqs = q2cA + 256;
    int m = blockIdx.x, fl = blockIdx.y, tid = threadIdx.x;
    int seqC = fl ? 192 : (128 + m);
    int seqQ = fl ? (64 + m) : m;
    const float* Crow = d_Hout + (size_t)seqC * KC * 256;
    const float* Qrow = d_Hout + (size_t)seqQ * KC * 256;
    for (int idx = tid; idx < 32 * 256; idx += 256) {
        int i = idx >> 8, d = idx & 255;
        csm[i * 257 + d] = Crow[i * 256 + d];
        qsm[i * 257 + d] = Qrow[i * 256 + d];
    }
    wcqs[tid] = wcq[tid];
    __syncthreads();
    if (tid < 32) {
        float a = 0.f;
        for (int d = 0; d < 256; d++) a += csm[tid * 257 + d] * wc[d];
        cwcA[tid] = a;
    } else if (tid < 64) {
        int j = tid - 32;
        float a = 0.f;
        for (int d = 0; d < 256; d++) a += qsm[j * 257 + d] * wq[d];
        qwqA[j] = a;
    }
    __syncthreads();
    float K0 = bcp[0] + bqp[0] + bcqp[0];
    for (int e = tid; e < 1024; e += 256) {
        int i = e >> 5, j = e & 31;
        float acc = 0.f;
        for (int d = 0; d < 256; d++)
            acc += csm[i * 257 + d] * wcqs[d] * qsm[j * 257 + d];
        sA[i * 33 + j] = acc + cwcA[i] + qwqA[j] + K0;
    }
    __syncthreads();
    if (tid < 32) {
        int i = tid;
        float mx = -1e30f;
        for (int j = 0; j < 32; j++) mx = fmaxf(mx, sA[i * 33 + j]);
        rowmaxA[i] = mx;
        float s = 0.f;
        for (int j = 0; j < 32; j++) { float e2 = expf(sA[i * 33 + j] - mx); sA[i * 33 + j] = e2; s += e2; }
        float inv = 1.f / s;
        for (int j = 0; j < 32; j++) sA[i * 33 + j] *= inv;
    }
    __syncthreads();
    if (tid == 0) {
        float mx = -1e30f;
        for (int i = 0; i < 32; i++) mx = fmaxf(mx, rowmaxA[i]);
        float s = 0.f;
        for (int i = 0; i < 32; i++) { float e2 = expf(rowmaxA[i] - mx); betaA[i] = e2; s += e2; }
        float inv = 1.f / s;
        for (int i = 0; i < 32; i++) betaA[i] *= inv;
    }
    __syncthreads();
    {
        float a = 0.f;
        for (int i = 0; i < 32; i++) a += betaA[i] * csm[i * 257 + tid];
        q2cA[tid] = a;
    }
    __syncthreads();
    {
        int i = tid >> 3, sub = tid & 7, d0 = sub * 32;
        float pp = 0.f;
        for (int dd = 0; dd < 32; dd++) {
            int d = d0 + dd;
            float c2 = 0.f;
            for (int j = 0; j < 32; j++) c2 += sA[i * 33 + j] * qsm[j * 257 + d];
            float cd = csm[i * 257 + d];
            pp += cd * wz[d] + c2 * wz[256 + d] + cd * c2 * wz[512 + d] + cd * q2cA[d] * wz[768 + d];
        }
        pp += __shfl_xor_sync(0xffffffffu, pp, 1);
        pp += __shfl_xor_sync(0xffffffffu, pp, 2);
        pp += __shfl_xor_sync(0xffffffffu, pp, 4);
        if (sub == 0) d_Pp[fl * 2048 + m * 32 + i] = pp + bzp[0];
    }
}

__global__ void __launch_bounds__(256) final_kernel(
    const int* __restrict__ cand,
    const float* __restrict__ wp1, const float* __restrict__ bp1,
    const float* __restrict__ wp2, const float* __restrict__ bp2,
    float* __restrict__ out)
{
    int m = blockIdx.x, tid = threadIdx.x;
    const int R = MMEN * NENT;
    for (int j = tid; j < NENT; j += 256) {
        out[m * NENT + j] = 0.f;
        out[R + m * NENT + j] = 0.f;
        out[2 * R + m * NENT + j] = 0.f;
    }
    __syncthreads();
    if (tid < 32) {
        float s = wp1[0] * d_Pp[m * 32 + tid] + bp1[0] + wp2[0] * d_Pp[2048 + m * 32 + tid] + bp2[0];
        float mx = s;
        #pragma unroll
        for (int o = 16; o; o >>= 1) mx = fmaxf(mx, __shfl_xor_sync(0xffffffffu, mx, o));
        float e = expf(s - mx);
        float se = e, ss = s;
        #pragma unroll
        for (int o = 16; o; o >>= 1) {
            se += __shfl_xor_sync(0xffffffffu, se, o);
            ss += __shfl_xor_sync(0xffffffffu, ss, o);
        }
        int col = cand[m * 32 + tid];
        out[m * NENT + col] = s;
        out[R + m * NENT + col] = e / se;
        out[2 * R + m * NENT + col] = s / ss;
    }
}

extern "C" void kernel_launch(void* const* d_in, const int* in_sizes, int n_in,
                              void* d_out, int out_size) {
    const int* title = (const int*)d_in[0];
    const int* body  = (const int*)d_in[1];
    const int* ctx   = (const int*)d_in[3];
    const int* doc   = (const int*)d_in[4];
    const int* cand  = (const int*)d_in[5];
    const float* emb    = (const float*)d_in[6];
    const float* conv_w = (const float*)d_in[7];
    const float* conv_b = (const float*)d_in[8];
    const float* Wih_f = (const float*)d_in[9];
    const float* Whh_f = (const float*)d_in[10];
    const float* bih_f = (const float*)d_in[11];
    const float* bhh_f = (const float*)d_in[12];
    const float* Wih_b = (const float*)d_in[13];
    const float* Whh_b = (const float*)d_in[14];
    const float* bih_b = (const float*)d_in[15];
    const float* bhh_b = (const float*)d_in[16];
    const float* wc  = (const float*)d_in[17];
    const float* bc  = (const float*)d_in[18];
    const float* wq  = (const float*)d_in[19];
    const float* bq  = (const float*)d_in[20];
    const float* wcq = (const float*)d_in[21];
    const float* bcq = (const float*)d_in[22];
    const float* wz  = (const float*)d_in[23];
    const float* bz  = (const float*)d_in[24];
    const float* w_p1 = (const float*)d_in[25];
    const float* b_p1 = (const float*)d_in[26];
    const float* w_p2 = (const float*)d_in[27];
    const float* b_p2 = (const float*)d_in[28];
    float* out = (float*)d_out;

    float *pPre;
    __half* pPh;
    __nv_bfloat16 *pAeH, *pAeL, *pB1H, *pB1L, *pFtH, *pFtL, *pWcH, *pWcL;
    cudaGetSymbolAddress((void**)&pPh, d_Ph);
    cudaGetSymbolAddress((void**)&pPre, d_Pre);
    cudaGetSymbolAddress((void**)&pAeH, d_AeH);
    cudaGetSymbolAddress((void**)&pAeL, d_AeL);
    cudaGetSymbolAddress((void**)&pB1H, d_B1H);
    cudaGetSymbolAddress((void**)&pB1L, d_B1L);
    cudaGetSymbolAddress((void**)&pFtH, d_FtH);
    cudaGetSymbolAddress((void**)&pFtL, d_FtL);
    cudaGetSymbolAddress((void**)&pWcH, d_WcH);
    cudaGetSymbolAddress((void**)&pWcL, d_WcL);

    const int PREP_TOT = PCOLS * KPAD1 + 1024 * KPAD2 + MPAD1 * KPAD1 + 2 * 32 * 2048;
    cudaFuncSetAttribute(att_kernel, cudaFuncAttributeMaxDynamicSharedMemorySize, 73728);

    prep_kernel<<<(PREP_TOT + 255) / 256, 256>>>(conv_w, Wih_f, Wih_b, Whh_f, Whh_b, emb);
    gemm_mma<1><<<dim3(PCOLS / 128, MPAD1 / 128), 256>>>(
        VOCABN, KPAD1, PCOLS, pAeH, pAeL, pB1H, pB1L, pPh);
    conv_kernel<<<MPAD2, 128>>>(title, body, ctx, doc, conv_b);
    gemm_mma<0><<<dim3(1024 / 128, MPAD2 / 128), 256>>>(
        NFEAT, KPAD2, 1024, pFtH, pFtL, pWcH, pWcL, pPre);
    lstm_kernel<<<dim3((NSEQ + 3) / 4, 2), 128>>>(cand, bih_f, bhh_f, bih_b, bhh_b);
    att_kernel<<<dim3(MMEN, 2), 256, 72576>>>(wc, bc, wq, bq, wcq, bcq, wz, bz);
    final_kernel<<<MMEN, 256>>>(cand, w_p1, b_p1, w_p2, b_p2, out);
}

// round 8
// speedup vs baseline: 2.4334x; 1.3786x over previous
#include <cuda_runtime.h>
#include <cuda_bf16.h>
#include <cuda_fp16.h>
#include <math.h>

#define NENT   2048
#define MMEN   64
#define KC     32
#define VOCABN 5053
#define EMBD   300
#define CCSN   512
#define PCOLS  2560
#define HHN    128
#define NSEQ   193
#define NFEAT  4161
#define MPAD1  5120
#define KPAD1  320
#define MPAD2  4224
#define KPAD2  512

__device__ __align__(16) __half d_Ph[VOCABN * PCOLS];
__device__ __align__(16) float d_Pre[NFEAT * 1024];
__device__ __align__(16) float d_Hout[NSEQ * KC * 256];
__device__ __align__(16) float d_Pp[2 * MMEN * KC];
__device__ __align__(16) __half d_Wth[2 * 65536];         // fp16 transposed Whh, smem-layout
__device__ __align__(16) __half d_Ae16[MPAD1 * KPAD1];
__device__ __align__(16) __half d_B116[PCOLS * KPAD1];
__device__ __align__(16) __nv_bfloat16 d_FtH[MPAD2 * KPAD2];
__device__ __align__(16) __nv_bfloat16 d_FtL[MPAD2 * KPAD2];
__device__ __align__(16) __nv_bfloat16 d_WcH[1024 * KPAD2];
__device__ __align__(16) __nv_bfloat16 d_WcL[1024 * KPAD2];

typedef unsigned long long u64t;

__device__ __forceinline__ float sigf(float x) { return 1.f / (1.f + expf(-x)); }

__device__ __forceinline__ unsigned smem_u32(const void* p) {
    unsigned r;
    asm("{ .reg .u64 t; cvta.to.shared.u64 t, %1; cvt.u32.u64 %0, t; }" : "=r"(r) : "l"(p));
    return r;
}

static __device__ __forceinline__ void split_bf16(float v, __nv_bfloat16& h, __nv_bfloat16& l) {
    h = __float2bfloat16(v);
    l = __float2bfloat16(v - __bfloat162float(h));
}

__device__ __forceinline__ void ldmx4(unsigned* a, unsigned addr) {
    asm volatile("ldmatrix.sync.aligned.m8n8.x4.shared.b16 {%0,%1,%2,%3}, [%4];"
        : "=r"(a[0]), "=r"(a[1]), "=r"(a[2]), "=r"(a[3]) : "r"(addr));
}
__device__ __forceinline__ void ldmx2(unsigned* b, unsigned addr) {
    asm volatile("ldmatrix.sync.aligned.m8n8.x2.shared.b16 {%0,%1}, [%2];"
        : "=r"(b[0]), "=r"(b[1]) : "r"(addr));
}
__device__ __forceinline__ void mma_bf(float* c, const unsigned* a, const unsigned* b) {
    asm volatile("mma.sync.aligned.m16n8k16.row.col.f32.bf16.bf16.f32 "
        "{%0,%1,%2,%3}, {%4,%5,%6,%7}, {%8,%9}, {%0,%1,%2,%3};"
        : "+f"(c[0]), "+f"(c[1]), "+f"(c[2]), "+f"(c[3])
        : "r"(a[0]), "r"(a[1]), "r"(a[2]), "r"(a[3]), "r"(b[0]), "r"(b[1]));
}
__device__ __forceinline__ void mma_fp(float* c, const unsigned* a, const unsigned* b) {
    asm volatile("mma.sync.aligned.m16n8k16.row.col.f32.f16.f16.f32 "
        "{%0,%1,%2,%3}, {%4,%5,%6,%7}, {%8,%9}, {%0,%1,%2,%3};"
        : "+f"(c[0]), "+f"(c[1]), "+f"(c[2]), "+f"(c[3])
        : "r"(a[0]), "r"(a[1]), "r"(a[2]), "r"(a[3]), "r"(b[0]), "r"(b[1]));
}

__global__ void prep_kernel(const float* __restrict__ conv_w,
                            const float* __restrict__ Wih_f,
                            const float* __restrict__ Wih_b,
                            const float* __restrict__ Whh_f,
                            const float* __restrict__ Whh_b,
                            const float* __restrict__ emb) {
    int i = blockIdx.x * blockDim.x + threadIdx.x;
    const int T1 = PCOLS * KPAD1;
    const int T2 = 1024 * KPAD2;
    const int T3 = MPAD1 * KPAD1;
    const int T4 = 2 * 65536;
    if (i < T1) {
        int j = i / KPAD1, e = i - j * KPAD1;
        int w = j >> 9, c = j & 511;
        float v = (e < EMBD) ? conv_w[c * (EMBD * 5) + e * 5 + w] : 0.f;
        d_B116[i] = __float2half_rn(v);
        return;
    }
    int i2 = i - T1;
    if (i2 < T2) {
        int n = i2 >> 9, k = i2 & 511;
        int dir = n >> 9, col = n & 511;
        float v = (dir ? Wih_b : Wih_f)[col * CCSN + k];
        split_bf16(v, d_WcH[i2], d_WcL[i2]);
        return;
    }
    int i3 = i2 - T2;
    if (i3 < T3) {
        int r = i3 / KPAD1, k = i3 - r * KPAD1;
        float v = (r < VOCABN && k < EMBD) ? emb[r * EMBD + k] : 0.f;
        d_Ae16[i3] = __float2half_rn(v);
        return;
    }
    int i4 = i3 - T3;
    if (i4 < T4) {
        int dir = i4 >> 16;
        int r = i4 & 65535;
        int hb = r >> 12, rem = r & 4095;
        int gcol = rem >> 3, j = rem & 7;
        const float* W = dir ? Whh_b : Whh_f;
        d_Wth[i4] = __float2half_rn(W[gcol * HHN + hb * 8 + j]);
    }
}

#define SROW 40
// fp16 single-term: C_half[M,ldc] = A @ B^T
__global__ void __launch_bounds__(256) gemm_mma_h(
    int M, int Kpad, int ldc,
    const __half* __restrict__ A, const __half* __restrict__ B,
    __half* __restrict__ C)
{
    __shared__ __align__(16) __half sA[128 * SROW];
    __shared__ __align__(16) __half sB[128 * SROW];
    int tid = threadIdx.x, wid = tid >> 5, lane = tid & 31;
    int gm0 = blockIdx.y * 128, gn0 = blockIdx.x * 128;
    int wm0 = (wid & 1) * 64, wn0 = (wid >> 1) * 32;
    unsigned bA = smem_u32(sA), bB = smem_u32(sB);

    float acc[4][4][4];
    #pragma unroll
    for (int mi = 0; mi < 4; mi++)
        #pragma unroll
        for (int ni = 0; ni < 4; ni++)
            #pragma unroll
            for (int x = 0; x < 4; x++) acc[mi][ni][x] = 0.f;

    int lr = tid >> 2, lq = tid & 3;
    int arow = lane & 15;
    int acol = (lane >> 4) * 8;
    int brow = lane & 7;
    int bcol = lane & 8;

    int nchunks = Kpad >> 5;
    for (int kc = 0; kc < nchunks; kc++) {
        int kbase = kc << 5;
        {
            size_t ga0 = (size_t)(gm0 + lr) * Kpad + kbase + lq * 8;
            size_t ga1 = (size_t)(gm0 + lr + 64) * Kpad + kbase + lq * 8;
            size_t gb0 = (size_t)(gn0 + lr) * Kpad + kbase + lq * 8;
            size_t gb1 = (size_t)(gn0 + lr + 64) * Kpad + kbase + lq * 8;
            int so0 = lr * SROW + lq * 8, so1 = (lr + 64) * SROW + lq * 8;
            *(uint4*)&sA[so0] = *(const uint4*)(A + ga0);
            *(uint4*)&sA[so1] = *(const uint4*)(A + ga1);
            *(uint4*)&sB[so0] = *(const uint4*)(B + gb0);
            *(uint4*)&sB[so1] = *(const uint4*)(B + gb1);
        }
        __syncthreads();
        #pragma unroll
        for (int ko = 0; ko < 32; ko += 16) {
            unsigned fA[4][4], fB[4][2];
            #pragma unroll
            for (int ni = 0; ni < 4; ni++) {
                unsigned off = ((unsigned)((wn0 + ni * 8 + brow) * SROW + ko + bcol)) * 2u;
                ldmx2(fB[ni], bB + off);
            }
            #pragma unroll
            for (int mi = 0; mi < 4; mi++) {
                unsigned off = ((unsigned)((wm0 + mi * 16 + arow) * SROW + ko + acol)) * 2u;
                ldmx4(fA[mi], bA + off);
            }
            #pragma unroll
            for (int mi = 0; mi < 4; mi++)
                #pragma unroll
                for (int ni = 0; ni < 4; ni++)
                    mma_fp(acc[mi][ni], fA[mi], fB[ni]);
        }
        __syncthreads();
    }
    int gid = lane >> 2, tc = (lane & 3) * 2;
    #pragma unroll
    for (int mi = 0; mi < 4; mi++) {
        #pragma unroll
        for (int ni = 0; ni < 4; ni++) {
            int m0 = gm0 + wm0 + mi * 16 + gid;
            int n = gn0 + wn0 + ni * 8 + tc;
            if (m0 < M)
                *(__half2*)&C[(size_t)m0 * ldc + n] =
                    __floats2half2_rn(acc[mi][ni][0], acc[mi][ni][1]);
            if (m0 + 8 < M)
                *(__half2*)&C[(size_t)(m0 + 8) * ldc + n] =
                    __floats2half2_rn(acc[mi][ni][2], acc[mi][ni][3]);
        }
    }
}

// 3-term bf16 hi/lo: C_float[M,ldc] = (AH+AL) @ (BH+BL)^T
__global__ void __launch_bounds__(256) gemm_mma(
    int M, int Kpad, int ldc,
    const __nv_bfloat16* __restrict__ AH, const __nv_bfloat16* __restrict__ AL,
    const __nv_bfloat16* __restrict__ BH, const __nv_bfloat16* __restrict__ BL,
    float* __restrict__ C)
{
    __shared__ __align__(16) __nv_bfloat16 sAH[128 * SROW];
    __shared__ __align__(16) __nv_bfloat16 sAL[128 * SROW];
    __shared__ __align__(16) __nv_bfloat16 sBH[128 * SROW];
    __shared__ __align__(16) __nv_bfloat16 sBL[128 * SROW];
    int tid = threadIdx.x, wid = tid >> 5, lane = tid & 31;
    int gm0 = blockIdx.y * 128, gn0 = blockIdx.x * 128;
    int wm0 = (wid & 1) * 64, wn0 = (wid >> 1) * 32;
    unsigned bAH = smem_u32(sAH), bAL = smem_u32(sAL);
    unsigned bBH = smem_u32(sBH), bBL = smem_u32(sBL);

    float acc[4][4][4];
    #pragma unroll
    for (int mi = 0; mi < 4; mi++)
        #pragma unroll
        for (int ni = 0; ni < 4; ni++)
            #pragma unroll
            for (int x = 0; x < 4; x++) acc[mi][ni][x] = 0.f;

    int lr = tid >> 2, lq = tid & 3;
    int arow = lane & 15;
    int acol = (lane >> 4) * 8;
    int brow = lane & 7;
    int bcol = lane & 8;

    int nchunks = Kpad >> 5;
    for (int kc = 0; kc < nchunks; kc++) {
        int kbase = kc << 5;
        {
            size_t ga0 = (size_t)(gm0 + lr) * Kpad + kbase + lq * 8;
            size_t ga1 = (size_t)(gm0 + lr + 64) * Kpad + kbase + lq * 8;
            size_t gb0 = (size_t)(gn0 + lr) * Kpad + kbase + lq * 8;
            size_t gb1 = (size_t)(gn0 + lr + 64) * Kpad + kbase + lq * 8;
            int so0 = lr * SROW + lq * 8, so1 = (lr + 64) * SROW + lq * 8;
            *(uint4*)&sAH[so0] = *(const uint4*)(AH + ga0);
            *(uint4*)&sAH[so1] = *(const uint4*)(AH + ga1);
            *(uint4*)&sAL[so0] = *(const uint4*)(AL + ga0);
            *(uint4*)&sAL[so1] = *(const uint4*)(AL + ga1);
            *(uint4*)&sBH[so0] = *(const uint4*)(BH + gb0);
            *(uint4*)&sBH[so1] = *(const uint4*)(BH + gb1);
            *(uint4*)&sBL[so0] = *(const uint4*)(BL + gb0);
            *(uint4*)&sBL[so1] = *(const uint4*)(BL + gb1);
        }
        __syncthreads();
        #pragma unroll
        for (int ko = 0; ko < 32; ko += 16) {
            unsigned fAH[4][4], fAL[4][4], fBH[4][2], fBL[4][2];
            #pragma unroll
            for (int ni = 0; ni < 4; ni++) {
                unsigned off = ((unsigned)((wn0 + ni * 8 + brow) * SROW + ko + bcol)) * 2u;
                ldmx2(fBH[ni], bBH + off);
                ldmx2(fBL[ni], bBL + off);
            }
            #pragma unroll
            for (int mi = 0; mi < 4; mi++) {
                unsigned off = ((unsigned)((wm0 + mi * 16 + arow) * SROW + ko + acol)) * 2u;
                ldmx4(fAH[mi], bAH + off);
                ldmx4(fAL[mi], bAL + off);
            }
            #pragma unroll
            for (int mi = 0; mi < 4; mi++)
                #pragma unroll
                for (int ni = 0; ni < 4; ni++) {
                    mma_bf(acc[mi][ni], fAH[mi], fBH[ni]);
                    mma_bf(acc[mi][ni], fAH[mi], fBL[ni]);
                    mma_bf(acc[mi][ni], fAL[mi], fBH[ni]);
                }
        }
        __syncthreads();
    }
    int gid = lane >> 2, tc = (lane & 3) * 2;
    #pragma unroll
    for (int mi = 0; mi < 4; mi++) {
        #pragma unroll
        for (int ni = 0; ni < 4; ni++) {
            int m0 = gm0 + wm0 + mi * 16 + gid;
            int n = gn0 + wn0 + ni * 8 + tc;
            if (m0 < M) {
                float2 v; v.x = acc[mi][ni][0]; v.y = acc[mi][ni][1];
                *(float2*)&C[(size_t)m0 * ldc + n] = v;
            }
            if (m0 + 8 < M) {
                float2 v; v.x = acc[mi][ni][2]; v.y = acc[mi][ni][3];
                *(float2*)&C[(size_t)(m0 + 8) * ldc + n] = v;
            }
        }
    }
}

__global__ void __launch_bounds__(128) conv_kernel(
    const int* __restrict__ title, const int* __restrict__ body,
    const int* __restrict__ ctx, const int* __restrict__ doc,
    const float* __restrict__ conv_b)
{
    __shared__ int chars[512];
    int b = blockIdx.x, tid = threadIdx.x;
    int c4 = tid * 4;
    if (b >= NFEAT) {
        #pragma unroll
        for (int i = 0; i < 4; i++) {
            d_FtH[(size_t)b * CCSN + c4 + i] = __float2bfloat16(0.f);
            d_FtL[(size_t)b * CCSN + c4 + i] = __float2bfloat16(0.f);
        }
        return;
    }
    const int* src; int L;
    if (b < NENT)                 { src = title + b * 32;             L = 32;  }
    else if (b < 2 * NENT)        { src = body + (b - NENT) * 128;    L = 128; }
    else if (b < 2 * NENT + MMEN) { src = ctx + (b - 2 * NENT) * 128; L = 128; }
    else                          { src = doc;                        L = 512; }
    for (int i = tid; i < L; i += 128) chars[i] = src[i];
    __syncthreads();
    float mx0 = -1e30f, mx1 = -1e30f, mx2 = -1e30f, mx3 = -1e30f;
    int Lout = L - 4;
    #pragma unroll 2
    for (int t = 0; t < Lout; t++) {
        float s0 = 0.f, s1 = 0.f, s2 = 0.f, s3 = 0.f;
        #pragma unroll
        for (int w = 0; w < 5; w++) {
            const __half* prow = d_Ph + (size_t)chars[t + w] * PCOLS + (w << 9) + c4;
            uint2 u = *(const uint2*)prow;
            float2 f0 = __half22float2(*(const __half2*)&u.x);
            float2 f1 = __half22float2(*(const __half2*)&u.y);
            s0 += f0.x; s1 += f0.y; s2 += f1.x; s3 += f1.y;
        }
        mx0 = fmaxf(mx0, s0); mx1 = fmaxf(mx1, s1);
        mx2 = fmaxf(mx2, s2); mx3 = fmaxf(mx3, s3);
    }
    const float4 bb = *(const float4*)&conv_b[c4];
    float o[4];
    o[0] = fmaxf(0.f, mx0 + bb.x); o[1] = fmaxf(0.f, mx1 + bb.y);
    o[2] = fmaxf(0.f, mx2 + bb.z); o[3] = fmaxf(0.f, mx3 + bb.w);
    #pragma unroll
    for (int i = 0; i < 4; i++) {
        __nv_bfloat16 h, l;
        split_bf16(o[i], h, l);
        d_FtH[(size_t)b * CCSN + c4 + i] = h;
        d_FtL[(size_t)b * CCSN + c4 + i] = l;
    }
}

__device__ __forceinline__ u64t pack2(float x, float y) {
    u64t r;
    asm("mov.b64 %0, {%1, %2};" : "=l"(r) : "f"(x), "f"(y));
    return r;
}
__device__ __forceinline__ void unpack2(u64t v, float& x, float& y) {
    asm("mov.b64 {%0, %1}, %2;" : "=f"(x), "=f"(y) : "l"(v));
}
__device__ __forceinline__ void fma2(u64t& d, u64t a, u64t b) {
    asm("fma.rn.f32x2 %0, %1, %2, %0;" : "+l"(d) : "l"(a), "l"(b));
}

__global__ void __launch_bounds__(128) lstm_kernel(
    const int* __restrict__ cand_idx,
    const float* __restrict__ bih_f, const float* __restrict__ bhh_f,
    const float* __restrict__ bih_b, const float* __restrict__ bhh_b)
{
    extern __shared__ __align__(16) char lsm[];
    __half* sW   = (__half*)lsm;                     // 65536 halves = 131072 B
    float* presm = (float*)(lsm + 131072);           // 4*512 floats
    float* hsm   = presm + 4 * 512;                  // 128*4 floats
    int*  rowIdx = (int*)(hsm + 512);                // 4*32 ints
    int tid = threadIdx.x;
    int dir = blockIdx.y;
    int s0 = blockIdx.x * 4;
    const float* bih = dir ? bih_b : bih_f;
    const float* bhh = dir ? bhh_b : bhh_f;
    float bias[4];
    #pragma unroll
    for (int g = 0; g < 4; g++) { int col = (g << 7) + tid; bias[g] = bih[col] + bhh[col]; }
    {   // load Whh (fp16, prearranged layout) once into smem
        const uint4* src = (const uint4*)(d_Wth + dir * 65536);
        uint4* dst = (uint4*)sW;
        #pragma unroll
        for (int i = 0; i < 64; i++) dst[tid + i * 128] = src[tid + i * 128];
    }
    {
        int s = tid >> 5, t = tid & 31;
        int seq = s0 + s;
        int row;
        if (seq < 64)       row = cand_idx[seq * 32 + t];
        else if (seq < 128) row = NENT + cand_idx[(seq - 64) * 32 + t];
        else if (seq < 192) row = 2 * NENT + (seq - 128);
        else                row = NFEAT - 1;
        rowIdx[s * KC + t] = row;
    }
    *(float4*)&hsm[tid * 4] = make_float4(0.f, 0.f, 0.f, 0.f);
    float cst[4] = {0.f, 0.f, 0.f, 0.f};
    int nS = NSEQ - s0; if (nS > 4) nS = 4;
    int preOff = dir * 512;
    __syncthreads();
    for (int st = 0; st < KC; st++) {
        int t = dir ? (KC - 1 - st) : st;
        #pragma unroll
        for (int s = 0; s < 4; s++) {
            const float* prow = d_Pre + (size_t)rowIdx[s * KC + t] * 1024 + preOff;
            *(float4*)&presm[s * 512 + tid * 4] = *(const float4*)&prow[tid * 4];
        }
        __syncthreads();
        u64t acc2[4][2];
        #pragma unroll
        for (int g = 0; g < 4; g++) {
            int col = (g << 7) + tid;
            acc2[g][0] = pack2(presm[0 * 512 + col] + bias[g], presm[1 * 512 + col] + bias[g]);
            acc2[g][1] = pack2(presm[2 * 512 + col] + bias[g], presm[3 * 512 + col] + bias[g]);
        }
        #pragma unroll 2
        for (int hb = 0; hb < 16; hb++) {
            ulonglong2 hv[8];
            #pragma unroll
            for (int j = 0; j < 8; j++)
                hv[j] = *(const ulonglong2*)&hsm[(hb * 8 + j) * 4];
            #pragma unroll
            for (int g = 0; g < 4; g++) {
                uint4 wq = *(const uint4*)&sW[(hb * 512 + (g << 7) + tid) * 8];
                float2 w01 = __half22float2(*(const __half2*)&wq.x);
                float2 w23 = __half22float2(*(((const __half2*)&wq.x) + 1));
                float2 w45 = __half22float2(*(const __half2*)&wq.z);
                float2 w67 = __half22float2(*(((const __half2*)&wq.z) + 1));
                float wf[8] = {w01.x, w01.y, w23.x, w23.y, w45.x, w45.y, w67.x, w67.y};
                #pragma unroll
                for (int j = 0; j < 8; j++) {
                    u64t wp = pack2(wf[j], wf[j]);
                    fma2(acc2[g][0], wp, hv[j].x);
                    fma2(acc2[g][1], wp, hv[j].y);
                }
            }
        }
        float accs[4][4];
        #pragma unroll
        for (int g = 0; g < 4; g++) {
            unpack2(acc2[g][0], accs[g][0], accs[g][1]);
            unpack2(acc2[g][1], accs[g][2], accs[g][3]);
        }
        float hnew[4];
        #pragma unroll
        for (int s = 0; s < 4; s++) {
            float ig = sigf(accs[0][s]);
            float fg = sigf(accs[1][s]);
            float gg = tanhf(accs[2][s]);
            float og = sigf(accs[3][s]);
            cst[s] = fg * cst[s] + ig * gg;
            hnew[s] = og * tanhf(cst[s]);
        }
        __syncthreads();
        *(float4*)&hsm[tid * 4] = *(const float4*)&hnew[0];
        #pragma unroll
        for (int s = 0; s < 4; s++) {
            if (s < nS)
                d_Hout[((size_t)(s0 + s) * KC + t) * 256 + dir * HHN + tid] = hnew[s];
        }
    }
}

__global__ void __launch_bounds__(256) att_kernel(
    const float* __restrict__ wc, const float* __restrict__ bcp,
    const float* __restrict__ wq, const float* __restrict__ bqp,
    const float* __restrict__ wcq, const float* __restrict__ bcqp,
    const float* __restrict__ wz, const float* __restrict__ bzp)
{
    extern __shared__ float sbuf[];
    float* csm = sbuf;
    float* qsm = csm + 8224;
    float* sA  = qsm + 8224;
    float* cwcA = sA + 1056;
    float* qwqA = cwcA + 32;
    float* rowmaxA = qwqA + 32;
    float* betaA = rowmaxA + 32;
    float* q2cA = betaA + 32;
    float* wcqs = q2cA + 256;
    int m = blockIdx.x, fl = blockIdx.y, tid = threadIdx.x;
    int seqC = fl ? 192 : (128 + m);
    int seqQ = fl ? (64 + m) : m;
    const float* Crow = d_Hout + (size_t)seqC * KC * 256;
    const float* Qrow = d_Hout + (size_t)seqQ * KC * 256;
    for (int idx = tid; idx < 32 * 256; idx += 256) {
        int i = idx >> 8, d = idx & 255;
        csm[i * 257 + d] = Crow[i * 256 + d];
        qsm[i * 257 + d] = Qrow[i * 256 + d];
    }
    wcqs[tid] = wcq[tid];
    __syncthreads();
    if (tid < 32) {
        float a = 0.f;
        for (int d = 0; d < 256; d++) a += csm[tid * 257 + d] * wc[d];
        cwcA[tid] = a;
    } else if (tid < 64) {
        int j = tid - 32;
        float a = 0.f;
        for (int d = 0; d < 256; d++) a += qsm[j * 257 + d] * wq[d];
        qwqA[j] = a;
    }
    __syncthreads();
    float K0 = bcp[0] + bqp[0] + bcqp[0];
    for (int e = tid; e < 1024; e += 256) {
        int i = e >> 5, j = e & 31;
        float acc = 0.f;
        for (int d = 0; d < 256; d++)
            acc += csm[i * 257 + d] * wcqs[d] * qsm[j * 257 + d];
        sA[i * 33 + j] = acc + cwcA[i] + qwqA[j] + K0;
    }
    __syncthreads();
    if (tid < 32) {
        int i = tid;
        float mx = -1e30f;
        for (int j = 0; j < 32; j++) mx = fmaxf(mx, sA[i * 33 + j]);
        rowmaxA[i] = mx;
        float s = 0.f;
        for (int j = 0; j < 32; j++) { float e2 = expf(sA[i * 33 + j] - mx); sA[i * 33 + j] = e2; s += e2; }
        float inv = 1.f / s;
        for (int j = 0; j < 32; j++) sA[i * 33 + j] *= inv;
    }
    __syncthreads();
    if (tid == 0) {
        float mx = -1e30f;
        for (int i = 0; i < 32; i++) mx = fmaxf(mx, rowmaxA[i]);
        float s = 0.f;
        for (int i = 0; i < 32; i++) { float e2 = expf(rowmaxA[i] - mx); betaA[i] = e2; s += e2; }
        float inv = 1.f / s;
        for (int i = 0; i < 32; i++) betaA[i] *= inv;
    }
    __syncthreads();
    {
        float a = 0.f;
        for (int i = 0; i < 32; i++) a += betaA[i] * csm[i * 257 + tid];
        q2cA[tid] = a;
    }
    __syncthreads();
    {
        int i = tid >> 3, sub = tid & 7, d0 = sub * 32;
        float pp = 0.f;
        for (int dd = 0; dd < 32; dd++) {
            int d = d0 + dd;
            float c2 = 0.f;
            for (int j = 0; j < 32; j++) c2 += sA[i * 33 + j] * qsm[j * 257 + d];
            float cd = csm[i * 257 + d];
            pp += cd * wz[d] + c2 * wz[256 + d] + cd * c2 * wz[512 + d] + cd * q2cA[d] * wz[768 + d];
        }
        pp += __shfl_xor_sync(0xffffffffu, pp, 1);
        pp += __shfl_xor_sync(0xffffffffu, pp, 2);
        pp += __shfl_xor_sync(0xffffffffu, pp, 4);
        if (sub == 0) d_Pp[fl * 2048 + m * 32 + i] = pp + bzp[0];
    }
}

__global__ void __launch_bounds__(256) final_kernel(
    const int* __restrict__ cand,
    const float* __restrict__ wp1, const float* __restrict__ bp1,
    const float* __restrict__ wp2, const float* __restrict__ bp2,
    float* __restrict__ out)
{
    int m = blockIdx.x, tid = threadIdx.x;
    const int R = MMEN * NENT;
    for (int j = tid; j < NENT; j += 256) {
        out[m * NENT + j] = 0.f;
        out[R + m * NENT + j] = 0.f;
        out[2 * R + m * NENT + j] = 0.f;
    }
    __syncthreads();
    if (tid < 32) {
        float s = wp1[0] * d_Pp[m * 32 + tid] + bp1[0] + wp2[0] * d_Pp[2048 + m * 32 + tid] + bp2[0];
        float mx = s;
        #pragma unroll
        for (int o = 16; o; o >>= 1) mx = fmaxf(mx, __shfl_xor_sync(0xffffffffu, mx, o));
        float e = expf(s - mx);
        float se = e, ss = s;
        #pragma unroll
        for (int o = 16; o; o >>= 1) {
            se += __shfl_xor_sync(0xffffffffu, se, o);
            ss += __shfl_xor_sync(0xffffffffu, ss, o);
        }
        int col = cand[m * 32 + tid];
        out[m * NENT + col] = s;
        out[R + m * NENT + col] = e / se;
        out[2 * R + m * NENT + col] = s / ss;
    }
}

extern "C" void kernel_launch(void* const* d_in, const int* in_sizes, int n_in,
                              void* d_out, int out_size) {
    const int* title = (const int*)d_in[0];
    const int* body  = (const int*)d_in[1];
    const int* ctx   = (const int*)d_in[3];
    const int* doc   = (const int*)d_in[4];
    const int* cand  = (const int*)d_in[5];
    const float* emb    = (const float*)d_in[6];
    const float* conv_w = (const float*)d_in[7];
    const float* conv_b = (const float*)d_in[8];
    const float* Wih_f = (const float*)d_in[9];
    const float* Whh_f = (const float*)d_in[10];
    const float* bih_f = (const float*)d_in[11];
    const float* bhh_f = (const float*)d_in[12];
    const float* Wih_b = (const float*)d_in[13];
    const float* Whh_b = (const float*)d_in[14];
    const float* bih_b = (const float*)d_in[15];
    const float* bhh_b = (const float*)d_in[16];
    const float* wc  = (const float*)d_in[17];
    const float* bc  = (const float*)d_in[18];
    const float* wq  = (const float*)d_in[19];
    const float* bq  = (const float*)d_in[20];
    const float* wcq = (const float*)d_in[21];
    const float* bcq = (const float*)d_in[22];
    const float* wz  = (const float*)d_in[23];
    const float* bz  = (const float*)d_in[24];
    const float* w_p1 = (const float*)d_in[25];
    const float* b_p1 = (const float*)d_in[26];
    const float* w_p2 = (const float*)d_in[27];
    const float* b_p2 = (const float*)d_in[28];
    float* out = (float*)d_out;

    float *pPre;
    __half *pPh, *pAe16, *pB116;
    __nv_bfloat16 *pFtH, *pFtL, *pWcH, *pWcL;
    cudaGetSymbolAddress((void**)&pPh, d_Ph);
    cudaGetSymbolAddress((void**)&pPre, d_Pre);
    cudaGetSymbolAddress((void**)&pAe16, d_Ae16);
    cudaGetSymbolAddress((void**)&pB116, d_B116);
    cudaGetSymbolAddress((void**)&pFtH, d_FtH);
    cudaGetSymbolAddress((void**)&pFtL, d_FtL);
    cudaGetSymbolAddress((void**)&pWcH, d_WcH);
    cudaGetSymbolAddress((void**)&pWcL, d_WcL);

    const int PREP_TOT = PCOLS * KPAD1 + 1024 * KPAD2 + MPAD1 * KPAD1 + 2 * 65536;
    const int LSTM_SMEM = 131072 + 8192 + 2048 + 512;
    cudaFuncSetAttribute(att_kernel, cudaFuncAttributeMaxDynamicSharedMemorySize, 73728);
    cudaFuncSetAttribute(lstm_kernel, cudaFuncAttributeMaxDynamicSharedMemorySize, LSTM_SMEM);

    prep_kernel<<<(PREP_TOT + 255) / 256, 256>>>(conv_w, Wih_f, Wih_b, Whh_f, Whh_b, emb);
    gemm_mma_h<<<dim3(PCOLS / 128, MPAD1 / 128), 256>>>(
        VOCABN, KPAD1, PCOLS, pAe16, pB116, pPh);
    conv_kernel<<<MPAD2, 128>>>(title, body, ctx, doc, conv_b);
    gemm_mma<<<dim3(1024 / 128, MPAD2 / 128), 256>>>(
        NFEAT, KPAD2, 1024, pFtH, pFtL, pWcH, pWcL, pPre);
    lstm_kernel<<<dim3((NSEQ + 3) / 4, 2), 128, LSTM_SMEM>>>(cand, bih_f, bhh_f, bih_b, bhh_b);
    att_kernel<<<dim3(MMEN, 2), 256, 72576>>>(wc, bc, wq, bq, wcq, bcq, wz, bz);
    final_kernel<<<MMEN, 256>>>(cand, w_p1, b_p1, w_p2, b_p2, out);
}

// round 9
// speedup vs baseline: 2.5805x; 1.0604x over previous
#include <cuda_runtime.h>
#include <cuda_fp16.h>
#include <math.h>

#define NENT   2048
#define MMEN   64
#define KC     32
#define VOCABN 5053
#define EMBD   300
#define CCSN   512
#define PCOLS  2560
#define HHN    128
#define NSEQ   193
#define NFEAT  4161
#define MPAD1  5120
#define KPAD1  320
#define MPAD2  4224
#define KPAD2  512

__device__ __align__(16) __half d_Ph[VOCABN * PCOLS];
__device__ __align__(16) float d_Pre[NFEAT * 1024];
__device__ __align__(16) float d_Hout[NSEQ * KC * 256];
__device__ __align__(16) float d_Pp[2 * MMEN * KC];
__device__ __align__(16) __half d_Wth[2 * 65536];
__device__ __align__(16) __half d_Ae16[MPAD1 * KPAD1];
__device__ __align__(16) __half d_B116[PCOLS * KPAD1];
__device__ __align__(16) __half d_Ft16[MPAD2 * KPAD2];
__device__ __align__(16) __half d_Wc16[1024 * KPAD2];

typedef unsigned long long u64t;

__device__ __forceinline__ float sigf(float x) { return 1.f / (1.f + expf(-x)); }

__device__ __forceinline__ unsigned smem_u32(const void* p) {
    unsigned r;
    asm("{ .reg .u64 t; cvta.to.shared.u64 t, %1; cvt.u32.u64 %0, t; }" : "=r"(r) : "l"(p));
    return r;
}

__device__ __forceinline__ void ldmx4(unsigned* a, unsigned addr) {
    asm volatile("ldmatrix.sync.aligned.m8n8.x4.shared.b16 {%0,%1,%2,%3}, [%4];"
        : "=r"(a[0]), "=r"(a[1]), "=r"(a[2]), "=r"(a[3]) : "r"(addr));
}
__device__ __forceinline__ void ldmx2(unsigned* b, unsigned addr) {
    asm volatile("ldmatrix.sync.aligned.m8n8.x2.shared.b16 {%0,%1}, [%2];"
        : "=r"(b[0]), "=r"(b[1]) : "r"(addr));
}
__device__ __forceinline__ void mma_fp(float* c, const unsigned* a, const unsigned* b) {
    asm volatile("mma.sync.aligned.m16n8k16.row.col.f32.f16.f16.f32 "
        "{%0,%1,%2,%3}, {%4,%5,%6,%7}, {%8,%9}, {%0,%1,%2,%3};"
        : "+f"(c[0]), "+f"(c[1]), "+f"(c[2]), "+f"(c[3])
        : "r"(a[0]), "r"(a[1]), "r"(a[2]), "r"(a[3]), "r"(b[0]), "r"(b[1]));
}

__global__ void prep_kernel(const float* __restrict__ conv_w,
                            const float* __restrict__ Wih_f,
                            const float* __restrict__ Wih_b,
                            const float* __restrict__ Whh_f,
                            const float* __restrict__ Whh_b,
                            const float* __restrict__ emb) {
    int i = blockIdx.x * blockDim.x + threadIdx.x;
    const int T1 = PCOLS * KPAD1;
    const int T2 = 1024 * KPAD2;
    const int T3 = MPAD1 * KPAD1;
    const int T4 = 2 * 65536;
    if (i < T1) {
        int j = i / KPAD1, e = i - j * KPAD1;
        int w = j >> 9, c = j & 511;
        float v = (e < EMBD) ? conv_w[c * (EMBD * 5) + e * 5 + w] : 0.f;
        d_B116[i] = __float2half_rn(v);
        return;
    }
    int i2 = i - T1;
    if (i2 < T2) {
        int n = i2 >> 9, k = i2 & 511;
        int dir = n >> 9, col = n & 511;
        float v = (dir ? Wih_b : Wih_f)[col * CCSN + k];
        d_Wc16[i2] = __float2half_rn(v);
        return;
    }
    int i3 = i2 - T2;
    if (i3 < T3) {
        int r = i3 / KPAD1, k = i3 - r * KPAD1;
        float v = (r < VOCABN && k < EMBD) ? emb[r * EMBD + k] : 0.f;
        d_Ae16[i3] = __float2half_rn(v);
        return;
    }
    int i4 = i3 - T3;
    if (i4 < T4) {
        int dir = i4 >> 16;
        int r = i4 & 65535;
        int hb = r >> 12, rem = r & 4095;
        int gcol = rem >> 3, j = rem & 7;
        const float* W = dir ? Whh_b : Whh_f;
        d_Wth[i4] = __float2half_rn(W[gcol * HHN + hb * 8 + j]);
    }
}

#define SROW 40
// fp16 single-term: C[M,ldc] = A @ B^T. FOUT=0: half out, 1: float out.
template <int FOUT>
__global__ void __launch_bounds__(256) gemm_mma_h(
    int M, int Kpad, int ldc,
    const __half* __restrict__ A, const __half* __restrict__ B,
    void* __restrict__ Cv)
{
    __shared__ __align__(16) __half sA[128 * SROW];
    __shared__ __align__(16) __half sB[128 * SROW];
    int tid = threadIdx.x, wid = tid >> 5, lane = tid & 31;
    int gm0 = blockIdx.y * 128, gn0 = blockIdx.x * 128;
    int wm0 = (wid & 1) * 64, wn0 = (wid >> 1) * 32;
    unsigned bA = smem_u32(sA), bB = smem_u32(sB);

    float acc[4][4][4];
    #pragma unroll
    for (int mi = 0; mi < 4; mi++)
        #pragma unroll
        for (int ni = 0; ni < 4; ni++)
            #pragma unroll
            for (int x = 0; x < 4; x++) acc[mi][ni][x] = 0.f;

    int lr = tid >> 2, lq = tid & 3;
    int arow = lane & 15;
    int acol = (lane >> 4) * 8;
    int brow = lane & 7;
    int bcol = lane & 8;

    int nchunks = Kpad >> 5;
    for (int kc = 0; kc < nchunks; kc++) {
        int kbase = kc << 5;
        {
            size_t ga0 = (size_t)(gm0 + lr) * Kpad + kbase + lq * 8;
            size_t ga1 = (size_t)(gm0 + lr + 64) * Kpad + kbase + lq * 8;
            size_t gb0 = (size_t)(gn0 + lr) * Kpad + kbase + lq * 8;
            size_t gb1 = (size_t)(gn0 + lr + 64) * Kpad + kbase + lq * 8;
            int so0 = lr * SROW + lq * 8, so1 = (lr + 64) * SROW + lq * 8;
            *(uint4*)&sA[so0] = *(const uint4*)(A + ga0);
            *(uint4*)&sA[so1] = *(const uint4*)(A + ga1);
            *(uint4*)&sB[so0] = *(const uint4*)(B + gb0);
            *(uint4*)&sB[so1] = *(const uint4*)(B + gb1);
        }
        __syncthreads();
        #pragma unroll
        for (int ko = 0; ko < 32; ko += 16) {
            unsigned fA[4][4], fB[4][2];
            #pragma unroll
            for (int ni = 0; ni < 4; ni++) {
                unsigned off = ((unsigned)((wn0 + ni * 8 + brow) * SROW + ko + bcol)) * 2u;
                ldmx2(fB[ni], bB + off);
            }
            #pragma unroll
            for (int mi = 0; mi < 4; mi++) {
                unsigned off = ((unsigned)((wm0 + mi * 16 + arow) * SROW + ko + acol)) * 2u;
                ldmx4(fA[mi], bA + off);
            }
            #pragma unroll
            for (int mi = 0; mi < 4; mi++)
                #pragma unroll
                for (int ni = 0; ni < 4; ni++)
                    mma_fp(acc[mi][ni], fA[mi], fB[ni]);
        }
        __syncthreads();
    }
    int gid = lane >> 2, tc = (lane & 3) * 2;
    #pragma unroll
    for (int mi = 0; mi < 4; mi++) {
        #pragma unroll
        for (int ni = 0; ni < 4; ni++) {
            int m0 = gm0 + wm0 + mi * 16 + gid;
            int n = gn0 + wn0 + ni * 8 + tc;
            if (FOUT) {
                float* C = (float*)Cv;
                if (m0 < M) {
                    float2 v; v.x = acc[mi][ni][0]; v.y = acc[mi][ni][1];
                    *(float2*)&C[(size_t)m0 * ldc + n] = v;
                }
                if (m0 + 8 < M) {
                    float2 v; v.x = acc[mi][ni][2]; v.y = acc[mi][ni][3];
                    *(float2*)&C[(size_t)(m0 + 8) * ldc + n] = v;
                }
            } else {
                __half* C = (__half*)Cv;
                if (m0 < M)
                    *(__half2*)&C[(size_t)m0 * ldc + n] =
                        __floats2half2_rn(acc[mi][ni][0], acc[mi][ni][1]);
                if (m0 + 8 < M)
                    *(__half2*)&C[(size_t)(m0 + 8) * ldc + n] =
                        __floats2half2_rn(acc[mi][ni][2], acc[mi][ni][3]);
            }
        }
    }
}

__global__ void __launch_bounds__(128) conv_kernel(
    const int* __restrict__ title, const int* __restrict__ body,
    const int* __restrict__ ctx, const int* __restrict__ doc,
    const float* __restrict__ conv_b)
{
    __shared__ int chars[512];
    int b = blockIdx.x, tid = threadIdx.x;
    int c4 = tid * 4;
    if (b >= NFEAT) {
        *(ushort4*)&d_Ft16[(size_t)b * CCSN + c4] = make_ushort4(0, 0, 0, 0);
        return;
    }
    const int* src; int L;
    if (b < NENT)                 { src = title + b * 32;             L = 32;  }
    else if (b < 2 * NENT)        { src = body + (b - NENT) * 128;    L = 128; }
    else if (b < 2 * NENT + MMEN) { src = ctx + (b - 2 * NENT) * 128; L = 128; }
    else                          { src = doc;                        L = 512; }
    for (int i = tid; i < L; i += 128) chars[i] = src[i];
    __syncthreads();
    float mx0 = -1e30f, mx1 = -1e30f, mx2 = -1e30f, mx3 = -1e30f;
    int Lout = L - 4;
    #pragma unroll 2
    for (int t = 0; t < Lout; t++) {
        float s0 = 0.f, s1 = 0.f, s2 = 0.f, s3 = 0.f;
        #pragma unroll
        for (int w = 0; w < 5; w++) {
            const __half* prow = d_Ph + (size_t)chars[t + w] * PCOLS + (w << 9) + c4;
            uint2 u = *(const uint2*)prow;
            float2 f0 = __half22float2(*(const __half2*)&u.x);
            float2 f1 = __half22float2(*(const __half2*)&u.y);
            s0 += f0.x; s1 += f0.y; s2 += f1.x; s3 += f1.y;
        }
        mx0 = fmaxf(mx0, s0); mx1 = fmaxf(mx1, s1);
        mx2 = fmaxf(mx2, s2); mx3 = fmaxf(mx3, s3);
    }
    const float4 bb = *(const float4*)&conv_b[c4];
    float o0 = fmaxf(0.f, mx0 + bb.x), o1 = fmaxf(0.f, mx1 + bb.y);
    float o2 = fmaxf(0.f, mx2 + bb.z), o3 = fmaxf(0.f, mx3 + bb.w);
    __half2 p0 = __floats2half2_rn(o0, o1);
    __half2 p1 = __floats2half2_rn(o2, o3);
    uint2 w2;
    w2.x = *(unsigned*)&p0;
    w2.y = *(unsigned*)&p1;
    *(uint2*)&d_Ft16[(size_t)b * CCSN + c4] = w2;
}

__device__ __forceinline__ u64t pack2(float x, float y) {
    u64t r;
    asm("mov.b64 %0, {%1, %2};" : "=l"(r) : "f"(x), "f"(y));
    return r;
}
__device__ __forceinline__ void unpack2(u64t v, float& x, float& y) {
    asm("mov.b64 {%0, %1}, %2;" : "=f"(x), "=f"(y) : "l"(v));
}
__device__ __forceinline__ void fma2(u64t& d, u64t a, u64t b) {
    asm("fma.rn.f32x2 %0, %1, %2, %0;" : "+l"(d) : "l"(a), "l"(b));
}

__global__ void __launch_bounds__(128) lstm_kernel(
    const int* __restrict__ cand_idx,
    const float* __restrict__ bih_f, const float* __restrict__ bhh_f,
    const float* __restrict__ bih_b, const float* __restrict__ bhh_b)
{
    extern __shared__ __align__(16) char lsm[];
    __half* sW   = (__half*)lsm;
    float* presm = (float*)(lsm + 131072);
    float* hsm   = presm + 4 * 512;
    int*  rowIdx = (int*)(hsm + 512);
    int tid = threadIdx.x;
    int dir = blockIdx.y;
    int s0 = blockIdx.x * 4;
    const float* bih = dir ? bih_b : bih_f;
    const float* bhh = dir ? bhh_b : bhh_f;
    float bias[4];
    #pragma unroll
    for (int g = 0; g < 4; g++) { int col = (g << 7) + tid; bias[g] = bih[col] + bhh[col]; }
    {
        const uint4* src = (const uint4*)(d_Wth + dir * 65536);
        uint4* dst = (uint4*)sW;
        #pragma unroll
        for (int i = 0; i < 64; i++) dst[tid + i * 128] = src[tid + i * 128];
    }
    {
        int s = tid >> 5, t = tid & 31;
        int seq = s0 + s;
        int row;
        if (seq < 64)       row = cand_idx[seq * 32 + t];
        else if (seq < 128) row = NENT + cand_idx[(seq - 64) * 32 + t];
        else if (seq < 192) row = 2 * NENT + (seq - 128);
        else                row = NFEAT - 1;
        rowIdx[s * KC + t] = row;
    }
    *(float4*)&hsm[tid * 4] = make_float4(0.f, 0.f, 0.f, 0.f);
    float cst[4] = {0.f, 0.f, 0.f, 0.f};
    int nS = NSEQ - s0; if (nS > 4) nS = 4;
    int preOff = dir * 512;
    __syncthreads();
    for (int st = 0; st < KC; st++) {
        int t = dir ? (KC - 1 - st) : st;
        #pragma unroll
        for (int s = 0; s < 4; s++) {
            const float* prow = d_Pre + (size_t)rowIdx[s * KC + t] * 1024 + preOff;
            *(float4*)&presm[s * 512 + tid * 4] = *(const float4*)&prow[tid * 4];
        }
        __syncthreads();
        u64t acc2[4][2];
        #pragma unroll
        for (int g = 0; g < 4; g++) {
            int col = (g << 7) + tid;
            acc2[g][0] = pack2(presm[0 * 512 + col] + bias[g], presm[1 * 512 + col] + bias[g]);
            acc2[g][1] = pack2(presm[2 * 512 + col] + bias[g], presm[3 * 512 + col] + bias[g]);
        }
        #pragma unroll 2
        for (int hb = 0; hb < 16; hb++) {
            ulonglong2 hv[8];
            #pragma unroll
            for (int j = 0; j < 8; j++)
                hv[j] = *(const ulonglong2*)&hsm[(hb * 8 + j) * 4];
            #pragma unroll
            for (int g = 0; g < 4; g++) {
                uint4 wq = *(const uint4*)&sW[(hb * 512 + (g << 7) + tid) * 8];
                float2 w01 = __half22float2(*(const __half2*)&wq.x);
                float2 w23 = __half22float2(*(((const __half2*)&wq.x) + 1));
                float2 w45 = __half22float2(*(const __half2*)&wq.z);
                float2 w67 = __half22float2(*(((const __half2*)&wq.z) + 1));
                float wf[8] = {w01.x, w01.y, w23.x, w23.y, w45.x, w45.y, w67.x, w67.y};
                #pragma unroll
                for (int j = 0; j < 8; j++) {
                    u64t wp = pack2(wf[j], wf[j]);
                    fma2(acc2[g][0], wp, hv[j].x);
                    fma2(acc2[g][1], wp, hv[j].y);
                }
            }
        }
        float accs[4][4];
        #pragma unroll
        for (int g = 0; g < 4; g++) {
            unpack2(acc2[g][0], accs[g][0], accs[g][1]);
            unpack2(acc2[g][1], accs[g][2], accs[g][3]);
        }
        float hnew[4];
        #pragma unroll
        for (int s = 0; s < 4; s++) {
            float ig = sigf(accs[0][s]);
            float fg = sigf(accs[1][s]);
            float gg = tanhf(accs[2][s]);
            float og = sigf(accs[3][s]);
            cst[s] = fg * cst[s] + ig * gg;
            hnew[s] = og * tanhf(cst[s]);
        }
        __syncthreads();
        *(float4*)&hsm[tid * 4] = *(const float4*)&hnew[0];
        #pragma unroll
        for (int s = 0; s < 4; s++) {
            if (s < nS)
                d_Hout[((size_t)(s0 + s) * KC + t) * 256 + dir * HHN + tid] = hnew[s];
        }
    }
}

__global__ void __launch_bounds__(256) att_kernel(
    const float* __restrict__ wc, const float* __restrict__ bcp,
    const float* __restrict__ wq, const float* __restrict__ bqp,
    const float* __restrict__ wcq, const float* __restrict__ bcqp,
    const float* __restrict__ wz, const float* __restrict__ bzp)
{
    extern __shared__ float sbuf[];
    float* csm = sbuf;
    float* qsm = csm + 8224;
    float* sA  = qsm + 8224;
    float* cwcA = sA + 1056;
    float* qwqA = cwcA + 32;
    float* rowmaxA = qwqA + 32;
    float* betaA = rowmaxA + 32;
    float* q2cA = betaA + 32;
    float* wcqs = q2cA + 256;
    int m = blockIdx.x, fl = blockIdx.y, tid = threadIdx.x;
    int seqC = fl ? 192 : (128 + m);
    int seqQ = fl ? (64 + m) : m;
    const float* Crow = d_Hout + (size_t)seqC * KC * 256;
    const float* Qrow = d_Hout + (size_t)seqQ * KC * 256;
    for (int idx = tid; idx < 32 * 256; idx += 256) {
        int i = idx >> 8, d = idx & 255;
        csm[i * 257 + d] = Crow[i * 256 + d];
        qsm[i * 257 + d] = Qrow[i * 256 + d];
    }
    wcqs[tid] = wcq[tid];
    __syncthreads();
    if (tid < 32) {
        float a = 0.f;
        for (int d = 0; d < 256; d++) a += csm[tid * 257 + d] * wc[d];
        cwcA[tid] = a;
    } else if (tid < 64) {
        int j = tid - 32;
        float a = 0.f;
        for (int d = 0; d < 256; d++) a += qsm[j * 257 + d] * wq[d];
        qwqA[j] = a;
    }
    __syncthreads();
    float K0 = bcp[0] + bqp[0] + bcqp[0];
    for (int e = tid; e < 1024; e += 256) {
        int i = e >> 5, j = e & 31;
        float acc = 0.f;
        for (int d = 0; d < 256; d++)
            acc += csm[i * 257 + d] * wcqs[d] * qsm[j * 257 + d];
        sA[i * 33 + j] = acc + cwcA[i] + qwqA[j] + K0;
    }
    __syncthreads();
    if (tid < 32) {
        int i = tid;
        float mx = -1e30f;
        for (int j = 0; j < 32; j++) mx = fmaxf(mx, sA[i * 33 + j]);
        rowmaxA[i] = mx;
        float s = 0.f;
        for (int j = 0; j < 32; j++) { float e2 = expf(sA[i * 33 + j] - mx); sA[i * 33 + j] = e2; s += e2; }
        float inv = 1.f / s;
        for (int j = 0; j < 32; j++) sA[i * 33 + j] *= inv;
    }
    __syncthreads();
    if (tid == 0) {
        float mx = -1e30f;
        for (int i = 0; i < 32; i++) mx = fmaxf(mx, rowmaxA[i]);
        float s = 0.f;
        for (int i = 0; i < 32; i++) { float e2 = expf(rowmaxA[i] - mx); betaA[i] = e2; s += e2; }
        float inv = 1.f / s;
        for (int i = 0; i < 32; i++) betaA[i] *= inv;
    }
    __syncthreads();
    {
        float a = 0.f;
        for (int i = 0; i < 32; i++) a += betaA[i] * csm[i * 257 + tid];
        q2cA[tid] = a;
    }
    __syncthreads();
    {
        int i = tid >> 3, sub = tid & 7, d0 = sub * 32;
        float pp = 0.f;
        for (int dd = 0; dd < 32; dd++) {
            int d = d0 + dd;
            float c2 = 0.f;
            for (int j = 0; j < 32; j++) c2 += sA[i * 33 + j] * qsm[j * 257 + d];
            float cd = csm[i * 257 + d];
            pp += cd * wz[d] + c2 * wz[256 + d] + cd * c2 * wz[512 + d] + cd * q2cA[d] * wz[768 + d];
        }
        pp += __shfl_xor_sync(0xffffffffu, pp, 1);
        pp += __shfl_xor_sync(0xffffffffu, pp, 2);
        pp += __shfl_xor_sync(0xffffffffu, pp, 4);
        if (sub == 0) d_Pp[fl * 2048 + m * 32 + i] = pp + bzp[0];
    }
}

__global__ void __launch_bounds__(256) final_kernel(
    const int* __restrict__ cand,
    const float* __restrict__ wp1, const float* __restrict__ bp1,
    const float* __restrict__ wp2, const float* __restrict__ bp2,
    float* __restrict__ out)
{
    int m = blockIdx.x, tid = threadIdx.x;
    const int R = MMEN * NENT;
    for (int j = tid; j < NENT; j += 256) {
        out[m * NENT + j] = 0.f;
        out[R + m * NENT + j] = 0.f;
        out[2 * R + m * NENT + j] = 0.f;
    }
    __syncthreads();
    if (tid < 32) {
        float s = wp1[0] * d_Pp[m * 32 + tid] + bp1[0] + wp2[0] * d_Pp[2048 + m * 32 + tid] + bp2[0];
        float mx = s;
        #pragma unroll
        for (int o = 16; o; o >>= 1) mx = fmaxf(mx, __shfl_xor_sync(0xffffffffu, mx, o));
        float e = expf(s - mx);
        float se = e, ss = s;
        #pragma unroll
        for (int o = 16; o; o >>= 1) {
            se += __shfl_xor_sync(0xffffffffu, se, o);
            ss += __shfl_xor_sync(0xffffffffu, ss, o);
        }
        int col = cand[m * 32 + tid];
        out[m * NENT + col] = s;
        out[R + m * NENT + col] = e / se;
        out[2 * R + m * NENT + col] = s / ss;
    }
}

extern "C" void kernel_launch(void* const* d_in, const int* in_sizes, int n_in,
                              void* d_out, int out_size) {
    const int* title = (const int*)d_in[0];
    const int* body  = (const int*)d_in[1];
    const int* ctx   = (const int*)d_in[3];
    const int* doc   = (const int*)d_in[4];
    const int* cand  = (const int*)d_in[5];
    const float* emb    = (const float*)d_in[6];
    const float* conv_w = (const float*)d_in[7];
    const float* conv_b = (const float*)d_in[8];
    const float* Wih_f = (const float*)d_in[9];
    const float* Whh_f = (const float*)d_in[10];
    const float* bih_f = (const float*)d_in[11];
    const float* bhh_f = (const float*)d_in[12];
    const float* Wih_b = (const float*)d_in[13];
    const float* Whh_b = (const float*)d_in[14];
    const float* bih_b = (const float*)d_in[15];
    const float* bhh_b = (const float*)d_in[16];
    const float* wc  = (const float*)d_in[17];
    const float* bc  = (const float*)d_in[18];
    const float* wq  = (const float*)d_in[19];
    const float* bq  = (const float*)d_in[20];
    const float* wcq = (const float*)d_in[21];
    const float* bcq = (const float*)d_in[22];
    const float* wz  = (const float*)d_in[23];
    const float* bz  = (const float*)d_in[24];
    const float* w_p1 = (const float*)d_in[25];
    const float* b_p1 = (const float*)d_in[26];
    const float* w_p2 = (const float*)d_in[27];
    const float* b_p2 = (const float*)d_in[28];
    float* out = (float*)d_out;

    float *pPre;
    __half *pPh, *pAe16, *pB116, *pFt16, *pWc16;
    cudaGetSymbolAddress((void**)&pPh, d_Ph);
    cudaGetSymbolAddress((void**)&pPre, d_Pre);
    cudaGetSymbolAddress((void**)&pAe16, d_Ae16);
    cudaGetSymbolAddress((void**)&pB116, d_B116);
    cudaGetSymbolAddress((void**)&pFt16, d_Ft16);
    cudaGetSymbolAddress((void**)&pWc16, d_Wc16);

    const int PREP_TOT = PCOLS * KPAD1 + 1024 * KPAD2 + MPAD1 * KPAD1 + 2 * 65536;
    const int LSTM_SMEM = 131072 + 8192 + 2048 + 512;
    cudaFuncSetAttribute(att_kernel, cudaFuncAttributeMaxDynamicSharedMemorySize, 73728);
    cudaFuncSetAttribute(lstm_kernel, cudaFuncAttributeMaxDynamicSharedMemorySize, LSTM_SMEM);

    prep_kernel<<<(PREP_TOT + 255) / 256, 256>>>(conv_w, Wih_f, Wih_b, Whh_f, Whh_b, emb);
    gemm_mma_h<0><<<dim3(PCOLS / 128, MPAD1 / 128), 256>>>(
        VOCABN, KPAD1, PCOLS, pAe16, pB116, pPh);
    conv_kernel<<<MPAD2, 128>>>(title, body, ctx, doc, conv_b);
    gemm_mma_h<1><<<dim3(1024 / 128, MPAD2 / 128), 256>>>(
        NFEAT, KPAD2, 1024, pFt16, pWc16, pPre);
    lstm_kernel<<<dim3((NSEQ + 3) / 4, 2), 128, LSTM_SMEM>>>(cand, bih_f, bhh_f, bih_b, bhh_b);
    att_kernel<<<dim3(MMEN, 2), 256, 72576>>>(wc, bc, wq, bq, wcq, bcq, wz, bz);
    final_kernel<<<MMEN, 256>>>(cand, w_p1, b_p1, w_p2, b_p2, out);
}

// round 12
// speedup vs baseline: 3.3480x; 1.2974x over previous
#include <cuda_runtime.h>
#include <cuda_fp16.h>
#include <math.h>

#define NENT   2048
#define MMEN   64
#define KC     32
#define VOCABN 5053
#define EMBD   300
#define CCSN   512
#define PCOLS  2560
#define HHN    128
#define NSEQ   193
#define NFEAT  4161
#define MPAD1  5120
#define KPAD1  320
#define MPAD2  4224
#define KPAD2  512
#define DOCBLK 8

__device__ __align__(16) __half d_Ph[VOCABN * PCOLS];
__device__ __align__(16) float d_Pre[NFEAT * 1024];
__device__ __align__(16) float d_Hout[NSEQ * KC * 256];
__device__ __align__(16) float d_Pp[2 * MMEN * KC];
__device__ __align__(16) __half d_Wth[2 * 65536];
__device__ __align__(16) __half d_Ae16[MPAD1 * KPAD1];
__device__ __align__(16) __half d_B116[PCOLS * KPAD1];
__device__ __align__(16) __half d_Ft16[MPAD2 * KPAD2];
__device__ __align__(16) __half d_Wc16[1024 * KPAD2];
__device__ unsigned d_DocMax[CCSN];

typedef unsigned long long u64t;

__device__ __forceinline__ float sigf(float x) { return 1.f / (1.f + expf(-x)); }

__device__ __forceinline__ unsigned enc_f(float f) {
    unsigned u = __float_as_uint(f);
    return (u >> 31) ? ~u : (u | 0x80000000u);
}
__device__ __forceinline__ float dec_f(unsigned e) {
    return (e >> 31) ? __uint_as_float(e & 0x7fffffffu) : __uint_as_float(~e);
}

__device__ __forceinline__ unsigned smem_u32(const void* p) {
    unsigned r;
    asm("{ .reg .u64 t; cvta.to.shared.u64 t, %1; cvt.u32.u64 %0, t; }" : "=r"(r) : "l"(p));
    return r;
}

__device__ __forceinline__ void ldmx4(unsigned* a, unsigned addr) {
    asm volatile("ldmatrix.sync.aligned.m8n8.x4.shared.b16 {%0,%1,%2,%3}, [%4];"
        : "=r"(a[0]), "=r"(a[1]), "=r"(a[2]), "=r"(a[3]) : "r"(addr));
}
__device__ __forceinline__ void ldmx2(unsigned* b, unsigned addr) {
    asm volatile("ldmatrix.sync.aligned.m8n8.x2.shared.b16 {%0,%1}, [%2];"
        : "=r"(b[0]), "=r"(b[1]) : "r"(addr));
}
__device__ __forceinline__ void mma_fp(float* c, const unsigned* a, const unsigned* b) {
    asm volatile("mma.sync.aligned.m16n8k16.row.col.f32.f16.f16.f32 "
        "{%0,%1,%2,%3}, {%4,%5,%6,%7}, {%8,%9}, {%0,%1,%2,%3};"
        : "+f"(c[0]), "+f"(c[1]), "+f"(c[2]), "+f"(c[3])
        : "r"(a[0]), "r"(a[1]), "r"(a[2]), "r"(a[3]), "r"(b[0]), "r"(b[1]));
}

__global__ void prep_kernel(const float* __restrict__ conv_w,
                            const float* __restrict__ Wih_f,
                            const float* __restrict__ Wih_b,
                            const float* __restrict__ Whh_f,
                            const float* __restrict__ Whh_b,
                            const float* __restrict__ emb) {
    int i = blockIdx.x * blockDim.x + threadIdx.x;
    const int T1 = PCOLS * KPAD1;
    const int T2 = 1024 * KPAD2;
    const int T3 = MPAD1 * KPAD1;
    const int T4 = 2 * 65536;
    if (i < T1) {
        int j = i / KPAD1, e = i - j * KPAD1;
        int w = j >> 9, c = j & 511;
        float v = (e < EMBD) ? conv_w[c * (EMBD * 5) + e * 5 + w] : 0.f;
        d_B116[i] = __float2half_rn(v);
        return;
    }
    int i2 = i - T1;
    if (i2 < T2) {
        int n = i2 >> 9, k = i2 & 511;
        int dir = n >> 9, col = n & 511;
        float v = (dir ? Wih_b : Wih_f)[col * CCSN + k];
        d_Wc16[i2] = __float2half_rn(v);
        return;
    }
    int i3 = i2 - T2;
    if (i3 < T3) {
        int r = i3 / KPAD1, k = i3 - r * KPAD1;
        float v = (r < VOCABN && k < EMBD) ? emb[r * EMBD + k] : 0.f;
        d_Ae16[i3] = __float2half_rn(v);
        return;
    }
    int i4 = i3 - T3;
    if (i4 < T4) {
        int dir = i4 >> 16;
        int r = i4 & 65535;
        int hb = r >> 12, rem = r & 4095;
        int gcol = rem >> 3, j = rem & 7;
        const float* W = dir ? Whh_b : Whh_f;
        d_Wth[i4] = __float2half_rn(W[gcol * HHN + hb * 8 + j]);
        return;
    }
    int i5 = i4 - T4;
    if (i5 < CCSN) d_DocMax[i5] = enc_f(-1e30f);
}

#define SROW 40
template <int FOUT>
__global__ void __launch_bounds__(256, 2) gemm_mma_h(
    int M, int Kpad, int ldc,
    const __half* __restrict__ A, const __half* __restrict__ B,
    void* __restrict__ Cv)
{
    __shared__ __align__(16) __half sA[128 * SROW];
    __shared__ __align__(16) __half sB[128 * SROW];
    int tid = threadIdx.x, wid = tid >> 5, lane = tid & 31;
    int gm0 = blockIdx.y * 128, gn0 = blockIdx.x * 128;
    int wm0 = (wid & 1) * 64, wn0 = (wid >> 1) * 32;
    unsigned bA = smem_u32(sA), bB = smem_u32(sB);

    float acc[4][4][4];
    #pragma unroll
    for (int mi = 0; mi < 4; mi++)
        #pragma unroll
        for (int ni = 0; ni < 4; ni++)
            #pragma unroll
            for (int x = 0; x < 4; x++) acc[mi][ni][x] = 0.f;

    int lr = tid >> 2, lq = tid & 3;
    int arow = lane & 15;
    int acol = (lane >> 4) * 8;
    int brow = lane & 7;
    int bcol = lane & 8;

    int nchunks = Kpad >> 5;
    for (int kc = 0; kc < nchunks; kc++) {
        int kbase = kc << 5;
        {
            size_t ga0 = (size_t)(gm0 + lr) * Kpad + kbase + lq * 8;
            size_t ga1 = (size_t)(gm0 + lr + 64) * Kpad + kbase + lq * 8;
            size_t gb0 = (size_t)(gn0 + lr) * Kpad + kbase + lq * 8;
            size_t gb1 = (size_t)(gn0 + lr + 64) * Kpad + kbase + lq * 8;
            int so0 = lr * SROW + lq * 8, so1 = (lr + 64) * SROW + lq * 8;
            *(uint4*)&sA[so0] = *(const uint4*)(A + ga0);
            *(uint4*)&sA[so1] = *(const uint4*)(A + ga1);
            *(uint4*)&sB[so0] = *(const uint4*)(B + gb0);
            *(uint4*)&sB[so1] = *(const uint4*)(B + gb1);
        }
        __syncthreads();
        #pragma unroll
        for (int ko = 0; ko < 32; ko += 16) {
            unsigned fA[4][4], fB[4][2];
            #pragma unroll
            for (int ni = 0; ni < 4; ni++) {
                unsigned off = ((unsigned)((wn0 + ni * 8 + brow) * SROW + ko + bcol)) * 2u;
                ldmx2(fB[ni], bB + off);
            }
            #pragma unroll
            for (int mi = 0; mi < 4; mi++) {
                unsigned off = ((unsigned)((wm0 + mi * 16 + arow) * SROW + ko + acol)) * 2u;
                ldmx4(fA[mi], bA + off);
            }
            #pragma unroll
            for (int mi = 0; mi < 4; mi++)
                #pragma unroll
                for (int ni = 0; ni < 4; ni++)
                    mma_fp(acc[mi][ni], fA[mi], fB[ni]);
        }
        __syncthreads();
    }
    int gid = lane >> 2, tc = (lane & 3) * 2;
    #pragma unroll
    for (int mi = 0; mi < 4; mi++) {
        #pragma unroll
        for (int ni = 0; ni < 4; ni++) {
            int m0 = gm0 + wm0 + mi * 16 + gid;
            int n = gn0 + wn0 + ni * 8 + tc;
            if (FOUT) {
                float* C = (float*)Cv;
                if (m0 < M) {
                    float2 v; v.x = acc[mi][ni][0]; v.y = acc[mi][ni][1];
                    *(float2*)&C[(size_t)m0 * ldc + n] = v;
                }
                if (m0 + 8 < M) {
                    float2 v; v.x = acc[mi][ni][2]; v.y = acc[mi][ni][3];
                    *(float2*)&C[(size_t)(m0 + 8) * ldc + n] = v;
                }
            } else {
                __half* C = (__half*)Cv;
                if (m0 < M)
                    *(__half2*)&C[(size_t)m0 * ldc + n] =
                        __floats2half2_rn(acc[mi][ni][0], acc[mi][ni][1]);
                if (m0 + 8 < M)
                    *(__half2*)&C[(size_t)(m0 + 8) * ldc + n] =
                        __floats2half2_rn(acc[mi][ni][2], acc[mi][ni][3]);
            }
        }
    }
}

__global__ void __launch_bounds__(128) conv_kernel(
    const int* __restrict__ title, const int* __restrict__ body,
    const int* __restrict__ ctx, const int* __restrict__ doc,
    const float* __restrict__ conv_b)
{
    __shared__ int chars[512];
    int b = blockIdx.x, tid = threadIdx.x;
    int c4 = tid * 4;
    if (b >= MPAD2) {   // doc chunk blocks
        int chunk = b - MPAD2;
        int t0 = chunk * 64;
        int tend = t0 + 64; if (tend > 508) tend = 508;
        int nload = tend - t0 + 4;     // chars [t0, tend+4)
        for (int i = tid; i < nload; i += 128) chars[i] = doc[t0 + i];
        __syncthreads();
        float mx0 = -1e30f, mx1 = -1e30f, mx2 = -1e30f, mx3 = -1e30f;
        int nt = tend - t0;
        #pragma unroll 4
        for (int t = 0; t < nt; t++) {
            float s0 = 0.f, s1 = 0.f, s2 = 0.f, s3 = 0.f;
            #pragma unroll
            for (int w = 0; w < 5; w++) {
                const __half* prow = d_Ph + (size_t)chars[t + w] * PCOLS + (w << 9) + c4;
                uint2 u = *(const uint2*)prow;
                float2 f0 = __half22float2(*(const __half2*)&u.x);
                float2 f1 = __half22float2(*(const __half2*)&u.y);
                s0 += f0.x; s1 += f0.y; s2 += f1.x; s3 += f1.y;
            }
            mx0 = fmaxf(mx0, s0); mx1 = fmaxf(mx1, s1);
            mx2 = fmaxf(mx2, s2); mx3 = fmaxf(mx3, s3);
        }
        atomicMax(&d_DocMax[c4 + 0], enc_f(mx0));
        atomicMax(&d_DocMax[c4 + 1], enc_f(mx1));
        atomicMax(&d_DocMax[c4 + 2], enc_f(mx2));
        atomicMax(&d_DocMax[c4 + 3], enc_f(mx3));
        return;
    }
    if (b >= NFEAT - 1) {   // pad rows AND doc row (doc_fin writes the real doc row)
        *(ushort4*)&d_Ft16[(size_t)b * CCSN + c4] = make_ushort4(0, 0, 0, 0);
        return;
    }
    const int* src; int L;
    if (b < NENT)                 { src = title + b * 32;             L = 32;  }
    else if (b < 2 * NENT)        { src = body + (b - NENT) * 128;    L = 128; }
    else                          { src = ctx + (b - 2 * NENT) * 128; L = 128; }
    for (int i = tid; i < L; i += 128) chars[i] = src[i];
    __syncthreads();
    float mx0 = -1e30f, mx1 = -1e30f, mx2 = -1e30f, mx3 = -1e30f;
    int Lout = L - 4;
    #pragma unroll 4
    for (int t = 0; t < Lout; t++) {
        float s0 = 0.f, s1 = 0.f, s2 = 0.f, s3 = 0.f;
        #pragma unroll
        for (int w = 0; w < 5; w++) {
            const __half* prow = d_Ph + (size_t)chars[t + w] * PCOLS + (w << 9) + c4;
            uint2 u = *(const uint2*)prow;
            float2 f0 = __half22float2(*(const __half2*)&u.x);
            float2 f1 = __half22float2(*(const __half2*)&u.y);
            s0 += f0.x; s1 += f0.y; s2 += f1.x; s3 += f1.y;
        }
        mx0 = fmaxf(mx0, s0); mx1 = fmaxf(mx1, s1);
        mx2 = fmaxf(mx2, s2); mx3 = fmaxf(mx3, s3);
    }
    const float4 bb = *(const float4*)&conv_b[c4];
    float o0 = fmaxf(0.f, mx0 + bb.x), o1 = fmaxf(0.f, mx1 + bb.y);
    float o2 = fmaxf(0.f, mx2 + bb.z), o3 = fmaxf(0.f, mx3 + bb.w);
    __half2 p0 = __floats2half2_rn(o0, o1);
    __half2 p1 = __floats2half2_rn(o2, o3);
    uint2 w2;
    w2.x = *(unsigned*)&p0;
    w2.y = *(unsigned*)&p1;
    *(uint2*)&d_Ft16[(size_t)b * CCSN + c4] = w2;
}

__global__ void __launch_bounds__(128) doc_fin_kernel(const float* __restrict__ conv_b) {
    int tid = threadIdx.x;
    int c4 = tid * 4;
    const float4 bb = *(const float4*)&conv_b[c4];
    float o0 = fmaxf(0.f, dec_f(d_DocMax[c4 + 0]) + bb.x);
    float o1 = fmaxf(0.f, dec_f(d_DocMax[c4 + 1]) + bb.y);
    float o2 = fmaxf(0.f, dec_f(d_DocMax[c4 + 2]) + bb.z);
    float o3 = fmaxf(0.f, dec_f(d_DocMax[c4 + 3]) + bb.w);
    __half2 p0 = __floats2half2_rn(o0, o1);
    __half2 p1 = __floats2half2_rn(o2, o3);
    uint2 w2;
    w2.x = *(unsigned*)&p0;
    w2.y = *(unsigned*)&p1;
    *(uint2*)&d_Ft16[(size_t)(NFEAT - 1) * CCSN + c4] = w2;
}

__device__ __forceinline__ u64t pack2(float x, float y) {
    u64t r;
    asm("mov.b64 %0, {%1, %2};" : "=l"(r) : "f"(x), "f"(y));
    return r;
}
__device__ __forceinline__ void unpack2(u64t v, float& x, float& y) {
    asm("mov.b64 {%0, %1}, %2;" : "=f"(x), "=f"(y) : "l"(v));
}
__device__ __forceinline__ void fma2(u64t& d, u64t a, u64t b) {
    asm("fma.rn.f32x2 %0, %1, %2, %0;" : "+l"(d) : "l"(a), "l"(b));
}

__global__ void __launch_bounds__(128) lstm_kernel(
    const int* __restrict__ cand_idx,
    const float* __restrict__ bih_f, const float* __restrict__ bhh_f,
    const float* __restrict__ bih_b, const float* __restrict__ bhh_b)
{
    extern __shared__ __align__(16) char lsm[];
    __half* sW   = (__half*)lsm;
    float* presm = (float*)(lsm + 131072);
    float* hsm   = presm + 4 * 512;
    int*  rowIdx = (int*)(hsm + 512);
    int tid = threadIdx.x;
    int dir = blockIdx.y;
    int s0 = blockIdx.x * 4;
    const float* bih = dir ? bih_b : bih_f;
    const float* bhh = dir ? bhh_b : bhh_f;
    float bias[4];
    #pragma unroll
    for (int g = 0; g < 4; g++) { int col = (g << 7) + tid; bias[g] = bih[col] + bhh[col]; }
    {
        const uint4* src = (const uint4*)(d_Wth + dir * 65536);
        uint4* dst = (uint4*)sW;
        #pragma unroll
        for (int i = 0; i < 64; i++) dst[tid + i * 128] = src[tid + i * 128];
    }
    {
        int s = tid >> 5, t = tid & 31;
        int seq = s0 + s;
        int row;
        if (seq < 64)       row = cand_idx[seq * 32 + t];
        else if (seq < 128) row = NENT + cand_idx[(seq - 64) * 32 + t];
        else if (seq < 192) row = 2 * NENT + (seq - 128);
        else                row = NFEAT - 1;
        rowIdx[s * KC + t] = row;
    }
    *(float4*)&hsm[tid * 4] = make_float4(0.f, 0.f, 0.f, 0.f);
    float cst[4] = {0.f, 0.f, 0.f, 0.f};
    int nS = NSEQ - s0; if (nS > 4) nS = 4;
    int preOff = dir * 512;
    __syncthreads();
    for (int st = 0; st < KC; st++) {
        int t = dir ? (KC - 1 - st) : st;
        #pragma unroll
        for (int s = 0; s < 4; s++) {
            const float* prow = d_Pre + (size_t)rowIdx[s * KC + t] * 1024 + preOff;
            *(float4*)&presm[s * 512 + tid * 4] = *(const float4*)&prow[tid * 4];
        }
        __syncthreads();
        u64t acc2[4][2];
        #pragma unroll
        for (int g = 0; g < 4; g++) {
            int col = (g << 7) + tid;
            acc2[g][0] = pack2(presm[0 * 512 + col] + bias[g], presm[1 * 512 + col] + bias[g]);
            acc2[g][1] = pack2(presm[2 * 512 + col] + bias[g], presm[3 * 512 + col] + bias[g]);
        }
        #pragma unroll 2
        for (int hb = 0; hb < 16; hb++) {
            ulonglong2 hv[8];
            #pragma unroll
            for (int j = 0; j < 8; j++)
                hv[j] = *(const ulonglong2*)&hsm[(hb * 8 + j) * 4];
            #pragma unroll
            for (int g = 0; g < 4; g++) {
                uint4 wq = *(const uint4*)&sW[(hb * 512 + (g << 7) + tid) * 8];
                float2 w01 = __half22float2(*(const __half2*)&wq.x);
                float2 w23 = __half22float2(*(((const __half2*)&wq.x) + 1));
                float2 w45 = __half22float2(*(const __half2*)&wq.z);
                float2 w67 = __half22float2(*(((const __half2*)&wq.z) + 1));
                float wf[8] = {w01.x, w01.y, w23.x, w23.y, w45.x, w45.y, w67.x, w67.y};
                #pragma unroll
                for (int j = 0; j < 8; j++) {
                    u64t wp = pack2(wf[j], wf[j]);
                    fma2(acc2[g][0], wp, hv[j].x);
                    fma2(acc2[g][1], wp, hv[j].y);
                }
            }
        }
        float accs[4][4];
        #pragma unroll
        for (int g = 0; g < 4; g++) {
            unpack2(acc2[g][0], accs[g][0], accs[g][1]);
            unpack2(acc2[g][1], accs[g][2], accs[g][3]);
        }
        float hnew[4];
        #pragma unroll
        for (int s = 0; s < 4; s++) {
            float ig = sigf(accs[0][s]);
            float fg = sigf(accs[1][s]);
            float gg = tanhf(accs[2][s]);
            float og = sigf(accs[3][s]);
            cst[s] = fg * cst[s] + ig * gg;
            hnew[s] = og * tanhf(cst[s]);
        }
        __syncthreads();
        *(float4*)&hsm[tid * 4] = *(const float4*)&hnew[0];
        #pragma unroll
        for (int s = 0; s < 4; s++) {
            if (s < nS)
                d_Hout[((size_t)(s0 + s) * KC + t) * 256 + dir * HHN + tid] = hnew[s];
        }
    }
}

__global__ void __launch_bounds__(256) att_kernel(
    const float* __restrict__ wc, const float* __restrict__ bcp,
    const float* __restrict__ wq, const float* __restrict__ bqp,
    const float* __restrict__ wcq, const float* __restrict__ bcqp,
    const float* __restrict__ wz, const float* __restrict__ bzp)
{
    extern __shared__ float sbuf[];
    float* csm = sbuf;
    float* qsm = csm + 8224;
    float* sA  = qsm + 8224;
    float* cwcA = sA + 1056;
    float* qwqA = cwcA + 32;
    float* rowmaxA = qwqA + 32;
    float* betaA = rowmaxA + 32;
    float* q2cA = betaA + 32;
    float* wcqs = q2cA + 256;
    int m = blockIdx.x, fl = blockIdx.y, tid = threadIdx.x;
    int seqC = fl ? 192 : (128 + m);
    int seqQ = fl ? (64 + m) : m;
    const float* Crow = d_Hout + (size_t)seqC * KC * 256;
    const float* Qrow = d_Hout + (size_t)seqQ * KC * 256;
    for (int idx = tid; idx < 32 * 256; idx += 256) {
        int i = idx >> 8, d = idx & 255;
        csm[i * 257 + d] = Crow[i * 256 + d];
        qsm[i * 257 + d] = Qrow[i * 256 + d];
    }
    wcqs[tid] = wcq[tid];
    __syncthreads();
    if (tid < 32) {
        float a = 0.f;
        for (int d = 0; d < 256; d++) a += csm[tid * 257 + d] * wc[d];
        cwcA[tid] = a;
    } else if (tid < 64) {
        int j = tid - 32;
        float a = 0.f;
        for (int d = 0; d < 256; d++) a += qsm[j * 257 + d] * wq[d];
        qwqA[j] = a;
    }
    __syncthreads();
    float K0 = bcp[0] + bqp[0] + bcqp[0];
    for (int e = tid; e < 1024; e += 256) {
        int i = e >> 5, j = e & 31;
        float acc = 0.f;
        for (int d = 0; d < 256; d++)
            acc += csm[i * 257 + d] * wcqs[d] * qsm[j * 257 + d];
        sA[i * 33 + j] = acc + cwcA[i] + qwqA[j] + K0;
    }
    __syncthreads();
    if (tid < 32) {
        int i = tid;
        float mx = -1e30f;
        for (int j = 0; j < 32; j++) mx = fmaxf(mx, sA[i * 33 + j]);
        rowmaxA[i] = mx;
        float s = 0.f;
        for (int j = 0; j < 32; j++) { float e2 = expf(sA[i * 33 + j] - mx); sA[i * 33 + j] = e2; s += e2; }
        float inv = 1.f / s;
        for (int j = 0; j < 32; j++) sA[i * 33 + j] *= inv;
    }
    __syncthreads();
    if (tid == 0) {
        float mx = -1e30f;
        for (int i = 0; i < 32; i++) mx = fmaxf(mx, rowmaxA[i]);
        float s = 0.f;
        for (int i = 0; i < 32; i++) { float e2 = expf(rowmaxA[i] - mx); betaA[i] = e2; s += e2; }
        float inv = 1.f / s;
        for (int i = 0; i < 32; i++) betaA[i] *= inv;
    }
    __syncthreads();
    {
        float a = 0.f;
        for (int i = 0; i < 32; i++) a += betaA[i] * csm[i * 257 + tid];
        q2cA[tid] = a;
    }
    __syncthreads();
    {
        int i = tid >> 3, sub = tid & 7, d0 = sub * 32;
        float pp = 0.f;
        for (int dd = 0; dd < 32; dd++) {
            int d = d0 + dd;
            float c2 = 0.f;
            for (int j = 0; j < 32; j++) c2 += sA[i * 33 + j] * qsm[j * 257 + d];
            float cd = csm[i * 257 + d];
            pp += cd * wz[d] + c2 * wz[256 + d] + cd * c2 * wz[512 + d] + cd * q2cA[d] * wz[768 + d];
        }
        pp += __shfl_xor_sync(0xffffffffu, pp, 1);
        pp += __shfl_xor_sync(0xffffffffu, pp, 2);
        pp += __shfl_xor_sync(0xffffffffu, pp, 4);
        if (sub == 0) d_Pp[fl * 2048 + m * 32 + i] = pp + bzp[0];
    }
}

__global__ void __launch_bounds__(256) final_kernel(
    const int* __restrict__ cand,
    const float* __restrict__ wp1, const float* __restrict__ bp1,
    const float* __restrict__ wp2, const float* __restrict__ bp2,
    float* __restrict__ out)
{
    int m = blockIdx.x, tid = threadIdx.x;
    const int R = MMEN * NENT;
    for (int j = tid; j < NENT; j += 256) {
        out[m * NENT + j] = 0.f;
        out[R + m * NENT + j] = 0.f;
        out[2 * R + m * NENT + j] = 0.f;
    }
    __syncthreads();
    if (tid < 32) {
        float s = wp1[0] * d_Pp[m * 32 + tid] + bp1[0] + wp2[0] * d_Pp[2048 + m * 32 + tid] + bp2[0];
        float mx = s;
        #pragma unroll
        for (int o = 16; o; o >>= 1) mx = fmaxf(mx, __shfl_xor_sync(0xffffffffu, mx, o));
        float e = expf(s - mx);
        float se = e, ss = s;
        #pragma unroll
        for (int o = 16; o; o >>= 1) {
            se += __shfl_xor_sync(0xffffffffu, se, o);
            ss += __shfl_xor_sync(0xffffffffu, ss, o);
        }
        int col = cand[m * 32 + tid];
        out[m * NENT + col] = s;
        out[R + m * NENT + col] = e / se;
        out[2 * R + m * NENT + col] = s / ss;
    }
}

extern "C" void kernel_launch(void* const* d_in, const int* in_sizes, int n_in,
                              void* d_out, int out_size) {
    const int* title = (const int*)d_in[0];
    const int* body  = (const int*)d_in[1];
    const int* ctx   = (const int*)d_in[3];
    const int* doc   = (const int*)d_in[4];
    const int* cand  = (const int*)d_in[5];
    const float* emb    = (const float*)d_in[6];
    const float* conv_w = (const float*)d_in[7];
    const float* conv_b = (const float*)d_in[8];
    const float* Wih_f = (const float*)d_in[9];
    const float* Whh_f = (const float*)d_in[10];
    const float* bih_f = (const float*)d_in[11];
    const float* bhh_f = (const float*)d_in[12];
    const float* Wih_b = (const float*)d_in[13];
    const float* Whh_b = (const float*)d_in[14];
    const float* bih_b = (const float*)d_in[15];
    const float* bhh_b = (const float*)d_in[16];
    const float* wc  = (const float*)d_in[17];
    const float* bc  = (const float*)d_in[18];
    const float* wq  = (const float*)d_in[19];
    const float* bq  = (const float*)d_in[20];
    const float* wcq = (const float*)d_in[21];
    const float* bcq = (const float*)d_in[22];
    const float* wz  = (const float*)d_in[23];
    const float* bz  = (const float*)d_in[24];
    const float* w_p1 = (const float*)d_in[25];
    const float* b_p1 = (const float*)d_in[26];
    const float* w_p2 = (const float*)d_in[27];
    const float* b_p2 = (const float*)d_in[28];
    float* out = (float*)d_out;

    float *pPre;
    __half *pPh, *pAe16, *pB116, *pFt16, *pWc16;
    cudaGetSymbolAddress((void**)&pPh, d_Ph);
    cudaGetSymbolAddress((void**)&pPre, d_Pre);
    cudaGetSymbolAddress((void**)&pAe16, d_Ae16);
    cudaGetSymbolAddress((void**)&pB116, d_B116);
    cudaGetSymbolAddress((void**)&pFt16, d_Ft16);
    cudaGetSymbolAddress((void**)&pWc16, d_Wc16);

    const int PREP_TOT = PCOLS * KPAD1 + 1024 * KPAD2 + MPAD1 * KPAD1 + 2 * 65536 + CCSN;
    const int LSTM_SMEM = 131072 + 8192 + 2048 + 512;
    cudaFuncSetAttribute(att_kernel, cudaFuncAttributeMaxDynamicSharedMemorySize, 73728);
    cudaFuncSetAttribute(lstm_kernel, cudaFuncAttributeMaxDynamicSharedMemorySize, LSTM_SMEM);

    prep_kernel<<<(PREP_TOT + 255) / 256, 256>>>(conv_w, Wih_f, Wih_b, Whh_f, Whh_b, emb);
    gemm_mma_h<0><<<dim3(PCOLS / 128, MPAD1 / 128), 256>>>(
        VOCABN, KPAD1, PCOLS, pAe16, pB116, pPh);
    conv_kernel<<<MPAD2 + DOCBLK, 128>>>(title, body, ctx, doc, conv_b);
    doc_fin_kernel<<<1, 128>>>(conv_b);
    gemm_mma_h<1><<<dim3(1024 / 128, MPAD2 / 128), 256>>>(
        NFEAT, KPAD2, 1024, pFt16, pWc16, pPre);
    lstm_kernel<<<dim3((NSEQ + 3) / 4, 2), 128, LSTM_SMEM>>>(cand, bih_f, bhh_f, bih_b, bhh_b);
    att_kernel<<<dim3(MMEN, 2), 256, 72576>>>(wc, bc, wq, bq, wcq, bcq, wz, bz);
    final_kernel<<<MMEN, 256>>>(cand, w_p1, b_p1, w_p2, b_p2, out);
}